// round 2
// baseline (speedup 1.0000x reference)
#include <cuda_runtime.h>
#include <math.h>

#define NPIX 9216
#define CCH  64
#define HH   96
#define WW   96
#define HS   24
#define KNN  5
#define CSPLIT 8
#define COLS_PER_SPLIT (NPIX / CSPLIT)   /* 1152 */
#define E5   (NPIX * KNN)                /* 46080 */
#define ETOT (E5 + NPIX)                 /* 55296 */

// ---------------- scratch (static device globals; no allocation) ----------------
__device__ float    g_hsi_up[CCH * NPIX];   // channel-major [c][pix]; also the residual
__device__ float    g_tmp  [NPIX * CCH];    // pixel-major
__device__ float    g_hfeat[NPIX * CCH];    // pixel-major [pix][c]
__device__ float    g_mfeat[NPIX * CCH];
__device__ float    g_z    [NPIX * CCH];
__device__ float    g_el   [NPIX];
__device__ float    g_er   [NPIX];
__device__ float    g_pval [CSPLIT * NPIX * KNN];
__device__ int      g_pidx [CSPLIT * NPIX * KNN];
__device__ int      g_topk [NPIX * KNN];
__device__ unsigned g_menc [NPIX];
__device__ float    g_den  [NPIX];
__device__ float    g_agg  [NPIX * CCH];    // pixel-major
__device__ float    g_fmap [CCH * NPIX];    // channel-major
__device__ float    g_up1  [CCH * NPIX];

// ---------------- helpers ----------------
__device__ __forceinline__ unsigned long long fma2(unsigned long long a,
                                                   unsigned long long b,
                                                   unsigned long long c) {
    unsigned long long d;
    asm("fma.rn.f32x2 %0, %1, %2, %3;" : "=l"(d) : "l"(a), "l"(b), "l"(c));
    return d;
}

__device__ __forceinline__ unsigned fenc(float f) {
    unsigned u = __float_as_uint(f);
    return (u & 0x80000000u) ? ~u : (u | 0x80000000u);
}
__device__ __forceinline__ float fdec(unsigned u) {
    u = (u & 0x80000000u) ? (u & 0x7fffffffu) : ~u;
    return __uint_as_float(u);
}

__device__ __forceinline__ float cubw(float d) {
    d = fabsf(d);
    const float a = -0.75f;
    if (d <= 1.0f) return ((a + 2.0f) * d - (a + 3.0f)) * d * d + 1.0f;
    if (d < 2.0f)  return ((a * d - 5.0f * a) * d + 8.0f * a) * d - 4.0f * a;
    return 0.0f;
}

// ---------------- K1: bicubic x4 upsample (24x24 -> 96x96, border replicate) ----
__global__ void k_bicubic(const float* __restrict__ in) {
    int t = blockIdx.x * blockDim.x + threadIdx.x;   // c*NPIX + y*96 + x
    if (t >= CCH * NPIX) return;
    int x = t % WW;
    int y = (t / WW) % HH;
    int c = t / NPIX;
    float fy = (y + 0.5f) * 0.25f - 0.5f;
    float iy = floorf(fy); float ty = fy - iy;
    float fx = (x + 0.5f) * 0.25f - 0.5f;
    float ix = floorf(fx); float tx = fx - ix;
    float wy[4], wx[4]; int sy[4], sx[4];
    #pragma unroll
    for (int o = 0; o < 4; o++) {
        wy[o] = cubw(ty - (float)(o - 1));
        wx[o] = cubw(tx - (float)(o - 1));
        sy[o] = min(max((int)iy + o - 1, 0), HS - 1);
        sx[o] = min(max((int)ix + o - 1, 0), HS - 1);
    }
    const float* ic = in + c * HS * HS;
    float acc = 0.0f;
    #pragma unroll
    for (int i = 0; i < 4; i++) {
        float r = 0.0f;
        #pragma unroll
        for (int j = 0; j < 4; j++) r = fmaf(wx[j], ic[sy[i] * HS + sx[j]], r);
        acc = fmaf(wy[i], r, acc);
    }
    g_hsi_up[t] = acc;
}

// ---------------- K2: 1x1 conv (64->64) + PReLU ----------------
// in_cm: input layout flag (1 = channel-major [c][pix], 0 = pixel-major [pix][c])
// output is always pixel-major [pix][64]
__global__ void k_lin64(const float* __restrict__ X, int in_cm,
                        const float* __restrict__ Wm, const float* __restrict__ b,
                        const float* __restrict__ aptr, float* __restrict__ Y) {
    __shared__ float Ws[64 * 64];
    __shared__ float bs[64];
    __shared__ float s_alpha;
    int tid = threadIdx.x;
    for (int i = tid; i < 4096; i += 256) Ws[i] = Wm[i];
    if (tid < 64) bs[tid] = b[tid];
    if (tid == 0) s_alpha = aptr[0];
    __syncthreads();
    int pix = blockIdx.x * 256 + tid;
    if (pix >= NPIX) return;
    float acc[64];
    #pragma unroll
    for (int o = 0; o < 64; o++) acc[o] = bs[o];
    for (int c = 0; c < 64; c++) {
        float xv = in_cm ? X[c * NPIX + pix] : X[pix * 64 + c];
        #pragma unroll
        for (int o = 0; o < 64; o++) acc[o] = fmaf(Ws[o * 64 + c], xv, acc[o]);
    }
    float al = s_alpha;
    #pragma unroll
    for (int o = 0; o < 64; o++) {
        float v = acc[o];
        Y[pix * 64 + o] = (v >= 0.0f) ? v : al * v;
    }
}

// ---------------- K3: fused sim GEMM + per-row running top-5 (partial per column split)
__global__ __launch_bounds__(256, 2) void k_simtopk() {
    __shared__ float sm[64 * 64];
    const int row   = blockIdx.x * 256 + threadIdx.x;
    const int split = blockIdx.y;
    const int cbase = split * COLS_PER_SPLIT;

    unsigned long long h2[32];
    {
        const unsigned long long* hr = (const unsigned long long*)(g_hfeat + row * 64);
        #pragma unroll
        for (int i = 0; i < 32; i++) h2[i] = hr[i];
    }
    float v0 = -INFINITY, v1 = -INFINITY, v2 = -INFINITY, v3 = -INFINITY, v4 = -INFINITY;
    int   i0 = 0, i1 = 0, i2 = 0, i3 = 0, i4 = 0;

    for (int tile = 0; tile < COLS_PER_SPLIT / 64; tile++) {
        int cb = cbase + tile * 64;
        __syncthreads();
        {
            const float4* src = (const float4*)(g_mfeat + cb * 64);
            float4* dst = (float4*)sm;
            #pragma unroll
            for (int i = 0; i < 4; i++) dst[threadIdx.x + 256 * i] = src[threadIdx.x + 256 * i];
        }
        __syncthreads();
        for (int j = 0; j < 64; j++) {
            const unsigned long long* mr = (const unsigned long long*)(sm + j * 64);
            unsigned long long a0 = 0ull, a1 = 0ull;
            #pragma unroll
            for (int q = 0; q < 16; q++) {
                a0 = fma2(h2[2 * q],     mr[2 * q],     a0);
                a1 = fma2(h2[2 * q + 1], mr[2 * q + 1], a1);
            }
            float x0 = __uint_as_float((unsigned)a0);
            float x1 = __uint_as_float((unsigned)(a0 >> 32));
            float y0 = __uint_as_float((unsigned)a1);
            float y1 = __uint_as_float((unsigned)(a1 >> 32));
            float dot = (x0 + y0) + (x1 + y1);
            if (dot > v4) {                 // strict >: lax.top_k lowest-index tie-break
                v4 = dot; i4 = cb + j;
                if (v4 > v3) { float t = v3; v3 = v4; v4 = t; int ti = i3; i3 = i4; i4 = ti; }
                if (v3 > v2) { float t = v2; v2 = v3; v3 = t; int ti = i2; i2 = i3; i3 = ti; }
                if (v2 > v1) { float t = v1; v1 = v2; v2 = t; int ti = i1; i1 = i2; i2 = ti; }
                if (v1 > v0) { float t = v0; v0 = v1; v1 = t; int ti = i0; i0 = i1; i1 = ti; }
            }
        }
    }
    int base = (split * NPIX + row) * KNN;
    g_pval[base + 0] = v0; g_pval[base + 1] = v1; g_pval[base + 2] = v2;
    g_pval[base + 3] = v3; g_pval[base + 4] = v4;
    g_pidx[base + 0] = i0; g_pidx[base + 1] = i1; g_pidx[base + 2] = i2;
    g_pidx[base + 3] = i3; g_pidx[base + 4] = i4;
}

// ---------------- K4: merge the CSPLIT partial top-5 lists per row ----------------
__global__ void k_merge() {
    int row = blockIdx.x * blockDim.x + threadIdx.x;
    if (row >= NPIX) return;
    float v0 = -INFINITY, v1 = -INFINITY, v2 = -INFINITY, v3 = -INFINITY, v4 = -INFINITY;
    int   i0 = 0, i1 = 0, i2 = 0, i3 = 0, i4 = 0;
    for (int s = 0; s < CSPLIT; s++) {      // ascending split => ascending index on ties
        int b = (s * NPIX + row) * KNN;
        #pragma unroll
        for (int k = 0; k < KNN; k++) {
            float d = g_pval[b + k];
            int   j = g_pidx[b + k];
            if (d > v4) {
                v4 = d; i4 = j;
                if (v4 > v3) { float t = v3; v3 = v4; v4 = t; int ti = i3; i3 = i4; i4 = ti; }
                if (v3 > v2) { float t = v2; v2 = v3; v3 = t; int ti = i2; i2 = i3; i3 = ti; }
                if (v2 > v1) { float t = v1; v1 = v2; v2 = t; int ti = i1; i1 = i2; i2 = ti; }
                if (v1 > v0) { float t = v0; v0 = v1; v1 = t; int ti = i0; i0 = i1; i1 = ti; }
            }
        }
    }
    int o = row * KNN;
    g_topk[o + 0] = i0; g_topk[o + 1] = i1; g_topk[o + 2] = i2;
    g_topk[o + 3] = i3; g_topk[o + 4] = i4;
}

// ---------------- K5: GAT fc  z = [hfeat|mfeat] @ Wg,  el/er per node --------------
__global__ void k_gatz(const float* __restrict__ Wg,
                       const float* __restrict__ al_v, const float* __restrict__ ar_v) {
    __shared__ float Ws[128 * 64];   // 32 KB
    __shared__ float als[64], ars[64];
    int tid = threadIdx.x;
    for (int i = tid; i < 128 * 64; i += 256) Ws[i] = Wg[i];
    if (tid < 64) { als[tid] = al_v[tid]; ars[tid] = ar_v[tid]; }
    __syncthreads();
    int n = blockIdx.x * 256 + tid;
    if (n >= NPIX) return;
    float acc[64];
    #pragma unroll
    for (int o = 0; o < 64; o++) acc[o] = 0.0f;
    for (int i = 0; i < 64; i++) {
        float xv = g_hfeat[n * 64 + i];
        #pragma unroll
        for (int o = 0; o < 64; o++) acc[o] = fmaf(Ws[i * 64 + o], xv, acc[o]);
    }
    for (int i = 0; i < 64; i++) {
        float xv = g_mfeat[n * 64 + i];
        #pragma unroll
        for (int o = 0; o < 64; o++) acc[o] = fmaf(Ws[(64 + i) * 64 + o], xv, acc[o]);
    }
    float el = 0.0f, er = 0.0f;
    #pragma unroll
    for (int o = 0; o < 64; o++) {
        float zv = acc[o];
        g_z[n * 64 + o] = zv;
        el = fmaf(zv, als[o], el);
        er = fmaf(zv, ars[o], er);
    }
    g_el[n] = el;
    g_er[n] = er;
}

// ---------------- K6: clear reduction buffers ----------------
__global__ void k_zero() {
    int t = blockIdx.x * blockDim.x + threadIdx.x;
    if (t < NPIX) { g_menc[t] = 0u; g_den[t] = 0.0f; }
    if (t < NPIX * CCH) g_agg[t] = 0.0f;
}

// edge helpers: faithful to reference's (mismatched) pairing:
// e < E5:  src = e % NPIX, dst = topk_flat[e];  else self loop.
__device__ __forceinline__ void edge_sd(int e, int& src, int& dst) {
    if (e < E5) { src = e % NPIX; dst = g_topk[e]; }
    else        { src = e - E5;   dst = src; }
}

// ---------------- K7: segment max via ordered-uint atomicMax ----------------
__global__ void k_edge_max() {
    int e = blockIdx.x * blockDim.x + threadIdx.x;
    if (e >= ETOT) return;
    int src, dst; edge_sd(e, src, dst);
    float l = g_el[src] + g_er[dst];
    l = (l >= 0.0f) ? l : 0.2f * l;
    atomicMax(&g_menc[dst], fenc(l));
}

// ---------------- K8: softmax denominator ----------------
__global__ void k_edge_den() {
    int e = blockIdx.x * blockDim.x + threadIdx.x;
    if (e >= ETOT) return;
    int src, dst; edge_sd(e, src, dst);
    float l = g_el[src] + g_er[dst];
    l = (l >= 0.0f) ? l : 0.2f * l;
    float m = fdec(g_menc[dst]);
    atomicAdd(&g_den[dst], expf(l - m));
}

// ---------------- K9: weighted aggregation (4 threads / edge, 16 ch each) ----------
__global__ void k_edge_agg() {
    int t = blockIdx.x * blockDim.x + threadIdx.x;
    int e = t >> 2;
    if (e >= ETOT) return;
    int c0 = (t & 3) * 16;
    int src, dst; edge_sd(e, src, dst);
    float l = g_el[src] + g_er[dst];
    l = (l >= 0.0f) ? l : 0.2f * l;
    float m = fdec(g_menc[dst]);
    float alpha = expf(l - m) / g_den[dst];
    const float* zs = g_z + src * 64 + c0;
    float* ag = g_agg + dst * 64 + c0;
    #pragma unroll
    for (int c = 0; c < 16; c++) atomicAdd(ag + c, alpha * zs[c]);
}

// ---------------- K10: transpose pixel-major agg -> channel-major fmap (+bg) -------
__global__ void k_transbias(const float* __restrict__ bg) {
    int t = blockIdx.x * blockDim.x + threadIdx.x;
    if (t >= NPIX * CCH) return;
    int c = t & 63;
    int n = t >> 6;
    g_fmap[c * NPIX + n] = g_agg[t] + bg[c];
}

// ---------------- K11: 3x3 conv (SAME, zero pad) + PReLU (+ optional residual) -----
// grid (6,6,4): 16x16 pixel tile, 16-out-channel group; 256 threads
__global__ __launch_bounds__(256) void k_conv3x3(const float* __restrict__ In,
                                                 const float* __restrict__ Kw,
                                                 const float* __restrict__ bias,
                                                 const float* __restrict__ aptr,
                                                 float* __restrict__ Out,
                                                 const float* __restrict__ resid) {
    __shared__ float ws[16 * 64 * 9];   // 36864 B
    __shared__ float tile[18 * 18];
    int og = blockIdx.z * 16;
    for (int i = threadIdx.x; i < 16 * 64 * 9; i += 256) ws[i] = Kw[og * 576 + i];
    float alpha = aptr[0];
    int tx = threadIdx.x % 16, ty = threadIdx.x / 16;
    int x0 = blockIdx.x * 16, y0 = blockIdx.y * 16;
    int ox = x0 + tx, oy = y0 + ty;
    float acc[16];
    #pragma unroll
    for (int o = 0; o < 16; o++) acc[o] = bias[og + o];
    for (int c = 0; c < 64; c++) {
        __syncthreads();
        for (int i = threadIdx.x; i < 324; i += 256) {
            int lx = i % 18 - 1 + x0;
            int ly = i / 18 - 1 + y0;
            tile[i] = (lx >= 0 && lx < WW && ly >= 0 && ly < HH)
                        ? In[c * NPIX + ly * WW + lx] : 0.0f;
        }
        __syncthreads();
        float r[9];
        #pragma unroll
        for (int ky = 0; ky < 3; ky++)
            #pragma unroll
            for (int kx = 0; kx < 3; kx++)
                r[ky * 3 + kx] = tile[(ty + ky) * 18 + tx + kx];
        #pragma unroll
        for (int o = 0; o < 16; o++) {
            const float* w = ws + (o * 64 + c) * 9;
            #pragma unroll
            for (int k = 0; k < 9; k++) acc[o] = fmaf(w[k], r[k], acc[o]);
        }
    }
    #pragma unroll
    for (int o = 0; o < 16; o++) {
        float v = acc[o];
        v = (v >= 0.0f) ? v : alpha * v;
        int oidx = (og + o) * NPIX + oy * WW + ox;
        if (resid) v += resid[oidx];
        Out[oidx] = v;
    }
}

// ---------------- launch ----------------
extern "C" void kernel_launch(void* const* d_in, const int* in_sizes, int n_in,
                              void* d_out, int out_size) {
    const float* msi  = (const float*)d_in[0];
    const float* hsi  = (const float*)d_in[1];
    const float* W1a  = (const float*)d_in[2];
    const float* b1a  = (const float*)d_in[3];
    const float* a1a  = (const float*)d_in[4];
    const float* W1b  = (const float*)d_in[5];
    const float* b1b  = (const float*)d_in[6];
    const float* a1b  = (const float*)d_in[7];
    const float* W2a  = (const float*)d_in[8];
    const float* b2a  = (const float*)d_in[9];
    const float* a2a  = (const float*)d_in[10];
    const float* W2b  = (const float*)d_in[11];
    const float* b2b  = (const float*)d_in[12];
    const float* a2b  = (const float*)d_in[13];
    const float* Wg   = (const float*)d_in[14];
    const float* attl = (const float*)d_in[15];
    const float* attr = (const float*)d_in[16];
    const float* bg   = (const float*)d_in[17];
    const float* Ku1  = (const float*)d_in[18];
    const float* bu1  = (const float*)d_in[19];
    const float* au1  = (const float*)d_in[20];
    const float* Ku2  = (const float*)d_in[21];
    const float* bu2  = (const float*)d_in[22];
    const float* au2  = (const float*)d_in[23];

    float *p_hsi_up, *p_tmp, *p_hfeat, *p_mfeat, *p_fmap, *p_up1;
    cudaGetSymbolAddress((void**)&p_hsi_up, g_hsi_up);
    cudaGetSymbolAddress((void**)&p_tmp,    g_tmp);
    cudaGetSymbolAddress((void**)&p_hfeat,  g_hfeat);
    cudaGetSymbolAddress((void**)&p_mfeat,  g_mfeat);
    cudaGetSymbolAddress((void**)&p_fmap,   g_fmap);
    cudaGetSymbolAddress((void**)&p_up1,    g_up1);

    k_bicubic<<<(CCH * NPIX + 255) / 256, 256>>>(hsi);

    k_lin64<<<36, 256>>>(p_hsi_up, 1, W1a, b1a, a1a, p_tmp);
    k_lin64<<<36, 256>>>(p_tmp,    0, W1b, b1b, a1b, p_hfeat);
    k_lin64<<<36, 256>>>(msi,      1, W2a, b2a, a2a, p_tmp);
    k_lin64<<<36, 256>>>(p_tmp,    0, W2b, b2b, a2b, p_mfeat);

    k_simtopk<<<dim3(36, CSPLIT), 256>>>();
    k_merge<<<36, 256>>>();

    k_gatz<<<36, 256>>>(Wg, attl, attr);
    k_zero<<<(NPIX * CCH + 255) / 256, 256>>>();
    k_edge_max<<<(ETOT + 255) / 256, 256>>>();
    k_edge_den<<<(ETOT + 255) / 256, 256>>>();
    k_edge_agg<<<(ETOT * 4 + 255) / 256, 256>>>();

    k_transbias<<<(NPIX * CCH + 255) / 256, 256>>>(bg);

    k_conv3x3<<<dim3(6, 6, 4), 256>>>(p_fmap, Ku1, bu1, au1, p_up1, nullptr);
    k_conv3x3<<<dim3(6, 6, 4), 256>>>(p_up1, Ku2, bu2, au2, (float*)d_out, p_hsi_up);
}

// round 4
// speedup vs baseline: 1.3928x; 1.3928x over previous
#include <cuda_runtime.h>
#include <math.h>

#define NPIX 9216
#define CCH  64
#define HH   96
#define WW   96
#define HS   24
#define KNN  5
#define CSPLIT 8
#define COLS_PER_SPLIT (NPIX / CSPLIT)   /* 1152 */
#define E5   (NPIX * KNN)                /* 46080 */
#define ETOT (E5 + NPIX)                 /* 55296 */

// ---------------- scratch (static device globals; no allocation) ----------------
__device__ float    g_hsi_up[CCH * NPIX];   // channel-major [c][pix]; also the residual
__device__ float    g_hfeat[NPIX * CCH];    // pixel-major [pix][c]
__device__ float    g_mfeat[NPIX * CCH];
__device__ float    g_z    [NPIX * CCH];
__device__ float    g_el   [NPIX];
__device__ float    g_er   [NPIX];
__device__ float    g_pval [CSPLIT * NPIX * KNN];
__device__ int      g_pidx [CSPLIT * NPIX * KNN];
__device__ int      g_topk [NPIX * KNN];
__device__ float    g_den  [NPIX];
__device__ float    g_agg  [NPIX * CCH];    // pixel-major
__device__ float    g_fmap [CCH * NPIX];    // channel-major
__device__ float    g_up1  [CCH * NPIX];

// ---------------- helpers ----------------
__device__ __forceinline__ unsigned long long fma2(unsigned long long a,
                                                   unsigned long long b,
                                                   unsigned long long c) {
    unsigned long long d;
    asm("fma.rn.f32x2 %0, %1, %2, %3;" : "=l"(d) : "l"(a), "l"(b), "l"(c));
    return d;
}

__device__ __forceinline__ float cubw(float d) {
    d = fabsf(d);
    const float a = -0.75f;
    if (d <= 1.0f) return ((a + 2.0f) * d - (a + 3.0f)) * d * d + 1.0f;
    if (d < 2.0f)  return ((a * d - 5.0f * a) * d + 8.0f * a) * d - 4.0f * a;
    return 0.0f;
}

// ---------------- K1: bicubic x4 upsample (24x24 -> 96x96, border replicate) ----
__global__ void k_bicubic(const float* __restrict__ in) {
    int t = blockIdx.x * blockDim.x + threadIdx.x;   // c*NPIX + y*96 + x
    if (t >= CCH * NPIX) return;
    int x = t % WW;
    int y = (t / WW) % HH;
    int c = t / NPIX;
    float fy = (y + 0.5f) * 0.25f - 0.5f;
    float iy = floorf(fy); float ty = fy - iy;
    float fx = (x + 0.5f) * 0.25f - 0.5f;
    float ix = floorf(fx); float tx = fx - ix;
    float wy[4], wx[4]; int sy[4], sx[4];
    #pragma unroll
    for (int o = 0; o < 4; o++) {
        wy[o] = cubw(ty - (float)(o - 1));
        wx[o] = cubw(tx - (float)(o - 1));
        sy[o] = min(max((int)iy + o - 1, 0), HS - 1);
        sx[o] = min(max((int)ix + o - 1, 0), HS - 1);
    }
    const float* ic = in + c * HS * HS;
    float acc = 0.0f;
    #pragma unroll
    for (int i = 0; i < 4; i++) {
        float r = 0.0f;
        #pragma unroll
        for (int j = 0; j < 4; j++) r = fmaf(wx[j], ic[sy[i] * HS + sx[j]], r);
        acc = fmaf(wy[i], r, acc);
    }
    g_hsi_up[t] = acc;
}

// ---------------- K2: fused 2-layer 1x1-conv embed, both branches -----------------
// grid (144, 2): 64-pixel tiles, branch = blockIdx.y. block 256 = (tx16, ty16),
// each thread computes 4 pixels (tx+16i) x 4 outputs (ty*4+j).
__global__ __launch_bounds__(256) void k_embed(
    const float* __restrict__ X0, const float* __restrict__ X1,
    const float* __restrict__ Wa0, const float* __restrict__ ba0, const float* __restrict__ aa0,
    const float* __restrict__ Wb0, const float* __restrict__ bb0, const float* __restrict__ ab0,
    const float* __restrict__ Wa1, const float* __restrict__ ba1, const float* __restrict__ aa1,
    const float* __restrict__ Wb1, const float* __restrict__ bb1, const float* __restrict__ ab1,
    float* __restrict__ Y0, float* __restrict__ Y1)
{
    __shared__ float xs[64 * 64];
    __shared__ float ws[64 * 64];
    __shared__ float bsh[64];
    __shared__ float s_alpha;
    int br = blockIdx.y;
    const float* X  = br ? X1 : X0;
    const float* Wa = br ? Wa1 : Wa0;
    const float* ba = br ? ba1 : ba0;
    const float* aa = br ? aa1 : aa0;
    const float* Wb = br ? Wb1 : Wb0;
    const float* bb = br ? bb1 : bb0;
    const float* ab = br ? ab1 : ab0;
    float* Y = br ? Y1 : Y0;
    int tid = threadIdx.x;
    int tx = tid & 15, ty = tid >> 4;
    int pbase = blockIdx.x * 64;

    // xs[c][p]: channel-major input -> coalesced float4 loads
    for (int t = tid; t < 1024; t += 256) {
        int c = t >> 4, p4 = t & 15;
        ((float4*)xs)[c * 16 + p4] = *(const float4*)(X + c * NPIX + pbase + p4 * 4);
    }
    for (int t = tid; t < 1024; t += 256)
        ((float4*)ws)[t] = ((const float4*)Wa)[t];
    if (tid < 64) bsh[tid] = ba[tid];
    if (tid == 0) s_alpha = aa[0];
    __syncthreads();

    float acc[4][4];
    #pragma unroll
    for (int j = 0; j < 4; j++)
        #pragma unroll
        for (int i = 0; i < 4; i++) acc[j][i] = bsh[ty * 4 + j];
    for (int c = 0; c < 64; c++) {
        float xv[4], wv[4];
        #pragma unroll
        for (int i = 0; i < 4; i++) xv[i] = xs[c * 64 + tx + 16 * i];
        #pragma unroll
        for (int j = 0; j < 4; j++) wv[j] = ws[(ty * 4 + j) * 64 + c];
        #pragma unroll
        for (int j = 0; j < 4; j++)
            #pragma unroll
            for (int i = 0; i < 4; i++) acc[j][i] = fmaf(wv[j], xv[i], acc[j][i]);
    }
    float al = s_alpha;
    __syncthreads();   // all stage-1 reads of xs / ws / s_alpha done

    // PReLU + stage intermediate back into xs; reload weights/bias for layer 2
    #pragma unroll
    for (int j = 0; j < 4; j++)
        #pragma unroll
        for (int i = 0; i < 4; i++) {
            float v = acc[j][i];
            v = (v >= 0.0f) ? v : al * v;
            xs[(ty * 4 + j) * 64 + tx + 16 * i] = v;
        }
    for (int t = tid; t < 1024; t += 256)
        ((float4*)ws)[t] = ((const float4*)Wb)[t];
    if (tid < 64) bsh[tid] = bb[tid];
    if (tid == 0) s_alpha = ab[0];
    __syncthreads();

    #pragma unroll
    for (int j = 0; j < 4; j++)
        #pragma unroll
        for (int i = 0; i < 4; i++) acc[j][i] = bsh[ty * 4 + j];
    for (int c = 0; c < 64; c++) {
        float xv[4], wv[4];
        #pragma unroll
        for (int i = 0; i < 4; i++) xv[i] = xs[c * 64 + tx + 16 * i];
        #pragma unroll
        for (int j = 0; j < 4; j++) wv[j] = ws[(ty * 4 + j) * 64 + c];
        #pragma unroll
        for (int j = 0; j < 4; j++)
            #pragma unroll
            for (int i = 0; i < 4; i++) acc[j][i] = fmaf(wv[j], xv[i], acc[j][i]);
    }
    float al2 = s_alpha;
    #pragma unroll
    for (int i = 0; i < 4; i++) {
        float4 o4;
        float v;
        v = acc[0][i]; o4.x = (v >= 0.0f) ? v : al2 * v;
        v = acc[1][i]; o4.y = (v >= 0.0f) ? v : al2 * v;
        v = acc[2][i]; o4.z = (v >= 0.0f) ? v : al2 * v;
        v = acc[3][i]; o4.w = (v >= 0.0f) ? v : al2 * v;
        *(float4*)(Y + (pbase + tx + 16 * i) * 64 + ty * 4) = o4;
    }
}

// ---------------- K3: fused sim GEMM + per-row running top-5 ----------------------
__global__ __launch_bounds__(256, 2) void k_simtopk() {
    __shared__ float sm[64 * 64];
    const int row   = blockIdx.x * 256 + threadIdx.x;
    const int split = blockIdx.y;
    const int cbase = split * COLS_PER_SPLIT;

    unsigned long long h2[32];
    {
        const unsigned long long* hr = (const unsigned long long*)(g_hfeat + row * 64);
        #pragma unroll
        for (int i = 0; i < 32; i++) h2[i] = hr[i];
    }
    float v0 = -INFINITY, v1 = -INFINITY, v2 = -INFINITY, v3 = -INFINITY, v4 = -INFINITY;
    int   i0 = 0, i1 = 0, i2 = 0, i3 = 0, i4 = 0;

    for (int tile = 0; tile < COLS_PER_SPLIT / 64; tile++) {
        int cb = cbase + tile * 64;
        __syncthreads();
        {
            const float4* src = (const float4*)(g_mfeat + cb * 64);
            float4* dst = (float4*)sm;
            #pragma unroll
            for (int i = 0; i < 4; i++) dst[threadIdx.x + 256 * i] = src[threadIdx.x + 256 * i];
        }
        __syncthreads();
        for (int j = 0; j < 64; j++) {
            const ulonglong2* mr = (const ulonglong2*)(sm + j * 64);
            unsigned long long a0 = 0ull, a1 = 0ull;
            #pragma unroll
            for (int q = 0; q < 16; q++) {
                ulonglong2 v = mr[q];
                a0 = fma2(h2[2 * q],     v.x, a0);
                a1 = fma2(h2[2 * q + 1], v.y, a1);
            }
            float x0 = __uint_as_float((unsigned)a0);
            float x1 = __uint_as_float((unsigned)(a0 >> 32));
            float y0 = __uint_as_float((unsigned)a1);
            float y1 = __uint_as_float((unsigned)(a1 >> 32));
            float dot = (x0 + y0) + (x1 + y1);
            if (dot > v4) {                 // strict >: lax.top_k lowest-index tie-break
                v4 = dot; i4 = cb + j;
                if (v4 > v3) { float t = v3; v3 = v4; v4 = t; int ti = i3; i3 = i4; i4 = ti; }
                if (v3 > v2) { float t = v2; v2 = v3; v3 = t; int ti = i2; i2 = i3; i3 = ti; }
                if (v2 > v1) { float t = v1; v1 = v2; v2 = t; int ti = i1; i1 = i2; i2 = ti; }
                if (v1 > v0) { float t = v0; v0 = v1; v1 = t; int ti = i0; i0 = i1; i1 = ti; }
            }
        }
    }
    int base = (split * NPIX + row) * KNN;
    g_pval[base + 0] = v0; g_pval[base + 1] = v1; g_pval[base + 2] = v2;
    g_pval[base + 3] = v3; g_pval[base + 4] = v4;
    g_pidx[base + 0] = i0; g_pidx[base + 1] = i1; g_pidx[base + 2] = i2;
    g_pidx[base + 3] = i3; g_pidx[base + 4] = i4;
}

// ---------------- K4: merge the CSPLIT partial top-5 lists per row ----------------
__global__ void k_merge() {
    int row = blockIdx.x * blockDim.x + threadIdx.x;
    if (row >= NPIX) return;
    float v0 = -INFINITY, v1 = -INFINITY, v2 = -INFINITY, v3 = -INFINITY, v4 = -INFINITY;
    int   i0 = 0, i1 = 0, i2 = 0, i3 = 0, i4 = 0;
    for (int s = 0; s < CSPLIT; s++) {      // ascending split => ascending index on ties
        int b = (s * NPIX + row) * KNN;
        #pragma unroll
        for (int k = 0; k < KNN; k++) {
            float d = g_pval[b + k];
            int   j = g_pidx[b + k];
            if (d > v4) {
                v4 = d; i4 = j;
                if (v4 > v3) { float t = v3; v3 = v4; v4 = t; int ti = i3; i3 = i4; i4 = ti; }
                if (v3 > v2) { float t = v2; v2 = v3; v3 = t; int ti = i2; i2 = i3; i3 = ti; }
                if (v2 > v1) { float t = v1; v1 = v2; v2 = t; int ti = i1; i1 = i2; i2 = ti; }
                if (v1 > v0) { float t = v0; v0 = v1; v1 = t; int ti = i0; i0 = i1; i1 = ti; }
            }
        }
    }
    int o = row * KNN;
    g_topk[o + 0] = i0; g_topk[o + 1] = i1; g_topk[o + 2] = i2;
    g_topk[o + 3] = i3; g_topk[o + 4] = i4;
}

// ---------------- K5: GAT fc  z = [hfeat|mfeat] @ Wg,  el/er per node --------------
// grid 144 (64-pixel tiles), block 256, 4 pix x 4 out per thread, K in 2 halves.
__global__ __launch_bounds__(256) void k_gatz(const float* __restrict__ Wg,
                                              const float* __restrict__ alv,
                                              const float* __restrict__ arv) {
    __shared__ float xs[64 * 65];
    __shared__ float ws[64 * 64];
    __shared__ float als[64], ars[64];
    __shared__ float sel[64], ser[64];
    int tid = threadIdx.x, tx = tid & 15, ty = tid >> 4;
    int pbase = blockIdx.x * 64;
    if (tid < 64) { als[tid] = alv[tid]; ars[tid] = arv[tid]; sel[tid] = 0.0f; ser[tid] = 0.0f; }

    float acc[4][4];
    #pragma unroll
    for (int j = 0; j < 4; j++)
        #pragma unroll
        for (int i = 0; i < 4; i++) acc[j][i] = 0.0f;

    for (int half = 0; half < 2; half++) {
        const float* X = half ? g_mfeat : g_hfeat;
        __syncthreads();
        // transpose-load xs[c][p] from pixel-major X (pitch 65 => conflict-free)
        for (int t = tid; t < 1024; t += 256) {
            int p = t >> 4, cc = t & 15;
            float4 v = *(const float4*)(X + (pbase + p) * 64 + cc * 4);
            xs[(4 * cc + 0) * 65 + p] = v.x;
            xs[(4 * cc + 1) * 65 + p] = v.y;
            xs[(4 * cc + 2) * 65 + p] = v.z;
            xs[(4 * cc + 3) * 65 + p] = v.w;
        }
        for (int t = tid; t < 1024; t += 256)
            ((float4*)ws)[t] = ((const float4*)(Wg + half * 64 * 64))[t];
        __syncthreads();
        for (int c = 0; c < 64; c++) {
            float xv[4];
            #pragma unroll
            for (int i = 0; i < 4; i++) xv[i] = xs[c * 65 + tx + 16 * i];
            float4 w4 = *(const float4*)(ws + c * 64 + ty * 4);
            float wv[4] = {w4.x, w4.y, w4.z, w4.w};
            #pragma unroll
            for (int j = 0; j < 4; j++)
                #pragma unroll
                for (int i = 0; i < 4; i++) acc[j][i] = fmaf(wv[j], xv[i], acc[j][i]);
        }
    }

    float a_l[4], a_r[4];
    #pragma unroll
    for (int j = 0; j < 4; j++) { a_l[j] = als[ty * 4 + j]; a_r[j] = ars[ty * 4 + j]; }
    #pragma unroll
    for (int i = 0; i < 4; i++) {
        int p = pbase + tx + 16 * i;
        float4 z4 = make_float4(acc[0][i], acc[1][i], acc[2][i], acc[3][i]);
        *(float4*)(g_z + p * 64 + ty * 4) = z4;
        float e_l = 0.0f, e_r = 0.0f;
        #pragma unroll
        for (int j = 0; j < 4; j++) {
            e_l = fmaf(acc[j][i], a_l[j], e_l);
            e_r = fmaf(acc[j][i], a_r[j], e_r);
        }
        atomicAdd(&sel[tx + 16 * i], e_l);
        atomicAdd(&ser[tx + 16 * i], e_r);
    }
    __syncthreads();
    if (tid < 64) { g_el[pbase + tid] = sel[tid]; g_er[pbase + tid] = ser[tid]; }
}

// ---------------- K6: clear reduction buffers ----------------
__global__ void k_zero() {
    int t = blockIdx.x * blockDim.x + threadIdx.x;
    if (t < NPIX) g_den[t] = 0.0f;
    if (t < NPIX * CCH) g_agg[t] = 0.0f;
}

// edge helpers: faithful to reference's (mismatched) pairing:
// e < E5:  src = e % NPIX, dst = topk_flat[e];  else self loop.
__device__ __forceinline__ void edge_sd(int e, int& src, int& dst) {
    if (e < E5) { src = e % NPIX; dst = g_topk[e]; }
    else        { src = e - E5;   dst = src; }
}

// ---------------- K7: softmax denominator (no max shift: logits are O(4)) ---------
__global__ void k_edge_den() {
    int e = blockIdx.x * blockDim.x + threadIdx.x;
    if (e >= ETOT) return;
    int src, dst; edge_sd(e, src, dst);
    float l = g_el[src] + g_er[dst];
    l = (l >= 0.0f) ? l : 0.2f * l;
    atomicAdd(&g_den[dst], expf(l));
}

// ---------------- K8: weighted aggregation (4 threads / edge, 16 ch each) ----------
__global__ void k_edge_agg() {
    int t = blockIdx.x * blockDim.x + threadIdx.x;
    int e = t >> 2;
    if (e >= ETOT) return;
    int c0 = (t & 3) * 16;
    int src, dst; edge_sd(e, src, dst);
    float l = g_el[src] + g_er[dst];
    l = (l >= 0.0f) ? l : 0.2f * l;
    float alpha = expf(l) / g_den[dst];
    const float* zs = g_z + src * 64 + c0;
    float* ag = g_agg + dst * 64 + c0;
    #pragma unroll
    for (int c = 0; c < 16; c++) atomicAdd(ag + c, alpha * zs[c]);
}

// ---------------- K9: tiled transpose pixel-major agg -> channel-major (+bg) -------
__global__ __launch_bounds__(256) void k_transbias(const float* __restrict__ bg) {
    __shared__ float tb[64 * 65];
    __shared__ float bs[64];
    int tid = threadIdx.x;
    int nb = blockIdx.x * 64;
    if (tid < 64) bs[tid] = bg[tid];
    for (int t = tid; t < 1024; t += 256) {
        int p = t >> 4, cc = t & 15;
        float4 v = *(const float4*)(g_agg + (nb + p) * 64 + cc * 4);
        tb[(4 * cc + 0) * 65 + p] = v.x;
        tb[(4 * cc + 1) * 65 + p] = v.y;
        tb[(4 * cc + 2) * 65 + p] = v.z;
        tb[(4 * cc + 3) * 65 + p] = v.w;
    }
    __syncthreads();
    for (int k = 0; k < 16; k++) {
        int idx = tid + k * 256;           // c = idx/64, nn = idx%64
        int c = idx >> 6, nn = idx & 63;
        g_fmap[c * NPIX + nb + nn] = tb[c * 65 + nn] + bs[c];
    }
}

// ---------------- K10: 3x3 conv (SAME, zero pad) + PReLU (+ optional residual) -----
// grid (6,6,4): 16x16 pixel tile, 16-out-channel group; 256 threads
// thread = (sub 0..3 -> 4 outputs, quad 0..63 -> 4 consecutive x pixels)
__global__ __launch_bounds__(256) void k_conv3x3(const float* __restrict__ In,
                                                 const float* __restrict__ Kw,
                                                 const float* __restrict__ bias,
                                                 const float* __restrict__ aptr,
                                                 float* __restrict__ Out,
                                                 const float* __restrict__ resid) {
    __shared__ float ws[16 * 64 * 9];   // 36864 B
    __shared__ float tile[18 * 18];
    int og = blockIdx.z * 16;
    for (int i = threadIdx.x; i < 16 * 64 * 9; i += 256) ws[i] = Kw[og * 576 + i];
    float alpha = aptr[0];
    int sub = threadIdx.x >> 6;          // 0..3: outputs og + sub*4 + j
    int q   = threadIdx.x & 63;          // quad id
    int qx  = q & 3, y = q >> 2;         // x quad 0..3, row 0..15
    int x0 = blockIdx.x * 16, y0 = blockIdx.y * 16;
    float acc[4][4];
    #pragma unroll
    for (int j = 0; j < 4; j++) {
        float b = bias[og + sub * 4 + j];
        #pragma unroll
        for (int i = 0; i < 4; i++) acc[j][i] = b;
    }
    for (int c = 0; c < 64; c++) {
        __syncthreads();
        for (int i = threadIdx.x; i < 324; i += 256) {
            int lx = i % 18 - 1 + x0;
            int ly = i / 18 - 1 + y0;
            tile[i] = (lx >= 0 && lx < WW && ly >= 0 && ly < HH)
                        ? In[c * NPIX + ly * WW + lx] : 0.0f;
        }
        __syncthreads();
        float r[3][6];
        #pragma unroll
        for (int ky = 0; ky < 3; ky++)
            #pragma unroll
            for (int m = 0; m < 6; m++)
                r[ky][m] = tile[(y + ky) * 18 + qx * 4 + m];
        #pragma unroll
        for (int j = 0; j < 4; j++) {
            const float* w = ws + ((sub * 4 + j) * 64 + c) * 9;
            float wv[9];
            #pragma unroll
            for (int k = 0; k < 9; k++) wv[k] = w[k];
            #pragma unroll
            for (int i = 0; i < 4; i++)
                #pragma unroll
                for (int ky = 0; ky < 3; ky++)
                    #pragma unroll
                    for (int kx = 0; kx < 3; kx++)
                        acc[j][i] = fmaf(wv[ky * 3 + kx], r[ky][kx + i], acc[j][i]);
        }
    }
    int pix0 = (y0 + y) * WW + x0 + qx * 4;
    #pragma unroll
    for (int j = 0; j < 4; j++) {
        int o = og + sub * 4 + j;
        float4 v4;
        float v;
        v = acc[j][0]; v4.x = (v >= 0.0f) ? v : alpha * v;
        v = acc[j][1]; v4.y = (v >= 0.0f) ? v : alpha * v;
        v = acc[j][2]; v4.z = (v >= 0.0f) ? v : alpha * v;
        v = acc[j][3]; v4.w = (v >= 0.0f) ? v : alpha * v;
        if (resid) {
            float4 rr = *(const float4*)(resid + o * NPIX + pix0);
            v4.x += rr.x; v4.y += rr.y; v4.z += rr.z; v4.w += rr.w;
        }
        *(float4*)(Out + o * NPIX + pix0) = v4;
    }
}

// ---------------- launch ----------------
extern "C" void kernel_launch(void* const* d_in, const int* in_sizes, int n_in,
                              void* d_out, int out_size) {
    const float* msi  = (const float*)d_in[0];
    const float* hsi  = (const float*)d_in[1];
    const float* W1a  = (const float*)d_in[2];
    const float* b1a  = (const float*)d_in[3];
    const float* a1a  = (const float*)d_in[4];
    const float* W1b  = (const float*)d_in[5];
    const float* b1b  = (const float*)d_in[6];
    const float* a1b  = (const float*)d_in[7];
    const float* W2a  = (const float*)d_in[8];
    const float* b2a  = (const float*)d_in[9];
    const float* a2a  = (const float*)d_in[10];
    const float* W2b  = (const float*)d_in[11];
    const float* b2b  = (const float*)d_in[12];
    const float* a2b  = (const float*)d_in[13];
    const float* Wg   = (const float*)d_in[14];
    const float* attl = (const float*)d_in[15];
    const float* attr = (const float*)d_in[16];
    const float* bg   = (const float*)d_in[17];
    const float* Ku1  = (const float*)d_in[18];
    const float* bu1  = (const float*)d_in[19];
    const float* au1  = (const float*)d_in[20];
    const float* Ku2  = (const float*)d_in[21];
    const float* bu2  = (const float*)d_in[22];
    const float* au2  = (const float*)d_in[23];

    float *p_hsi_up, *p_hfeat, *p_mfeat, *p_fmap, *p_up1;
    cudaGetSymbolAddress((void**)&p_hsi_up, g_hsi_up);
    cudaGetSymbolAddress((void**)&p_hfeat,  g_hfeat);
    cudaGetSymbolAddress((void**)&p_mfeat,  g_mfeat);
    cudaGetSymbolAddress((void**)&p_fmap,   g_fmap);
    cudaGetSymbolAddress((void**)&p_up1,    g_up1);

    k_bicubic<<<(CCH * NPIX + 255) / 256, 256>>>(hsi);

    k_embed<<<dim3(NPIX / 64, 2), 256>>>(p_hsi_up, msi,
                                         W1a, b1a, a1a, W1b, b1b, a1b,
                                         W2a, b2a, a2a, W2b, b2b, a2b,
                                         p_hfeat, p_mfeat);

    k_simtopk<<<dim3(36, CSPLIT), 256>>>();
    k_merge<<<36, 256>>>();

    k_gatz<<<NPIX / 64, 256>>>(Wg, attl, attr);
    k_zero<<<(NPIX * CCH + 255) / 256, 256>>>();
    k_edge_den<<<(ETOT + 255) / 256, 256>>>();
    k_edge_agg<<<(ETOT * 4 + 255) / 256, 256>>>();

    k_transbias<<<NPIX / 64, 256>>>(bg);

    k_conv3x3<<<dim3(6, 6, 4), 256>>>(p_fmap, Ku1, bu1, au1, p_up1, nullptr);
    k_conv3x3<<<dim3(6, 6, 4), 256>>>(p_up1, Ku2, bu2, au2, (float*)d_out, p_hsi_up);
}

// round 5
// speedup vs baseline: 1.6662x; 1.1963x over previous
#include <cuda_runtime.h>
#include <cuda_bf16.h>
#include <math.h>

#define NPIX 9216
#define CCH  64
#define HH   96
#define WW   96
#define HS   24
#define KNN  5
#define E5   (NPIX * KNN)                /* 46080 */
#define ETOT (E5 + NPIX)                 /* 55296 */
#define NCAND 64                         /* candidates per row (2 splits x 4 groups x 8) */

// ---------------- scratch (static device globals; no allocation) ----------------
__device__ float    g_hsi_up[CCH * NPIX];   // channel-major [c][pix]; also the residual
__device__ float    g_hfeat[NPIX * CCH];    // pixel-major [pix][c]
__device__ float    g_mfeat[NPIX * CCH];
__device__ unsigned short g_hbf[NPIX * CCH];  // bf16 copies, pixel-major
__device__ unsigned short g_mbf[NPIX * CCH];
__device__ float    g_z    [NPIX * CCH];
__device__ float    g_el   [NPIX];
__device__ float    g_er   [NPIX];
__device__ float    g_cval [NPIX * NCAND];
__device__ int      g_cidx [NPIX * NCAND];
__device__ int      g_topk [NPIX * KNN];
__device__ float    g_den  [NPIX];
__device__ float    g_agg  [NPIX * CCH];    // pixel-major
__device__ float    g_fmap [CCH * NPIX];    // channel-major
__device__ float    g_up1  [CCH * NPIX];

// ---------------- helpers ----------------
__device__ __forceinline__ unsigned pack_bf16x2(float lo, float hi) {
    unsigned d;
    asm("cvt.rn.bf16x2.f32 %0, %1, %2;" : "=r"(d) : "f"(hi), "f"(lo));
    return d;
}

__device__ __forceinline__ float cubw(float d) {
    d = fabsf(d);
    const float a = -0.75f;
    if (d <= 1.0f) return ((a + 2.0f) * d - (a + 3.0f)) * d * d + 1.0f;
    if (d < 2.0f)  return ((a * d - 5.0f * a) * d + 8.0f * a) * d - 4.0f * a;
    return 0.0f;
}

// top-8 running list, all-static indexing (stays in registers)
__device__ __forceinline__ void top8_update(float (&v)[8], int (&id)[8], float val, int idx) {
    if (val <= v[7]) return;
    v[7] = val; id[7] = idx;
    #pragma unroll
    for (int s = 7; s > 0; s--) {
        if (v[s] > v[s - 1]) {
            float tv = v[s - 1]; v[s - 1] = v[s]; v[s] = tv;
            int   ti = id[s - 1]; id[s - 1] = id[s]; id[s] = ti;
        }
    }
}

// ---------------- K1: bicubic x4 upsample (24x24 -> 96x96, border replicate) ----
__global__ void k_bicubic(const float* __restrict__ in) {
    int t = blockIdx.x * blockDim.x + threadIdx.x;   // c*NPIX + y*96 + x
    if (t >= CCH * NPIX) return;
    int x = t % WW;
    int y = (t / WW) % HH;
    int c = t / NPIX;
    float fy = (y + 0.5f) * 0.25f - 0.5f;
    float iy = floorf(fy); float ty = fy - iy;
    float fx = (x + 0.5f) * 0.25f - 0.5f;
    float ix = floorf(fx); float tx = fx - ix;
    float wy[4], wx[4]; int sy[4], sx[4];
    #pragma unroll
    for (int o = 0; o < 4; o++) {
        wy[o] = cubw(ty - (float)(o - 1));
        wx[o] = cubw(tx - (float)(o - 1));
        sy[o] = min(max((int)iy + o - 1, 0), HS - 1);
        sx[o] = min(max((int)ix + o - 1, 0), HS - 1);
    }
    const float* ic = in + c * HS * HS;
    float acc = 0.0f;
    #pragma unroll
    for (int i = 0; i < 4; i++) {
        float r = 0.0f;
        #pragma unroll
        for (int j = 0; j < 4; j++) r = fmaf(wx[j], ic[sy[i] * HS + sx[j]], r);
        acc = fmaf(wy[i], r, acc);
    }
    g_hsi_up[t] = acc;
}

// ---------------- K2: fused 2-layer 1x1-conv embed, both branches -----------------
// grid (144, 2); also emits bf16 copies of the outputs for the HMMA sim kernel.
__global__ __launch_bounds__(256) void k_embed(
    const float* __restrict__ X0, const float* __restrict__ X1,
    const float* __restrict__ Wa0, const float* __restrict__ ba0, const float* __restrict__ aa0,
    const float* __restrict__ Wb0, const float* __restrict__ bb0, const float* __restrict__ ab0,
    const float* __restrict__ Wa1, const float* __restrict__ ba1, const float* __restrict__ aa1,
    const float* __restrict__ Wb1, const float* __restrict__ bb1, const float* __restrict__ ab1,
    float* __restrict__ Y0, float* __restrict__ Y1,
    unsigned short* __restrict__ Yb0, unsigned short* __restrict__ Yb1)
{
    __shared__ float xs[64 * 64];
    __shared__ float ws[64 * 64];
    __shared__ float bsh[64];
    __shared__ float s_alpha;
    int br = blockIdx.y;
    const float* X  = br ? X1 : X0;
    const float* Wa = br ? Wa1 : Wa0;
    const float* ba = br ? ba1 : ba0;
    const float* aa = br ? aa1 : aa0;
    const float* Wb = br ? Wb1 : Wb0;
    const float* bb = br ? bb1 : bb0;
    const float* ab = br ? ab1 : ab0;
    float* Y = br ? Y1 : Y0;
    unsigned short* Yb = br ? Yb1 : Yb0;
    int tid = threadIdx.x;
    int tx = tid & 15, ty = tid >> 4;
    int pbase = blockIdx.x * 64;

    for (int t = tid; t < 1024; t += 256) {
        int c = t >> 4, p4 = t & 15;
        ((float4*)xs)[c * 16 + p4] = *(const float4*)(X + c * NPIX + pbase + p4 * 4);
    }
    for (int t = tid; t < 1024; t += 256)
        ((float4*)ws)[t] = ((const float4*)Wa)[t];
    if (tid < 64) bsh[tid] = ba[tid];
    if (tid == 0) s_alpha = aa[0];
    __syncthreads();

    float acc[4][4];
    #pragma unroll
    for (int j = 0; j < 4; j++)
        #pragma unroll
        for (int i = 0; i < 4; i++) acc[j][i] = bsh[ty * 4 + j];
    for (int c = 0; c < 64; c++) {
        float xv[4], wv[4];
        #pragma unroll
        for (int i = 0; i < 4; i++) xv[i] = xs[c * 64 + tx + 16 * i];
        #pragma unroll
        for (int j = 0; j < 4; j++) wv[j] = ws[(ty * 4 + j) * 64 + c];
        #pragma unroll
        for (int j = 0; j < 4; j++)
            #pragma unroll
            for (int i = 0; i < 4; i++) acc[j][i] = fmaf(wv[j], xv[i], acc[j][i]);
    }
    float al = s_alpha;
    __syncthreads();

    #pragma unroll
    for (int j = 0; j < 4; j++)
        #pragma unroll
        for (int i = 0; i < 4; i++) {
            float v = acc[j][i];
            v = (v >= 0.0f) ? v : al * v;
            xs[(ty * 4 + j) * 64 + tx + 16 * i] = v;
        }
    for (int t = tid; t < 1024; t += 256)
        ((float4*)ws)[t] = ((const float4*)Wb)[t];
    if (tid < 64) bsh[tid] = bb[tid];
    if (tid == 0) s_alpha = ab[0];
    __syncthreads();

    #pragma unroll
    for (int j = 0; j < 4; j++)
        #pragma unroll
        for (int i = 0; i < 4; i++) acc[j][i] = bsh[ty * 4 + j];
    for (int c = 0; c < 64; c++) {
        float xv[4], wv[4];
        #pragma unroll
        for (int i = 0; i < 4; i++) xv[i] = xs[c * 64 + tx + 16 * i];
        #pragma unroll
        for (int j = 0; j < 4; j++) wv[j] = ws[(ty * 4 + j) * 64 + c];
        #pragma unroll
        for (int j = 0; j < 4; j++)
            #pragma unroll
            for (int i = 0; i < 4; i++) acc[j][i] = fmaf(wv[j], xv[i], acc[j][i]);
    }
    float al2 = s_alpha;
    #pragma unroll
    for (int i = 0; i < 4; i++) {
        int pix = pbase + tx + 16 * i;
        float4 o4;
        float v;
        v = acc[0][i]; o4.x = (v >= 0.0f) ? v : al2 * v;
        v = acc[1][i]; o4.y = (v >= 0.0f) ? v : al2 * v;
        v = acc[2][i]; o4.z = (v >= 0.0f) ? v : al2 * v;
        v = acc[3][i]; o4.w = (v >= 0.0f) ? v : al2 * v;
        *(float4*)(Y + pix * 64 + ty * 4) = o4;
        uint2 b2;
        b2.x = pack_bf16x2(o4.x, o4.y);
        b2.y = pack_bf16x2(o4.z, o4.w);
        *(uint2*)(Yb + pix * 64 + ty * 4) = b2;
    }
}

// ---------------- K3: bf16 HMMA sim GEMM + fused per-thread top-8 candidates -------
// grid (72, 2): 128 rows per block, column-half per blockIdx.y. 256 threads = 8 warps,
// warp w owns rows rowbase + w*16 .. +15 (m16n8k16 layout). B tile staged in smem.
#define BPITCH 72   /* bf16 elems per B-tile row: 144 bytes -> conflict-free frag LDS */
__global__ __launch_bounds__(256) void k_sim_hmma() {
    __shared__ __align__(16) unsigned short Bs[128 * BPITCH];
    int tid = threadIdx.x;
    int w = tid >> 5, lane = tid & 31;
    int rowbase = blockIdx.x * 128;
    int split = blockIdx.y;
    int colbase = split * 4608;

    int r0 = rowbase + w * 16 + (lane >> 2);   // accum rows for this thread
    int r1 = r0 + 8;
    int lg = lane & 3;                          // lane group: covers cols n%8 in {2lg,2lg+1}

    // A fragments: 4 k-steps x 4 regs, register resident for the whole kernel
    unsigned a[4][4];
    #pragma unroll
    for (int ks = 0; ks < 4; ks++) {
        int k0 = ks * 16 + lg * 2;
        a[ks][0] = *(const unsigned*)(g_hbf + r0 * 64 + k0);
        a[ks][1] = *(const unsigned*)(g_hbf + r1 * 64 + k0);
        a[ks][2] = *(const unsigned*)(g_hbf + r0 * 64 + k0 + 8);
        a[ks][3] = *(const unsigned*)(g_hbf + r1 * 64 + k0 + 8);
    }

    float v0[8], v1[8]; int id0[8], id1[8];
    #pragma unroll
    for (int j = 0; j < 8; j++) {
        v0[j] = -INFINITY; v1[j] = -INFINITY; id0[j] = 0; id1[j] = 0;
    }

    for (int tile = 0; tile < 36; tile++) {
        int cb = colbase + tile * 128;
        __syncthreads();
        // stage B tile: 128 cols x 64 K bf16, row pitch BPITCH
        for (int q = tid; q < 1024; q += 256) {
            int n = q >> 3, c8 = q & 7;
            *(float4*)(Bs + n * BPITCH + c8 * 8) =
                *(const float4*)(g_mbf + (cb + n) * 64 + c8 * 8);
        }
        __syncthreads();

        #pragma unroll 2
        for (int nc = 0; nc < 16; nc++) {
            int n0 = nc * 8;
            float c0 = 0.0f, c1 = 0.0f, c2 = 0.0f, c3 = 0.0f;
            const unsigned short* brow = Bs + (n0 + (lane >> 2)) * BPITCH + lg * 2;
            #pragma unroll
            for (int ks = 0; ks < 4; ks++) {
                unsigned b0 = *(const unsigned*)(brow + ks * 16);
                unsigned b1 = *(const unsigned*)(brow + ks * 16 + 8);
                asm volatile(
                    "mma.sync.aligned.m16n8k16.row.col.f32.bf16.bf16.f32 "
                    "{%0,%1,%2,%3}, {%4,%5,%6,%7}, {%8,%9}, {%0,%1,%2,%3};"
                    : "+f"(c0), "+f"(c1), "+f"(c2), "+f"(c3)
                    : "r"(a[ks][0]), "r"(a[ks][1]), "r"(a[ks][2]), "r"(a[ks][3]),
                      "r"(b0), "r"(b1));
            }
            int col = cb + n0 + lg * 2;
            top8_update(v0, id0, c0, col);
            top8_update(v0, id0, c1, col + 1);
            top8_update(v1, id1, c2, col);
            top8_update(v1, id1, c3, col + 1);
        }
    }

    int base0 = r0 * NCAND + split * 32 + lg * 8;
    int base1 = r1 * NCAND + split * 32 + lg * 8;
    #pragma unroll
    for (int j = 0; j < 8; j++) {
        g_cval[base0 + j] = v0[j]; g_cidx[base0 + j] = id0[j];
        g_cval[base1 + j] = v1[j]; g_cidx[base1 + j] = id1[j];
    }
}

// ---------------- K4: exact fp32 rescore of 64 candidates/row -> ordered top-5 -----
// block 256 = 4 rows x 64 threads (thread t scores candidate t of its row).
__global__ __launch_bounds__(256) void k_rescore() {
    __shared__ float hs[4][64];
    __shared__ float sv[4][64];
    __shared__ int   si[4][64];
    int tid = threadIdx.x;
    int g = tid >> 6, t = tid & 63;
    int row = blockIdx.x * 4 + g;
    hs[g][t] = g_hfeat[row * 64 + t];
    __syncthreads();
    int ci = g_cidx[row * NCAND + t];
    const float4* m4 = (const float4*)(g_mfeat + ci * 64);
    float dot = 0.0f;
    #pragma unroll
    for (int q = 0; q < 16; q++) {
        float4 mv = m4[q];
        dot = fmaf(mv.x, hs[g][4 * q + 0], dot);
        dot = fmaf(mv.y, hs[g][4 * q + 1], dot);
        dot = fmaf(mv.z, hs[g][4 * q + 2], dot);
        dot = fmaf(mv.w, hs[g][4 * q + 3], dot);
    }
    sv[g][t] = dot;
    si[g][t] = ci;
    __syncthreads();
    if (t == 0) {
        // top-5 with lax.top_k ordering: value desc, index asc on ties
        float bv[5]; int bi[5];
        #pragma unroll
        for (int j = 0; j < 5; j++) { bv[j] = -INFINITY; bi[j] = 0x7fffffff; }
        for (int c = 0; c < 64; c++) {
            float vv = sv[g][c]; int ii = si[g][c];
            if (vv > bv[4] || (vv == bv[4] && ii < bi[4])) {
                bv[4] = vv; bi[4] = ii;
                #pragma unroll
                for (int s = 4; s > 0; s--) {
                    if (bv[s] > bv[s - 1] || (bv[s] == bv[s - 1] && bi[s] < bi[s - 1])) {
                        float tv = bv[s - 1]; bv[s - 1] = bv[s]; bv[s] = tv;
                        int   ti = bi[s - 1]; bi[s - 1] = bi[s]; bi[s] = ti;
                    }
                }
            }
        }
        #pragma unroll
        for (int j = 0; j < 5; j++) g_topk[row * KNN + j] = bi[j];
    }
}

// ---------------- K5: GAT fc  z = [hfeat|mfeat] @ Wg,  el/er per node --------------
__global__ __launch_bounds__(256) void k_gatz(const float* __restrict__ Wg,
                                              const float* __restrict__ alv,
                                              const float* __restrict__ arv) {
    __shared__ float xs[64 * 65];
    __shared__ float ws[64 * 64];
    __shared__ float als[64], ars[64];
    __shared__ float sel[64], ser[64];
    int tid = threadIdx.x, tx = tid & 15, ty = tid >> 4;
    int pbase = blockIdx.x * 64;
    if (tid < 64) { als[tid] = alv[tid]; ars[tid] = arv[tid]; sel[tid] = 0.0f; ser[tid] = 0.0f; }

    float acc[4][4];
    #pragma unroll
    for (int j = 0; j < 4; j++)
        #pragma unroll
        for (int i = 0; i < 4; i++) acc[j][i] = 0.0f;

    for (int half = 0; half < 2; half++) {
        const float* X = half ? g_mfeat : g_hfeat;
        __syncthreads();
        for (int t = tid; t < 1024; t += 256) {
            int p = t >> 4, cc = t & 15;
            float4 v = *(const float4*)(X + (pbase + p) * 64 + cc * 4);
            xs[(4 * cc + 0) * 65 + p] = v.x;
            xs[(4 * cc + 1) * 65 + p] = v.y;
            xs[(4 * cc + 2) * 65 + p] = v.z;
            xs[(4 * cc + 3) * 65 + p] = v.w;
        }
        for (int t = tid; t < 1024; t += 256)
            ((float4*)ws)[t] = ((const float4*)(Wg + half * 64 * 64))[t];
        __syncthreads();
        for (int c = 0; c < 64; c++) {
            float xv[4];
            #pragma unroll
            for (int i = 0; i < 4; i++) xv[i] = xs[c * 65 + tx + 16 * i];
            float4 w4 = *(const float4*)(ws + c * 64 + ty * 4);
            float wv[4] = {w4.x, w4.y, w4.z, w4.w};
            #pragma unroll
            for (int j = 0; j < 4; j++)
                #pragma unroll
                for (int i = 0; i < 4; i++) acc[j][i] = fmaf(wv[j], xv[i], acc[j][i]);
        }
    }

    float a_l[4], a_r[4];
    #pragma unroll
    for (int j = 0; j < 4; j++) { a_l[j] = als[ty * 4 + j]; a_r[j] = ars[ty * 4 + j]; }
    #pragma unroll
    for (int i = 0; i < 4; i++) {
        int p = pbase + tx + 16 * i;
        float4 z4 = make_float4(acc[0][i], acc[1][i], acc[2][i], acc[3][i]);
        *(float4*)(g_z + p * 64 + ty * 4) = z4;
        float e_l = 0.0f, e_r = 0.0f;
        #pragma unroll
        for (int j = 0; j < 4; j++) {
            e_l = fmaf(acc[j][i], a_l[j], e_l);
            e_r = fmaf(acc[j][i], a_r[j], e_r);
        }
        atomicAdd(&sel[tx + 16 * i], e_l);
        atomicAdd(&ser[tx + 16 * i], e_r);
    }
    __syncthreads();
    if (tid < 64) { g_el[pbase + tid] = sel[tid]; g_er[pbase + tid] = ser[tid]; }
}

// ---------------- K6: clear reduction buffers ----------------
__global__ void k_zero() {
    int t = blockIdx.x * blockDim.x + threadIdx.x;
    if (t < NPIX) g_den[t] = 0.0f;
    if (t < NPIX * CCH) g_agg[t] = 0.0f;
}

// edge helpers: faithful to reference's (mismatched) pairing:
// e < E5:  src = e % NPIX, dst = topk_flat[e];  else self loop.
__device__ __forceinline__ void edge_sd(int e, int& src, int& dst) {
    if (e < E5) { src = e % NPIX; dst = g_topk[e]; }
    else        { src = e - E5;   dst = src; }
}

// ---------------- K7: softmax denominator (no max shift: logits are O(4)) ---------
__global__ void k_edge_den() {
    int e = blockIdx.x * blockDim.x + threadIdx.x;
    if (e >= ETOT) return;
    int src, dst; edge_sd(e, src, dst);
    float l = g_el[src] + g_er[dst];
    l = (l >= 0.0f) ? l : 0.2f * l;
    atomicAdd(&g_den[dst], expf(l));
}

// ---------------- K8: weighted aggregation (4 threads / edge, 16 ch each) ----------
__global__ void k_edge_agg() {
    int t = blockIdx.x * blockDim.x + threadIdx.x;
    int e = t >> 2;
    if (e >= ETOT) return;
    int c0 = (t & 3) * 16;
    int src, dst; edge_sd(e, src, dst);
    float l = g_el[src] + g_er[dst];
    l = (l >= 0.0f) ? l : 0.2f * l;
    float alpha = expf(l) / g_den[dst];
    const float* zs = g_z + src * 64 + c0;
    float* ag = g_agg + dst * 64 + c0;
    #pragma unroll
    for (int c = 0; c < 16; c++) atomicAdd(ag + c, alpha * zs[c]);
}

// ---------------- K9: tiled transpose pixel-major agg -> channel-major (+bg) -------
__global__ __launch_bounds__(256) void k_transbias(const float* __restrict__ bg) {
    __shared__ float tb[64 * 65];
    __shared__ float bs[64];
    int tid = threadIdx.x;
    int nb = blockIdx.x * 64;
    if (tid < 64) bs[tid] = bg[tid];
    for (int t = tid; t < 1024; t += 256) {
        int p = t >> 4, cc = t & 15;
        float4 v = *(const float4*)(g_agg + (nb + p) * 64 + cc * 4);
        tb[(4 * cc + 0) * 65 + p] = v.x;
        tb[(4 * cc + 1) * 65 + p] = v.y;
        tb[(4 * cc + 2) * 65 + p] = v.z;
        tb[(4 * cc + 3) * 65 + p] = v.w;
    }
    __syncthreads();
    for (int k = 0; k < 16; k++) {
        int idx = tid + k * 256;
        int c = idx >> 6, nn = idx & 63;
        g_fmap[c * NPIX + nb + nn] = tb[c * 65 + nn] + bs[c];
    }
}

// ---------------- K10: 3x3 conv (SAME, zero pad) + PReLU (+ optional residual) -----
__global__ __launch_bounds__(256) void k_conv3x3(const float* __restrict__ In,
                                                 const float* __restrict__ Kw,
                                                 const float* __restrict__ bias,
                                                 const float* __restrict__ aptr,
                                                 float* __restrict__ Out,
                                                 const float* __restrict__ resid) {
    __shared__ float ws[16 * 64 * 9];   // 36864 B
    __shared__ float tile[18 * 18];
    int og = blockIdx.z * 16;
    for (int i = threadIdx.x; i < 16 * 64 * 9; i += 256) ws[i] = Kw[og * 576 + i];
    float alpha = aptr[0];
    int sub = threadIdx.x >> 6;
    int q   = threadIdx.x & 63;
    int qx  = q & 3, y = q >> 2;
    int x0 = blockIdx.x * 16, y0 = blockIdx.y * 16;
    float acc[4][4];
    #pragma unroll
    for (int j = 0; j < 4; j++) {
        float b = bias[og + sub * 4 + j];
        #pragma unroll
        for (int i = 0; i < 4; i++) acc[j][i] = b;
    }
    for (int c = 0; c < 64; c++) {
        __syncthreads();
        for (int i = threadIdx.x; i < 324; i += 256) {
            int lx = i % 18 - 1 + x0;
            int ly = i / 18 - 1 + y0;
            tile[i] = (lx >= 0 && lx < WW && ly >= 0 && ly < HH)
                        ? In[c * NPIX + ly * WW + lx] : 0.0f;
        }
        __syncthreads();
        float r[3][6];
        #pragma unroll
        for (int ky = 0; ky < 3; ky++)
            #pragma unroll
            for (int m = 0; m < 6; m++)
                r[ky][m] = tile[(y + ky) * 18 + qx * 4 + m];
        #pragma unroll
        for (int j = 0; j < 4; j++) {
            const float* w = ws + ((sub * 4 + j) * 64 + c) * 9;
            float wv[9];
            #pragma unroll
            for (int k = 0; k < 9; k++) wv[k] = w[k];
            #pragma unroll
            for (int i = 0; i < 4; i++)
                #pragma unroll
                for (int ky = 0; ky < 3; ky++)
                    #pragma unroll
                    for (int kx = 0; kx < 3; kx++)
                        acc[j][i] = fmaf(wv[ky * 3 + kx], r[ky][kx + i], acc[j][i]);
        }
    }
    int pix0 = (y0 + y) * WW + x0 + qx * 4;
    #pragma unroll
    for (int j = 0; j < 4; j++) {
        int o = og + sub * 4 + j;
        float4 v4;
        float v;
        v = acc[j][0]; v4.x = (v >= 0.0f) ? v : alpha * v;
        v = acc[j][1]; v4.y = (v >= 0.0f) ? v : alpha * v;
        v = acc[j][2]; v4.z = (v >= 0.0f) ? v : alpha * v;
        v = acc[j][3]; v4.w = (v >= 0.0f) ? v : alpha * v;
        if (resid) {
            float4 rr = *(const float4*)(resid + o * NPIX + pix0);
            v4.x += rr.x; v4.y += rr.y; v4.z += rr.z; v4.w += rr.w;
        }
        *(float4*)(Out + o * NPIX + pix0) = v4;
    }
}

// ---------------- launch ----------------
extern "C" void kernel_launch(void* const* d_in, const int* in_sizes, int n_in,
                              void* d_out, int out_size) {
    const float* msi  = (const float*)d_in[0];
    const float* hsi  = (const float*)d_in[1];
    const float* W1a  = (const float*)d_in[2];
    const float* b1a  = (const float*)d_in[3];
    const float* a1a  = (const float*)d_in[4];
    const float* W1b  = (const float*)d_in[5];
    const float* b1b  = (const float*)d_in[6];
    const float* a1b  = (const float*)d_in[7];
    const float* W2a  = (const float*)d_in[8];
    const float* b2a  = (const float*)d_in[9];
    const float* a2a  = (const float*)d_in[10];
    const float* W2b  = (const float*)d_in[11];
    const float* b2b  = (const float*)d_in[12];
    const float* a2b  = (const float*)d_in[13];
    const float* Wg   = (const float*)d_in[14];
    const float* attl = (const float*)d_in[15];
    const float* attr = (const float*)d_in[16];
    const float* bg   = (const float*)d_in[17];
    const float* Ku1  = (const float*)d_in[18];
    const float* bu1  = (const float*)d_in[19];
    const float* au1  = (const float*)d_in[20];
    const float* Ku2  = (const float*)d_in[21];
    const float* bu2  = (const float*)d_in[22];
    const float* au2  = (const float*)d_in[23];

    float *p_hsi_up, *p_hfeat, *p_mfeat, *p_fmap, *p_up1;
    unsigned short *p_hbf, *p_mbf;
    cudaGetSymbolAddress((void**)&p_hsi_up, g_hsi_up);
    cudaGetSymbolAddress((void**)&p_hfeat,  g_hfeat);
    cudaGetSymbolAddress((void**)&p_mfeat,  g_mfeat);
    cudaGetSymbolAddress((void**)&p_fmap,   g_fmap);
    cudaGetSymbolAddress((void**)&p_up1,    g_up1);
    cudaGetSymbolAddress((void**)&p_hbf,    g_hbf);
    cudaGetSymbolAddress((void**)&p_mbf,    g_mbf);

    k_bicubic<<<(CCH * NPIX + 255) / 256, 256>>>(hsi);

    k_embed<<<dim3(NPIX / 64, 2), 256>>>(p_hsi_up, msi,
                                         W1a, b1a, a1a, W1b, b1b, a1b,
                                         W2a, b2a, a2a, W2b, b2b, a2b,
                                         p_hfeat, p_mfeat, p_hbf, p_mbf);

    k_sim_hmma<<<dim3(72, 2), 256>>>();
    k_rescore<<<NPIX / 4, 256>>>();

    k_gatz<<<NPIX / 64, 256>>>(Wg, attl, attr);
    k_zero<<<(NPIX * CCH + 255) / 256, 256>>>();
    k_edge_den<<<(ETOT + 255) / 256, 256>>>();
    k_edge_agg<<<(ETOT * 4 + 255) / 256, 256>>>();

    k_transbias<<<NPIX / 64, 256>>>(bg);

    k_conv3x3<<<dim3(6, 6, 4), 256>>>(p_fmap, Ku1, bu1, au1, p_up1, nullptr);
    k_conv3x3<<<dim3(6, 6, 4), 256>>>(p_up1, Ku2, bu2, au2, (float*)d_out, p_hsi_up);
}

// round 9
// speedup vs baseline: 1.7713x; 1.0631x over previous
#include <cuda_runtime.h>
#include <cuda_bf16.h>
#include <math.h>

#define NPIX 9216
#define CCH  64
#define HH   96
#define WW   96
#define HS   24
#define KNN  5
#define E5   (NPIX * KNN)                /* 46080 */
#define ETOT (E5 + NPIX)                 /* 55296 */
#define NCAND 64                         /* candidates per row (2 splits x 4 groups x 8) */

// ---------------- scratch (static device globals; no allocation) ----------------
__device__ float    g_hsi_up[CCH * NPIX];   // channel-major [c][pix]; also the residual
__device__ float    g_hfeat[NPIX * CCH];    // pixel-major [pix][c]
__device__ float    g_mfeat[NPIX * CCH];
__device__ unsigned short g_hbf[NPIX * CCH];  // bf16 copies, pixel-major
__device__ unsigned short g_mbf[NPIX * CCH];
__device__ float    g_z    [NPIX * CCH];
__device__ float    g_el   [NPIX];
__device__ float    g_er   [NPIX];
__device__ int      g_cidx [NPIX * NCAND];
__device__ int      g_topk [NPIX * KNN];
__device__ float    g_den  [NPIX];
__device__ float    g_agg  [NPIX * CCH];    // pixel-major
__device__ float    g_fmap [CCH * NPIX];    // channel-major
__device__ float    g_up1  [CCH * NPIX];

// ---------------- helpers ----------------
__device__ __forceinline__ unsigned pack_bf16x2(float lo, float hi) {
    unsigned d;
    asm("cvt.rn.bf16x2.f32 %0, %1, %2;" : "=r"(d) : "f"(hi), "f"(lo));
    return d;
}

__device__ __forceinline__ float cubw(float d) {
    d = fabsf(d);
    const float a = -0.75f;
    if (d <= 1.0f) return ((a + 2.0f) * d - (a + 3.0f)) * d * d + 1.0f;
    if (d < 2.0f)  return ((a * d - 5.0f * a) * d + 8.0f * a) * d - 4.0f * a;
    return 0.0f;
}

// top-8 running list, all-static indexing (stays in registers)
__device__ __forceinline__ void top8_update(float (&v)[8], int (&id)[8], float val, int idx) {
    if (val <= v[7]) return;
    v[7] = val; id[7] = idx;
    #pragma unroll
    for (int s = 7; s > 0; s--) {
        if (v[s] > v[s - 1]) {
            float tv = v[s - 1]; v[s - 1] = v[s]; v[s] = tv;
            int   ti = id[s - 1]; id[s - 1] = id[s]; id[s] = ti;
        }
    }
}

// ---------------- K1: bicubic x4 upsample, smem-staged (24x24 -> 96x96) ----------
// grid (64, 4): channel x output-quarter. Input channel tile staged in smem.
__global__ __launch_bounds__(256) void k_bicubic(const float* __restrict__ in) {
    __shared__ float s[HS * HS];
    int c = blockIdx.x;
    for (int i = threadIdx.x; i < HS * HS; i += 256) s[i] = in[c * HS * HS + i];
    __syncthreads();
    int obase = blockIdx.y * (NPIX / 4);
    for (int o = obase + threadIdx.x; o < obase + NPIX / 4; o += 256) {
        int x = o % WW, y = o / WW;
        float fy = (y + 0.5f) * 0.25f - 0.5f;
        float iy = floorf(fy); float ty = fy - iy;
        float fx = (x + 0.5f) * 0.25f - 0.5f;
        float ix = floorf(fx); float tx = fx - ix;
        float wy[4], wx[4]; int sy[4], sx[4];
        #pragma unroll
        for (int k = 0; k < 4; k++) {
            wy[k] = cubw(ty - (float)(k - 1));
            wx[k] = cubw(tx - (float)(k - 1));
            sy[k] = min(max((int)iy + k - 1, 0), HS - 1);
            sx[k] = min(max((int)ix + k - 1, 0), HS - 1);
        }
        float acc = 0.0f;
        #pragma unroll
        for (int i = 0; i < 4; i++) {
            float r = 0.0f;
            #pragma unroll
            for (int j = 0; j < 4; j++) r = fmaf(wx[j], s[sy[i] * HS + sx[j]], r);
            acc = fmaf(wy[i], r, acc);
        }
        g_hsi_up[c * NPIX + o] = acc;
    }
}

// ---------------- K2: fused 2-layer 1x1-conv embed, both branches -----------------
// grid (144, 2); also emits bf16 copies of the outputs for the HMMA sim kernel.
__global__ __launch_bounds__(256) void k_embed(
    const float* __restrict__ X0, const float* __restrict__ X1,
    const float* __restrict__ Wa0, const float* __restrict__ ba0, const float* __restrict__ aa0,
    const float* __restrict__ Wb0, const float* __restrict__ bb0, const float* __restrict__ ab0,
    const float* __restrict__ Wa1, const float* __restrict__ ba1, const float* __restrict__ aa1,
    const float* __restrict__ Wb1, const float* __restrict__ bb1, const float* __restrict__ ab1,
    float* __restrict__ Y0, float* __restrict__ Y1,
    unsigned short* __restrict__ Yb0, unsigned short* __restrict__ Yb1)
{
    __shared__ float xs[64 * 64];
    __shared__ float ws[64 * 64];
    __shared__ float bsh[64];
    __shared__ float s_alpha;
    int br = blockIdx.y;
    const float* X  = br ? X1 : X0;
    const float* Wa = br ? Wa1 : Wa0;
    const float* ba = br ? ba1 : ba0;
    const float* aa = br ? aa1 : aa0;
    const float* Wb = br ? Wb1 : Wb0;
    const float* bb = br ? bb1 : bb0;
    const float* ab = br ? ab1 : ab0;
    float* Y = br ? Y1 : Y0;
    unsigned short* Yb = br ? Yb1 : Yb0;
    int tid = threadIdx.x;
    int tx = tid & 15, ty = tid >> 4;
    int pbase = blockIdx.x * 64;

    for (int t = tid; t < 1024; t += 256) {
        int c = t >> 4, p4 = t & 15;
        ((float4*)xs)[c * 16 + p4] = *(const float4*)(X + c * NPIX + pbase + p4 * 4);
    }
    for (int t = tid; t < 1024; t += 256)
        ((float4*)ws)[t] = ((const float4*)Wa)[t];
    if (tid < 64) bsh[tid] = ba[tid];
    if (tid == 0) s_alpha = aa[0];
    __syncthreads();

    float acc[4][4];
    #pragma unroll
    for (int j = 0; j < 4; j++)
        #pragma unroll
        for (int i = 0; i < 4; i++) acc[j][i] = bsh[ty * 4 + j];
    for (int c = 0; c < 64; c++) {
        float xv[4], wv[4];
        #pragma unroll
        for (int i = 0; i < 4; i++) xv[i] = xs[c * 64 + tx + 16 * i];
        #pragma unroll
        for (int j = 0; j < 4; j++) wv[j] = ws[(ty * 4 + j) * 64 + c];
        #pragma unroll
        for (int j = 0; j < 4; j++)
            #pragma unroll
            for (int i = 0; i < 4; i++) acc[j][i] = fmaf(wv[j], xv[i], acc[j][i]);
    }
    float al = s_alpha;
    __syncthreads();

    #pragma unroll
    for (int j = 0; j < 4; j++)
        #pragma unroll
        for (int i = 0; i < 4; i++) {
            float v = acc[j][i];
            v = (v >= 0.0f) ? v : al * v;
            xs[(ty * 4 + j) * 64 + tx + 16 * i] = v;
        }
    for (int t = tid; t < 1024; t += 256)
        ((float4*)ws)[t] = ((const float4*)Wb)[t];
    if (tid < 64) bsh[tid] = bb[tid];
    if (tid == 0) s_alpha = ab[0];
    __syncthreads();

    #pragma unroll
    for (int j = 0; j < 4; j++)
        #pragma unroll
        for (int i = 0; i < 4; i++) acc[j][i] = bsh[ty * 4 + j];
    for (int c = 0; c < 64; c++) {
        float xv[4], wv[4];
        #pragma unroll
        for (int i = 0; i < 4; i++) xv[i] = xs[c * 64 + tx + 16 * i];
        #pragma unroll
        for (int j = 0; j < 4; j++) wv[j] = ws[(ty * 4 + j) * 64 + c];
        #pragma unroll
        for (int j = 0; j < 4; j++)
            #pragma unroll
            for (int i = 0; i < 4; i++) acc[j][i] = fmaf(wv[j], xv[i], acc[j][i]);
    }
    float al2 = s_alpha;
    #pragma unroll
    for (int i = 0; i < 4; i++) {
        int pix = pbase + tx + 16 * i;
        float4 o4;
        float v;
        v = acc[0][i]; o4.x = (v >= 0.0f) ? v : al2 * v;
        v = acc[1][i]; o4.y = (v >= 0.0f) ? v : al2 * v;
        v = acc[2][i]; o4.z = (v >= 0.0f) ? v : al2 * v;
        v = acc[3][i]; o4.w = (v >= 0.0f) ? v : al2 * v;
        *(float4*)(Y + pix * 64 + ty * 4) = o4;
        uint2 b2;
        b2.x = pack_bf16x2(o4.x, o4.y);
        b2.y = pack_bf16x2(o4.z, o4.w);
        *(uint2*)(Yb + pix * 64 + ty * 4) = b2;
    }
}

// ---------------- K3: bf16 HMMA sim GEMM + fused per-thread top-8 candidates -------
#define BPITCH 72
__global__ __launch_bounds__(256) void k_sim_hmma() {
    __shared__ __align__(16) unsigned short Bs[128 * BPITCH];
    int tid = threadIdx.x;
    int w = tid >> 5, lane = tid & 31;
    int rowbase = blockIdx.x * 128;
    int split = blockIdx.y;
    int colbase = split * 4608;

    int r0 = rowbase + w * 16 + (lane >> 2);
    int r1 = r0 + 8;
    int lg = lane & 3;

    unsigned a[4][4];
    #pragma unroll
    for (int ks = 0; ks < 4; ks++) {
        int k0 = ks * 16 + lg * 2;
        a[ks][0] = *(const unsigned*)(g_hbf + r0 * 64 + k0);
        a[ks][1] = *(const unsigned*)(g_hbf + r1 * 64 + k0);
        a[ks][2] = *(const unsigned*)(g_hbf + r0 * 64 + k0 + 8);
        a[ks][3] = *(const unsigned*)(g_hbf + r1 * 64 + k0 + 8);
    }

    float v0[8], v1[8]; int id0[8], id1[8];
    #pragma unroll
    for (int j = 0; j < 8; j++) {
        v0[j] = -INFINITY; v1[j] = -INFINITY; id0[j] = 0; id1[j] = 0;
    }

    for (int tile = 0; tile < 36; tile++) {
        int cb = colbase + tile * 128;
        __syncthreads();
        for (int q = tid; q < 1024; q += 256) {
            int n = q >> 3, c8 = q & 7;
            *(float4*)(Bs + n * BPITCH + c8 * 8) =
                *(const float4*)(g_mbf + (cb + n) * 64 + c8 * 8);
        }
        __syncthreads();

        #pragma unroll 2
        for (int nc = 0; nc < 16; nc++) {
            int n0 = nc * 8;
            float c0 = 0.0f, c1 = 0.0f, c2 = 0.0f, c3 = 0.0f;
            const unsigned short* brow = Bs + (n0 + (lane >> 2)) * BPITCH + lg * 2;
            #pragma unroll
            for (int ks = 0; ks < 4; ks++) {
                unsigned b0 = *(const unsigned*)(brow + ks * 16);
                unsigned b1 = *(const unsigned*)(brow + ks * 16 + 8);
                asm volatile(
                    "mma.sync.aligned.m16n8k16.row.col.f32.bf16.bf16.f32 "
                    "{%0,%1,%2,%3}, {%4,%5,%6,%7}, {%8,%9}, {%0,%1,%2,%3};"
                    : "+f"(c0), "+f"(c1), "+f"(c2), "+f"(c3)
                    : "r"(a[ks][0]), "r"(a[ks][1]), "r"(a[ks][2]), "r"(a[ks][3]),
                      "r"(b0), "r"(b1));
            }
            int col = cb + n0 + lg * 2;
            if (fmaxf(c0, c1) > v0[7]) {
                top8_update(v0, id0, c0, col);
                top8_update(v0, id0, c1, col + 1);
            }
            if (fmaxf(c2, c3) > v1[7]) {
                top8_update(v1, id1, c2, col);
                top8_update(v1, id1, c3, col + 1);
            }
        }
    }

    int base0 = r0 * NCAND + split * 32 + lg * 8;
    int base1 = r1 * NCAND + split * 32 + lg * 8;
    #pragma unroll
    for (int j = 0; j < 8; j++) {
        g_cidx[base0 + j] = id0[j];
        g_cidx[base1 + j] = id1[j];
    }
}

// ---------------- K4: exact fp32 rescore, warp per row ----------------------------
// block 256 = 8 warps = 8 rows. Lane scores candidates (lane) and (lane+32);
// 5 rounds of shuffle-argmax with (value desc, index asc) tie-break.
__global__ __launch_bounds__(256) void k_rescore() {
    __shared__ float hs[8][64];
    int tid = threadIdx.x;
    int w = tid >> 5, lane = tid & 31;
    int rb = blockIdx.x * 8;
    for (int i = tid; i < 512; i += 256)
        hs[i >> 6][i & 63] = g_hfeat[(rb + (i >> 6)) * 64 + (i & 63)];
    __syncthreads();
    int row = rb + w;
    float v[2]; int ix[2];
    #pragma unroll
    for (int j = 0; j < 2; j++) {
        int ci = g_cidx[row * NCAND + lane + j * 32];
        ix[j] = ci;
        const float4* m4 = (const float4*)(g_mfeat + ci * 64);
        float dot = 0.0f;
        #pragma unroll
        for (int q = 0; q < 16; q++) {
            float4 mv = m4[q];
            dot = fmaf(mv.x, hs[w][4 * q + 0], dot);
            dot = fmaf(mv.y, hs[w][4 * q + 1], dot);
            dot = fmaf(mv.z, hs[w][4 * q + 2], dot);
            dot = fmaf(mv.w, hs[w][4 * q + 3], dot);
        }
        v[j] = dot;
    }
    #pragma unroll
    for (int sel = 0; sel < KNN; sel++) {
        bool first = (v[0] > v[1]) || (v[0] == v[1] && ix[0] < ix[1]);
        float bv = first ? v[0] : v[1];
        int   bi = first ? ix[0] : ix[1];
        #pragma unroll
        for (int off = 16; off; off >>= 1) {
            float ov = __shfl_xor_sync(0xffffffffu, bv, off);
            int   oi = __shfl_xor_sync(0xffffffffu, bi, off);
            if (ov > bv || (ov == bv && oi < bi)) { bv = ov; bi = oi; }
        }
        if (lane == 0) g_topk[row * KNN + sel] = bi;
        if (ix[0] == bi) v[0] = -INFINITY;
        if (ix[1] == bi) v[1] = -INFINITY;
    }
}

// ---------------- K5: GAT fc  z = [hfeat|mfeat] @ Wg,  el/er per node --------------
// also zeroes g_den for its 64 pixels (replaces k_zero).
__global__ __launch_bounds__(256) void k_gatz(const float* __restrict__ Wg,
                                              const float* __restrict__ alv,
                                              const float* __restrict__ arv) {
    __shared__ float xs[64 * 65];
    __shared__ float ws[64 * 64];
    __shared__ float als[64], ars[64];
    __shared__ float sel[64], ser[64];
    int tid = threadIdx.x, tx = tid & 15, ty = tid >> 4;
    int pbase = blockIdx.x * 64;
    if (tid < 64) { als[tid] = alv[tid]; ars[tid] = arv[tid]; sel[tid] = 0.0f; ser[tid] = 0.0f; }

    float acc[4][4];
    #pragma unroll
    for (int j = 0; j < 4; j++)
        #pragma unroll
        for (int i = 0; i < 4; i++) acc[j][i] = 0.0f;

    for (int half = 0; half < 2; half++) {
        const float* X = half ? g_mfeat : g_hfeat;
        __syncthreads();
        for (int t = tid; t < 1024; t += 256) {
            int p = t >> 4, cc = t & 15;
            float4 v = *(const float4*)(X + (pbase + p) * 64 + cc * 4);
            xs[(4 * cc + 0) * 65 + p] = v.x;
            xs[(4 * cc + 1) * 65 + p] = v.y;
            xs[(4 * cc + 2) * 65 + p] = v.z;
            xs[(4 * cc + 3) * 65 + p] = v.w;
        }
        for (int t = tid; t < 1024; t += 256)
            ((float4*)ws)[t] = ((const float4*)(Wg + half * 64 * 64))[t];
        __syncthreads();
        for (int c = 0; c < 64; c++) {
            float xv[4];
            #pragma unroll
            for (int i = 0; i < 4; i++) xv[i] = xs[c * 65 + tx + 16 * i];
            float4 w4 = *(const float4*)(ws + c * 64 + ty * 4);
            float wv[4] = {w4.x, w4.y, w4.z, w4.w};
            #pragma unroll
            for (int j = 0; j < 4; j++)
                #pragma unroll
                for (int i = 0; i < 4; i++) acc[j][i] = fmaf(wv[j], xv[i], acc[j][i]);
        }
    }

    float a_l[4], a_r[4];
    #pragma unroll
    for (int j = 0; j < 4; j++) { a_l[j] = als[ty * 4 + j]; a_r[j] = ars[ty * 4 + j]; }
    #pragma unroll
    for (int i = 0; i < 4; i++) {
        int p = pbase + tx + 16 * i;
        float4 z4 = make_float4(acc[0][i], acc[1][i], acc[2][i], acc[3][i]);
        *(float4*)(g_z + p * 64 + ty * 4) = z4;
        float e_l = 0.0f, e_r = 0.0f;
        #pragma unroll
        for (int j = 0; j < 4; j++) {
            e_l = fmaf(acc[j][i], a_l[j], e_l);
            e_r = fmaf(acc[j][i], a_r[j], e_r);
        }
        atomicAdd(&sel[tx + 16 * i], e_l);
        atomicAdd(&ser[tx + 16 * i], e_r);
    }
    __syncthreads();
    if (tid < 64) {
        g_el[pbase + tid] = sel[tid];
        g_er[pbase + tid] = ser[tid];
        g_den[pbase + tid] = 0.0f;
    }
}

// ---------------- K6: softmax denominator over ALL edges (k-NN + self loops) -------
__global__ void k_edge_den() {
    int e = blockIdx.x * blockDim.x + threadIdx.x;
    if (e >= ETOT) return;
    int src, dst;
    if (e < E5) { src = e % NPIX; dst = g_topk[e]; }
    else        { src = e - E5;   dst = src; }
    float l = g_el[src] + g_er[dst];
    l = (l >= 0.0f) ? l : 0.2f * l;
    atomicAdd(&g_den[dst], expf(l));
}

// ---------------- K7: self-loop contribution initializes g_agg (plain stores) -----
__global__ void k_selfagg() {
    int t = blockIdx.x * blockDim.x + threadIdx.x;   // n*16 + c4
    if (t >= NPIX * 16) return;
    int n = t >> 4, c4 = t & 15;
    float l = g_el[n] + g_er[n];
    l = (l >= 0.0f) ? l : 0.2f * l;
    float alpha = expf(l) / g_den[n];
    float4 zv = *(const float4*)(g_z + n * 64 + c4 * 4);
    float4 o;
    o.x = alpha * zv.x; o.y = alpha * zv.y; o.z = alpha * zv.z; o.w = alpha * zv.w;
    *(float4*)(g_agg + n * 64 + c4 * 4) = o;
}

// ---------------- K8: k-NN edge aggregation (4 threads / edge, 16 ch each) ---------
__global__ void k_edge_agg() {
    int t = blockIdx.x * blockDim.x + threadIdx.x;
    int e = t >> 2;
    if (e >= E5) return;
    int c0 = (t & 3) * 16;
    int src = e % NPIX;
    int dst = g_topk[e];
    float l = g_el[src] + g_er[dst];
    l = (l >= 0.0f) ? l : 0.2f * l;
    float alpha = expf(l) / g_den[dst];
    const float* zs = g_z + src * 64 + c0;
    float* ag = g_agg + dst * 64 + c0;
    #pragma unroll
    for (int c = 0; c < 16; c++) atomicAdd(ag + c, alpha * zs[c]);
}

// ---------------- K9: tiled transpose pixel-major agg -> channel-major (+bg) -------
__global__ __launch_bounds__(256) void k_transbias(const float* __restrict__ bg) {
    __shared__ float tb[64 * 65];
    __shared__ float bs[64];
    int tid = threadIdx.x;
    int nb = blockIdx.x * 64;
    if (tid < 64) bs[tid] = bg[tid];
    for (int t = tid; t < 1024; t += 256) {
        int p = t >> 4, cc = t & 15;
        float4 v = *(const float4*)(g_agg + (nb + p) * 64 + cc * 4);
        tb[(4 * cc + 0) * 65 + p] = v.x;
        tb[(4 * cc + 1) * 65 + p] = v.y;
        tb[(4 * cc + 2) * 65 + p] = v.z;
        tb[(4 * cc + 3) * 65 + p] = v.w;
    }
    __syncthreads();
    for (int k = 0; k < 16; k++) {
        int idx = tid + k * 256;
        int c = idx >> 6, nn = idx & 63;
        g_fmap[c * NPIX + nb + nn] = tb[c * 65 + nn] + bs[c];
    }
}

// ---------------- K10: 3x3 conv, 4 channels staged per barrier ---------------------
__global__ __launch_bounds__(256) void k_conv3x3(const float* __restrict__ In,
                                                 const float* __restrict__ Kw,
                                                 const float* __restrict__ bias,
                                                 const float* __restrict__ aptr,
                                                 float* __restrict__ Out,
                                                 const float* __restrict__ resid) {
    __shared__ float ws[16 * 64 * 9];   // 36864 B
    __shared__ float tile[4][324];
    int og = blockIdx.z * 16;
    for (int i = threadIdx.x; i < 16 * 64 * 9; i += 256) ws[i] = Kw[og * 576 + i];
    float alpha = aptr[0];
    int sub = threadIdx.x >> 6;
    int q   = threadIdx.x & 63;
    int qx  = q & 3, y = q >> 2;
    int x0 = blockIdx.x * 16, y0 = blockIdx.y * 16;
    float acc[4][4];
    #pragma unroll
    for (int j = 0; j < 4; j++) {
        float b = bias[og + sub * 4 + j];
        #pragma unroll
        for (int i = 0; i < 4; i++) acc[j][i] = b;
    }
    for (int cs = 0; cs < 64; cs += 4) {
        __syncthreads();
        for (int i = threadIdx.x; i < 1296; i += 256) {
            int cc = i / 324, p = i - cc * 324;
            int lx = p % 18 - 1 + x0;
            int ly = p / 18 - 1 + y0;
            tile[cc][p] = (lx >= 0 && lx < WW && ly >= 0 && ly < HH)
                            ? In[(cs + cc) * NPIX + ly * WW + lx] : 0.0f;
        }
        __syncthreads();
        #pragma unroll
        for (int cc = 0; cc < 4; cc++) {
            float r[3][6];
            #pragma unroll
            for (int ky = 0; ky < 3; ky++)
                #pragma unroll
                for (int m = 0; m < 6; m++)
                    r[ky][m] = tile[cc][(y + ky) * 18 + qx * 4 + m];
            #pragma unroll
            for (int j = 0; j < 4; j++) {
                const float* w = ws + ((sub * 4 + j) * 64 + cs + cc) * 9;
                float wv[9];
                #pragma unroll
                for (int k = 0; k < 9; k++) wv[k] = w[k];
                #pragma unroll
                for (int i = 0; i < 4; i++)
                    #pragma unroll
                    for (int ky = 0; ky < 3; ky++)
                        #pragma unroll
                        for (int kx = 0; kx < 3; kx++)
                            acc[j][i] = fmaf(wv[ky * 3 + kx], r[ky][kx + i], acc[j][i]);
            }
        }
    }
    int pix0 = (y0 + y) * WW + x0 + qx * 4;
    #pragma unroll
    for (int j = 0; j < 4; j++) {
        int o = og + sub * 4 + j;
        float4 v4;
        float v;
        v = acc[j][0]; v4.x = (v >= 0.0f) ? v : alpha * v;
        v = acc[j][1]; v4.y = (v >= 0.0f) ? v : alpha * v;
        v = acc[j][2]; v4.z = (v >= 0.0f) ? v : alpha * v;
        v = acc[j][3]; v4.w = (v >= 0.0f) ? v : alpha * v;
        if (resid) {
            float4 rr = *(const float4*)(resid + o * NPIX + pix0);
            v4.x += rr.x; v4.y += rr.y; v4.z += rr.z; v4.w += rr.w;
        }
        *(float4*)(Out + o * NPIX + pix0) = v4;
    }
}

// ---------------- launch ----------------
extern "C" void kernel_launch(void* const* d_in, const int* in_sizes, int n_in,
                              void* d_out, int out_size) {
    const float* msi  = (const float*)d_in[0];
    const float* hsi  = (const float*)d_in[1];
    const float* W1a  = (const float*)d_in[2];
    const float* b1a  = (const float*)d_in[3];
    const float* a1a  = (const float*)d_in[4];
    const float* W1b  = (const float*)d_in[5];
    const float* b1b  = (const float*)d_in[6];
    const float* a1b  = (const float*)d_in[7];
    const float* W2a  = (const float*)d_in[8];
    const float* b2a  = (const float*)d_in[9];
    const float* a2a  = (const float*)d_in[10];
    const float* W2b  = (const float*)d_in[11];
    const float* b2b  = (const float*)d_in[12];
    const float* a2b  = (const float*)d_in[13];
    const float* Wg   = (const float*)d_in[14];
    const float* attl = (const float*)d_in[15];
    const float* attr = (const float*)d_in[16];
    const float* bg   = (const float*)d_in[17];
    const float* Ku1  = (const float*)d_in[18];
    const float* bu1  = (const float*)d_in[19];
    const float* au1  = (const float*)d_in[20];
    const float* Ku2  = (const float*)d_in[21];
    const float* bu2  = (const float*)d_in[22];
    const float* au2  = (const float*)d_in[23];

    float *p_hsi_up, *p_hfeat, *p_mfeat, *p_fmap, *p_up1;
    unsigned short *p_hbf, *p_mbf;
    cudaGetSymbolAddress((void**)&p_hsi_up, g_hsi_up);
    cudaGetSymbolAddress((void**)&p_hfeat,  g_hfeat);
    cudaGetSymbolAddress((void**)&p_mfeat,  g_mfeat);
    cudaGetSymbolAddress((void**)&p_fmap,   g_fmap);
    cudaGetSymbolAddress((void**)&p_up1,    g_up1);
    cudaGetSymbolAddress((void**)&p_hbf,    g_hbf);
    cudaGetSymbolAddress((void**)&p_mbf,    g_mbf);

    k_bicubic<<<dim3(CCH, 4), 256>>>(hsi);

    k_embed<<<dim3(NPIX / 64, 2), 256>>>(p_hsi_up, msi,
                                         W1a, b1a, a1a, W1b, b1b, a1b,
                                         W2a, b2a, a2a, W2b, b2b, a2b,
                                         p_hfeat, p_mfeat, p_hbf, p_mbf);

    k_sim_hmma<<<dim3(72, 2), 256>>>();
    k_rescore<<<NPIX / 8, 256>>>();

    k_gatz<<<NPIX / 64, 256>>>(Wg, attl, attr);
    k_edge_den<<<(ETOT + 255) / 256, 256>>>();
    k_selfagg<<<(NPIX * 16 + 255) / 256, 256>>>();
    k_edge_agg<<<(E5 * 4 + 255) / 256, 256>>>();

    k_transbias<<<NPIX / 64, 256>>>(bg);

    k_conv3x3<<<dim3(6, 6, 4), 256>>>(p_fmap, Ku1, bu1, au1, p_up1, nullptr);
    k_conv3x3<<<dim3(6, 6, 4), 256>>>(p_up1, Ku2, bu2, au2, (float*)d_out, p_hsi_up);
}

// round 10
// speedup vs baseline: 1.7743x; 1.0017x over previous
#include <cuda_runtime.h>
#include <cuda_bf16.h>
#include <math.h>

#define NPIX 9216
#define CCH  64
#define HH   96
#define WW   96
#define HS   24
#define KNN  5
#define E5   (NPIX * KNN)                /* 46080 */
#define ETOT (E5 + NPIX)                 /* 55296 */
#define NCAND 64                         /* candidates per row (2 splits x 4 groups x 8) */

// ---------------- scratch (static device globals; no allocation) ----------------
__device__ float    g_hsi_up[CCH * NPIX];   // channel-major [c][pix]; also the residual
__device__ float    g_hfeat[NPIX * CCH];    // pixel-major [pix][c]
__device__ float    g_mfeat[NPIX * CCH];
__device__ unsigned short g_hbf[NPIX * CCH];  // bf16 copies, pixel-major
__device__ unsigned short g_mbf[NPIX * CCH];
__device__ float    g_z    [NPIX * CCH];
__device__ float    g_el   [NPIX];
__device__ float    g_er   [NPIX];
__device__ int      g_cidx [NPIX * NCAND];
__device__ int      g_topk [NPIX * KNN];
__device__ float    g_den  [NPIX];
__device__ float    g_agg  [NPIX * CCH];    // pixel-major
__device__ float    g_fmap [CCH * NPIX];    // channel-major
__device__ float    g_up1  [CCH * NPIX];

// ---------------- helpers ----------------
__device__ __forceinline__ unsigned pack_bf16x2(float lo, float hi) {
    unsigned d;
    asm("cvt.rn.bf16x2.f32 %0, %1, %2;" : "=r"(d) : "f"(hi), "f"(lo));
    return d;
}

__device__ __forceinline__ float cubw(float d) {
    d = fabsf(d);
    const float a = -0.75f;
    if (d <= 1.0f) return ((a + 2.0f) * d - (a + 3.0f)) * d * d + 1.0f;
    if (d < 2.0f)  return ((a * d - 5.0f * a) * d + 8.0f * a) * d - 4.0f * a;
    return 0.0f;
}

// top-8 running list, all-static indexing (stays in registers)
__device__ __forceinline__ void top8_update(float (&v)[8], int (&id)[8], float val, int idx) {
    if (val <= v[7]) return;
    v[7] = val; id[7] = idx;
    #pragma unroll
    for (int s = 7; s > 0; s--) {
        if (v[s] > v[s - 1]) {
            float tv = v[s - 1]; v[s - 1] = v[s]; v[s] = tv;
            int   ti = id[s - 1]; id[s - 1] = id[s]; id[s] = ti;
        }
    }
}

// ---------------- K1: bicubic x4 upsample, smem-staged (24x24 -> 96x96) ----------
// grid (64, 4): channel x output-quarter. Input channel tile staged in smem.
__global__ __launch_bounds__(256) void k_bicubic(const float* __restrict__ in) {
    __shared__ float s[HS * HS];
    int c = blockIdx.x;
    for (int i = threadIdx.x; i < HS * HS; i += 256) s[i] = in[c * HS * HS + i];
    __syncthreads();
    int obase = blockIdx.y * (NPIX / 4);
    for (int o = obase + threadIdx.x; o < obase + NPIX / 4; o += 256) {
        int x = o % WW, y = o / WW;
        float fy = (y + 0.5f) * 0.25f - 0.5f;
        float iy = floorf(fy); float ty = fy - iy;
        float fx = (x + 0.5f) * 0.25f - 0.5f;
        float ix = floorf(fx); float tx = fx - ix;
        float wy[4], wx[4]; int sy[4], sx[4];
        #pragma unroll
        for (int k = 0; k < 4; k++) {
            wy[k] = cubw(ty - (float)(k - 1));
            wx[k] = cubw(tx - (float)(k - 1));
            sy[k] = min(max((int)iy + k - 1, 0), HS - 1);
            sx[k] = min(max((int)ix + k - 1, 0), HS - 1);
        }
        float acc = 0.0f;
        #pragma unroll
        for (int i = 0; i < 4; i++) {
            float r = 0.0f;
            #pragma unroll
            for (int j = 0; j < 4; j++) r = fmaf(wx[j], s[sy[i] * HS + sx[j]], r);
            acc = fmaf(wy[i], r, acc);
        }
        g_hsi_up[c * NPIX + o] = acc;
    }
}

// ---------------- K2: fused 2-layer 1x1-conv embed, both branches -----------------
// grid (144, 2); also emits bf16 copies of the outputs for the HMMA sim kernel.
__global__ __launch_bounds__(256) void k_embed(
    const float* __restrict__ X0, const float* __restrict__ X1,
    const float* __restrict__ Wa0, const float* __restrict__ ba0, const float* __restrict__ aa0,
    const float* __restrict__ Wb0, const float* __restrict__ bb0, const float* __restrict__ ab0,
    const float* __restrict__ Wa1, const float* __restrict__ ba1, const float* __restrict__ aa1,
    const float* __restrict__ Wb1, const float* __restrict__ bb1, const float* __restrict__ ab1,
    float* __restrict__ Y0, float* __restrict__ Y1,
    unsigned short* __restrict__ Yb0, unsigned short* __restrict__ Yb1)
{
    __shared__ float xs[64 * 64];
    __shared__ float ws[64 * 64];
    __shared__ float bsh[64];
    __shared__ float s_alpha;
    int br = blockIdx.y;
    const float* X  = br ? X1 : X0;
    const float* Wa = br ? Wa1 : Wa0;
    const float* ba = br ? ba1 : ba0;
    const float* aa = br ? aa1 : aa0;
    const float* Wb = br ? Wb1 : Wb0;
    const float* bb = br ? bb1 : bb0;
    const float* ab = br ? ab1 : ab0;
    float* Y = br ? Y1 : Y0;
    unsigned short* Yb = br ? Yb1 : Yb0;
    int tid = threadIdx.x;
    int tx = tid & 15, ty = tid >> 4;
    int pbase = blockIdx.x * 64;

    for (int t = tid; t < 1024; t += 256) {
        int c = t >> 4, p4 = t & 15;
        ((float4*)xs)[c * 16 + p4] = *(const float4*)(X + c * NPIX + pbase + p4 * 4);
    }
    for (int t = tid; t < 1024; t += 256)
        ((float4*)ws)[t] = ((const float4*)Wa)[t];
    if (tid < 64) bsh[tid] = ba[tid];
    if (tid == 0) s_alpha = aa[0];
    __syncthreads();

    float acc[4][4];
    #pragma unroll
    for (int j = 0; j < 4; j++)
        #pragma unroll
        for (int i = 0; i < 4; i++) acc[j][i] = bsh[ty * 4 + j];
    for (int c = 0; c < 64; c++) {
        float xv[4], wv[4];
        #pragma unroll
        for (int i = 0; i < 4; i++) xv[i] = xs[c * 64 + tx + 16 * i];
        #pragma unroll
        for (int j = 0; j < 4; j++) wv[j] = ws[(ty * 4 + j) * 64 + c];
        #pragma unroll
        for (int j = 0; j < 4; j++)
            #pragma unroll
            for (int i = 0; i < 4; i++) acc[j][i] = fmaf(wv[j], xv[i], acc[j][i]);
    }
    float al = s_alpha;
    __syncthreads();

    #pragma unroll
    for (int j = 0; j < 4; j++)
        #pragma unroll
        for (int i = 0; i < 4; i++) {
            float v = acc[j][i];
            v = (v >= 0.0f) ? v : al * v;
            xs[(ty * 4 + j) * 64 + tx + 16 * i] = v;
        }
    for (int t = tid; t < 1024; t += 256)
        ((float4*)ws)[t] = ((const float4*)Wb)[t];
    if (tid < 64) bsh[tid] = bb[tid];
    if (tid == 0) s_alpha = ab[0];
    __syncthreads();

    #pragma unroll
    for (int j = 0; j < 4; j++)
        #pragma unroll
        for (int i = 0; i < 4; i++) acc[j][i] = bsh[ty * 4 + j];
    for (int c = 0; c < 64; c++) {
        float xv[4], wv[4];
        #pragma unroll
        for (int i = 0; i < 4; i++) xv[i] = xs[c * 64 + tx + 16 * i];
        #pragma unroll
        for (int j = 0; j < 4; j++) wv[j] = ws[(ty * 4 + j) * 64 + c];
        #pragma unroll
        for (int j = 0; j < 4; j++)
            #pragma unroll
            for (int i = 0; i < 4; i++) acc[j][i] = fmaf(wv[j], xv[i], acc[j][i]);
    }
    float al2 = s_alpha;
    #pragma unroll
    for (int i = 0; i < 4; i++) {
        int pix = pbase + tx + 16 * i;
        float4 o4;
        float v;
        v = acc[0][i]; o4.x = (v >= 0.0f) ? v : al2 * v;
        v = acc[1][i]; o4.y = (v >= 0.0f) ? v : al2 * v;
        v = acc[2][i]; o4.z = (v >= 0.0f) ? v : al2 * v;
        v = acc[3][i]; o4.w = (v >= 0.0f) ? v : al2 * v;
        *(float4*)(Y + pix * 64 + ty * 4) = o4;
        uint2 b2;
        b2.x = pack_bf16x2(o4.x, o4.y);
        b2.y = pack_bf16x2(o4.z, o4.w);
        *(uint2*)(Yb + pix * 64 + ty * 4) = b2;
    }
}

// ---------------- K3: bf16 HMMA sim GEMM + fused per-thread top-8 candidates -------
#define BPITCH 72
__global__ __launch_bounds__(256) void k_sim_hmma() {
    __shared__ __align__(16) unsigned short Bs[128 * BPITCH];
    int tid = threadIdx.x;
    int w = tid >> 5, lane = tid & 31;
    int rowbase = blockIdx.x * 128;
    int split = blockIdx.y;
    int colbase = split * 4608;

    int r0 = rowbase + w * 16 + (lane >> 2);
    int r1 = r0 + 8;
    int lg = lane & 3;

    unsigned a[4][4];
    #pragma unroll
    for (int ks = 0; ks < 4; ks++) {
        int k0 = ks * 16 + lg * 2;
        a[ks][0] = *(const unsigned*)(g_hbf + r0 * 64 + k0);
        a[ks][1] = *(const unsigned*)(g_hbf + r1 * 64 + k0);
        a[ks][2] = *(const unsigned*)(g_hbf + r0 * 64 + k0 + 8);
        a[ks][3] = *(const unsigned*)(g_hbf + r1 * 64 + k0 + 8);
    }

    float v0[8], v1[8]; int id0[8], id1[8];
    #pragma unroll
    for (int j = 0; j < 8; j++) {
        v0[j] = -INFINITY; v1[j] = -INFINITY; id0[j] = 0; id1[j] = 0;
    }

    for (int tile = 0; tile < 36; tile++) {
        int cb = colbase + tile * 128;
        __syncthreads();
        for (int q = tid; q < 1024; q += 256) {
            int n = q >> 3, c8 = q & 7;
            *(float4*)(Bs + n * BPITCH + c8 * 8) =
                *(const float4*)(g_mbf + (cb + n) * 64 + c8 * 8);
        }
        __syncthreads();

        #pragma unroll 2
        for (int nc = 0; nc < 16; nc++) {
            int n0 = nc * 8;
            float c0 = 0.0f, c1 = 0.0f, c2 = 0.0f, c3 = 0.0f;
            const unsigned short* brow = Bs + (n0 + (lane >> 2)) * BPITCH + lg * 2;
            #pragma unroll
            for (int ks = 0; ks < 4; ks++) {
                unsigned b0 = *(const unsigned*)(brow + ks * 16);
                unsigned b1 = *(const unsigned*)(brow + ks * 16 + 8);
                asm volatile(
                    "mma.sync.aligned.m16n8k16.row.col.f32.bf16.bf16.f32 "
                    "{%0,%1,%2,%3}, {%4,%5,%6,%7}, {%8,%9}, {%0,%1,%2,%3};"
                    : "+f"(c0), "+f"(c1), "+f"(c2), "+f"(c3)
                    : "r"(a[ks][0]), "r"(a[ks][1]), "r"(a[ks][2]), "r"(a[ks][3]),
                      "r"(b0), "r"(b1));
            }
            int col = cb + n0 + lg * 2;
            if (fmaxf(c0, c1) > v0[7]) {
                top8_update(v0, id0, c0, col);
                top8_update(v0, id0, c1, col + 1);
            }
            if (fmaxf(c2, c3) > v1[7]) {
                top8_update(v1, id1, c2, col);
                top8_update(v1, id1, c3, col + 1);
            }
        }
    }

    int base0 = r0 * NCAND + split * 32 + lg * 8;
    int base1 = r1 * NCAND + split * 32 + lg * 8;
    #pragma unroll
    for (int j = 0; j < 8; j++) {
        g_cidx[base0 + j] = id0[j];
        g_cidx[base1 + j] = id1[j];
    }
}

// ---------------- K4: exact fp32 rescore, warp per row ----------------------------
// block 256 = 8 warps = 8 rows. Lane scores candidates (lane) and (lane+32);
// 5 rounds of shuffle-argmax with (value desc, index asc) tie-break.
__global__ __launch_bounds__(256) void k_rescore() {
    __shared__ float hs[8][64];
    int tid = threadIdx.x;
    int w = tid >> 5, lane = tid & 31;
    int rb = blockIdx.x * 8;
    for (int i = tid; i < 512; i += 256)
        hs[i >> 6][i & 63] = g_hfeat[(rb + (i >> 6)) * 64 + (i & 63)];
    __syncthreads();
    int row = rb + w;
    float v[2]; int ix[2];
    #pragma unroll
    for (int j = 0; j < 2; j++) {
        int ci = g_cidx[row * NCAND + lane + j * 32];
        ix[j] = ci;
        const float4* m4 = (const float4*)(g_mfeat + ci * 64);
        float dot = 0.0f;
        #pragma unroll
        for (int q = 0; q < 16; q++) {
            float4 mv = m4[q];
            dot = fmaf(mv.x, hs[w][4 * q + 0], dot);
            dot = fmaf(mv.y, hs[w][4 * q + 1], dot);
            dot = fmaf(mv.z, hs[w][4 * q + 2], dot);
            dot = fmaf(mv.w, hs[w][4 * q + 3], dot);
        }
        v[j] = dot;
    }
    #pragma unroll
    for (int sel = 0; sel < KNN; sel++) {
        bool first = (v[0] > v[1]) || (v[0] == v[1] && ix[0] < ix[1]);
        float bv = first ? v[0] : v[1];
        int   bi = first ? ix[0] : ix[1];
        #pragma unroll
        for (int off = 16; off; off >>= 1) {
            float ov = __shfl_xor_sync(0xffffffffu, bv, off);
            int   oi = __shfl_xor_sync(0xffffffffu, bi, off);
            if (ov > bv || (ov == bv && oi < bi)) { bv = ov; bi = oi; }
        }
        if (lane == 0) g_topk[row * KNN + sel] = bi;
        if (ix[0] == bi) v[0] = -INFINITY;
        if (ix[1] == bi) v[1] = -INFINITY;
    }
}

// ---------------- K5: GAT fc  z = [hfeat|mfeat] @ Wg,  el/er per node --------------
// also zeroes g_den for its 64 pixels (replaces k_zero).
__global__ __launch_bounds__(256) void k_gatz(const float* __restrict__ Wg,
                                              const float* __restrict__ alv,
                                              const float* __restrict__ arv) {
    __shared__ float xs[64 * 65];
    __shared__ float ws[64 * 64];
    __shared__ float als[64], ars[64];
    __shared__ float sel[64], ser[64];
    int tid = threadIdx.x, tx = tid & 15, ty = tid >> 4;
    int pbase = blockIdx.x * 64;
    if (tid < 64) { als[tid] = alv[tid]; ars[tid] = arv[tid]; sel[tid] = 0.0f; ser[tid] = 0.0f; }

    float acc[4][4];
    #pragma unroll
    for (int j = 0; j < 4; j++)
        #pragma unroll
        for (int i = 0; i < 4; i++) acc[j][i] = 0.0f;

    for (int half = 0; half < 2; half++) {
        const float* X = half ? g_mfeat : g_hfeat;
        __syncthreads();
        for (int t = tid; t < 1024; t += 256) {
            int p = t >> 4, cc = t & 15;
            float4 v = *(const float4*)(X + (pbase + p) * 64 + cc * 4);
            xs[(4 * cc + 0) * 65 + p] = v.x;
            xs[(4 * cc + 1) * 65 + p] = v.y;
            xs[(4 * cc + 2) * 65 + p] = v.z;
            xs[(4 * cc + 3) * 65 + p] = v.w;
        }
        for (int t = tid; t < 1024; t += 256)
            ((float4*)ws)[t] = ((const float4*)(Wg + half * 64 * 64))[t];
        __syncthreads();
        for (int c = 0; c < 64; c++) {
            float xv[4];
            #pragma unroll
            for (int i = 0; i < 4; i++) xv[i] = xs[c * 65 + tx + 16 * i];
            float4 w4 = *(const float4*)(ws + c * 64 + ty * 4);
            float wv[4] = {w4.x, w4.y, w4.z, w4.w};
            #pragma unroll
            for (int j = 0; j < 4; j++)
                #pragma unroll
                for (int i = 0; i < 4; i++) acc[j][i] = fmaf(wv[j], xv[i], acc[j][i]);
        }
    }

    float a_l[4], a_r[4];
    #pragma unroll
    for (int j = 0; j < 4; j++) { a_l[j] = als[ty * 4 + j]; a_r[j] = ars[ty * 4 + j]; }
    #pragma unroll
    for (int i = 0; i < 4; i++) {
        int p = pbase + tx + 16 * i;
        float4 z4 = make_float4(acc[0][i], acc[1][i], acc[2][i], acc[3][i]);
        *(float4*)(g_z + p * 64 + ty * 4) = z4;
        float e_l = 0.0f, e_r = 0.0f;
        #pragma unroll
        for (int j = 0; j < 4; j++) {
            e_l = fmaf(acc[j][i], a_l[j], e_l);
            e_r = fmaf(acc[j][i], a_r[j], e_r);
        }
        atomicAdd(&sel[tx + 16 * i], e_l);
        atomicAdd(&ser[tx + 16 * i], e_r);
    }
    __syncthreads();
    if (tid < 64) {
        g_el[pbase + tid] = sel[tid];
        g_er[pbase + tid] = ser[tid];
        g_den[pbase + tid] = 0.0f;
    }
}

// ---------------- K6: softmax denominator over ALL edges (k-NN + self loops) -------
__global__ void k_edge_den() {
    int e = blockIdx.x * blockDim.x + threadIdx.x;
    if (e >= ETOT) return;
    int src, dst;
    if (e < E5) { src = e % NPIX; dst = g_topk[e]; }
    else        { src = e - E5;   dst = src; }
    float l = g_el[src] + g_er[dst];
    l = (l >= 0.0f) ? l : 0.2f * l;
    atomicAdd(&g_den[dst], expf(l));
}

// ---------------- K7: self-loop contribution initializes g_agg (plain stores) -----
__global__ void k_selfagg() {
    int t = blockIdx.x * blockDim.x + threadIdx.x;   // n*16 + c4
    if (t >= NPIX * 16) return;
    int n = t >> 4, c4 = t & 15;
    float l = g_el[n] + g_er[n];
    l = (l >= 0.0f) ? l : 0.2f * l;
    float alpha = expf(l) / g_den[n];
    float4 zv = *(const float4*)(g_z + n * 64 + c4 * 4);
    float4 o;
    o.x = alpha * zv.x; o.y = alpha * zv.y; o.z = alpha * zv.z; o.w = alpha * zv.w;
    *(float4*)(g_agg + n * 64 + c4 * 4) = o;
}

// ---------------- K8: k-NN edge aggregation (4 threads / edge, 16 ch each) ---------
__global__ void k_edge_agg() {
    int t = blockIdx.x * blockDim.x + threadIdx.x;
    int e = t >> 2;
    if (e >= E5) return;
    int c0 = (t & 3) * 16;
    int src = e % NPIX;
    int dst = g_topk[e];
    float l = g_el[src] + g_er[dst];
    l = (l >= 0.0f) ? l : 0.2f * l;
    float alpha = expf(l) / g_den[dst];
    const float* zs = g_z + src * 64 + c0;
    float* ag = g_agg + dst * 64 + c0;
    #pragma unroll
    for (int c = 0; c < 16; c++) atomicAdd(ag + c, alpha * zs[c]);
}

// ---------------- K9: tiled transpose pixel-major agg -> channel-major (+bg) -------
__global__ __launch_bounds__(256) void k_transbias(const float* __restrict__ bg) {
    __shared__ float tb[64 * 65];
    __shared__ float bs[64];
    int tid = threadIdx.x;
    int nb = blockIdx.x * 64;
    if (tid < 64) bs[tid] = bg[tid];
    for (int t = tid; t < 1024; t += 256) {
        int p = t >> 4, cc = t & 15;
        float4 v = *(const float4*)(g_agg + (nb + p) * 64 + cc * 4);
        tb[(4 * cc + 0) * 65 + p] = v.x;
        tb[(4 * cc + 1) * 65 + p] = v.y;
        tb[(4 * cc + 2) * 65 + p] = v.z;
        tb[(4 * cc + 3) * 65 + p] = v.w;
    }
    __syncthreads();
    for (int k = 0; k < 16; k++) {
        int idx = tid + k * 256;
        int c = idx >> 6, nn = idx & 63;
        g_fmap[c * NPIX + nb + nn] = tb[c * 65 + nn] + bs[c];
    }
}

// ---------------- K10: 3x3 conv, 4 channels staged per barrier ---------------------
__global__ __launch_bounds__(256) void k_conv3x3(const float* __restrict__ In,
                                                 const float* __restrict__ Kw,
                                                 const float* __restrict__ bias,
                                                 const float* __restrict__ aptr,
                                                 float* __restrict__ Out,
                                                 const float* __restrict__ resid) {
    __shared__ float ws[16 * 64 * 9];   // 36864 B
    __shared__ float tile[4][324];
    int og = blockIdx.z * 16;
    for (int i = threadIdx.x; i < 16 * 64 * 9; i += 256) ws[i] = Kw[og * 576 + i];
    float alpha = aptr[0];
    int sub = threadIdx.x >> 6;
    int q   = threadIdx.x & 63;
    int qx  = q & 3, y = q >> 2;
    int x0 = blockIdx.x * 16, y0 = blockIdx.y * 16;
    float acc[4][4];
    #pragma unroll
    for (int j = 0; j < 4; j++) {
        float b = bias[og + sub * 4 + j];
        #pragma unroll
        for (int i = 0; i < 4; i++) acc[j][i] = b;
    }
    for (int cs = 0; cs < 64; cs += 4) {
        __syncthreads();
        for (int i = threadIdx.x; i < 1296; i += 256) {
            int cc = i / 324, p = i - cc * 324;
            int lx = p % 18 - 1 + x0;
            int ly = p / 18 - 1 + y0;
            tile[cc][p] = (lx >= 0 && lx < WW && ly >= 0 && ly < HH)
                            ? In[(cs + cc) * NPIX + ly * WW + lx] : 0.0f;
        }
        __syncthreads();
        #pragma unroll
        for (int cc = 0; cc < 4; cc++) {
            float r[3][6];
            #pragma unroll
            for (int ky = 0; ky < 3; ky++)
                #pragma unroll
                for (int m = 0; m < 6; m++)
                    r[ky][m] = tile[cc][(y + ky) * 18 + qx * 4 + m];
            #pragma unroll
            for (int j = 0; j < 4; j++) {
                const float* w = ws + ((sub * 4 + j) * 64 + cs + cc) * 9;
                float wv[9];
                #pragma unroll
                for (int k = 0; k < 9; k++) wv[k] = w[k];
                #pragma unroll
                for (int i = 0; i < 4; i++)
                    #pragma unroll
                    for (int ky = 0; ky < 3; ky++)
                        #pragma unroll
                        for (int kx = 0; kx < 3; kx++)
                            acc[j][i] = fmaf(wv[ky * 3 + kx], r[ky][kx + i], acc[j][i]);
            }
        }
    }
    int pix0 = (y0 + y) * WW + x0 + qx * 4;
    #pragma unroll
    for (int j = 0; j < 4; j++) {
        int o = og + sub * 4 + j;
        float4 v4;
        float v;
        v = acc[j][0]; v4.x = (v >= 0.0f) ? v : alpha * v;
        v = acc[j][1]; v4.y = (v >= 0.0f) ? v : alpha * v;
        v = acc[j][2]; v4.z = (v >= 0.0f) ? v : alpha * v;
        v = acc[j][3]; v4.w = (v >= 0.0f) ? v : alpha * v;
        if (resid) {
            float4 rr = *(const float4*)(resid + o * NPIX + pix0);
            v4.x += rr.x; v4.y += rr.y; v4.z += rr.z; v4.w += rr.w;
        }
        *(float4*)(Out + o * NPIX + pix0) = v4;
    }
}

// ---------------- launch ----------------
extern "C" void kernel_launch(void* const* d_in, const int* in_sizes, int n_in,
                              void* d_out, int out_size) {
    const float* msi  = (const float*)d_in[0];
    const float* hsi  = (const float*)d_in[1];
    const float* W1a  = (const float*)d_in[2];
    const float* b1a  = (const float*)d_in[3];
    const float* a1a  = (const float*)d_in[4];
    const float* W1b  = (const float*)d_in[5];
    const float* b1b  = (const float*)d_in[6];
    const float* a1b  = (const float*)d_in[7];
    const float* W2a  = (const float*)d_in[8];
    const float* b2a  = (const float*)d_in[9];
    const float* a2a  = (const float*)d_in[10];
    const float* W2b  = (const float*)d_in[11];
    const float* b2b  = (const float*)d_in[12];
    const float* a2b  = (const float*)d_in[13];
    const float* Wg   = (const float*)d_in[14];
    const float* attl = (const float*)d_in[15];
    const float* attr = (const float*)d_in[16];
    const float* bg   = (const float*)d_in[17];
    const float* Ku1  = (const float*)d_in[18];
    const float* bu1  = (const float*)d_in[19];
    const float* au1  = (const float*)d_in[20];
    const float* Ku2  = (const float*)d_in[21];
    const float* bu2  = (const float*)d_in[22];
    const float* au2  = (const float*)d_in[23];

    float *p_hsi_up, *p_hfeat, *p_mfeat, *p_fmap, *p_up1;
    unsigned short *p_hbf, *p_mbf;
    cudaGetSymbolAddress((void**)&p_hsi_up, g_hsi_up);
    cudaGetSymbolAddress((void**)&p_hfeat,  g_hfeat);
    cudaGetSymbolAddress((void**)&p_mfeat,  g_mfeat);
    cudaGetSymbolAddress((void**)&p_fmap,   g_fmap);
    cudaGetSymbolAddress((void**)&p_up1,    g_up1);
    cudaGetSymbolAddress((void**)&p_hbf,    g_hbf);
    cudaGetSymbolAddress((void**)&p_mbf,    g_mbf);

    k_bicubic<<<dim3(CCH, 4), 256>>>(hsi);

    k_embed<<<dim3(NPIX / 64, 2), 256>>>(p_hsi_up, msi,
                                         W1a, b1a, a1a, W1b, b1b, a1b,
                                         W2a, b2a, a2a, W2b, b2b, a2b,
                                         p_hfeat, p_mfeat, p_hbf, p_mbf);

    k_sim_hmma<<<dim3(72, 2), 256>>>();
    k_rescore<<<NPIX / 8, 256>>>();

    k_gatz<<<NPIX / 64, 256>>>(Wg, attl, attr);
    k_edge_den<<<(ETOT + 255) / 256, 256>>>();
    k_selfagg<<<(NPIX * 16 + 255) / 256, 256>>>();
    k_edge_agg<<<(E5 * 4 + 255) / 256, 256>>>();

    k_transbias<<<NPIX / 64, 256>>>(bg);

    k_conv3x3<<<dim3(6, 6, 4), 256>>>(p_fmap, Ku1, bu1, au1, p_up1, nullptr);
    k_conv3x3<<<dim3(6, 6, 4), 256>>>(p_up1, Ku2, bu2, au2, (float*)d_out, p_hsi_up);
}

// round 11
// speedup vs baseline: 1.8701x; 1.0540x over previous
#include <cuda_runtime.h>
#include <cuda_bf16.h>
#include <math.h>

#define NPIX 9216
#define CCH  64
#define HH   96
#define WW   96
#define HS   24
#define KNN  5
#define E5   (NPIX * KNN)                /* 46080 */
#define ETOT (E5 + NPIX)                 /* 55296 */
#define NCAND 64                         /* candidates per row (2 splits x 4 groups x 8) */

// ---------------- scratch (static device globals; no allocation) ----------------
__device__ float    g_hsi_up[CCH * NPIX];   // channel-major [c][pix]; also the residual
__device__ float    g_hfeat[NPIX * CCH];    // pixel-major [pix][c]
__device__ float    g_mfeat[NPIX * CCH];
__device__ unsigned short g_hbf[NPIX * CCH];  // bf16 copies, pixel-major
__device__ unsigned short g_mbf[NPIX * CCH];
__device__ float    g_z    [NPIX * CCH];
__device__ float    g_el   [NPIX];
__device__ float    g_er   [NPIX];
__device__ int      g_cidx [NPIX * NCAND];
__device__ int      g_topk [NPIX * KNN];
__device__ float    g_den  [NPIX];
__device__ float    g_agg  [NPIX * CCH];    // pixel-major
__device__ float    g_fmap [CCH * NPIX];    // channel-major
__device__ float    g_up1  [CCH * NPIX];

// ---------------- helpers ----------------
__device__ __forceinline__ unsigned pack_bf16x2(float lo, float hi) {
    unsigned d;
    asm("cvt.rn.bf16x2.f32 %0, %1, %2;" : "=r"(d) : "f"(hi), "f"(lo));
    return d;
}

__device__ __forceinline__ float cubw(float d) {
    d = fabsf(d);
    const float a = -0.75f;
    if (d <= 1.0f) return ((a + 2.0f) * d - (a + 3.0f)) * d * d + 1.0f;
    if (d < 2.0f)  return ((a * d - 5.0f * a) * d + 8.0f * a) * d - 4.0f * a;
    return 0.0f;
}

// top-8 running list, all-static indexing (stays in registers)
__device__ __forceinline__ void top8_update(float (&v)[8], int (&id)[8], float val, int idx) {
    if (val <= v[7]) return;
    v[7] = val; id[7] = idx;
    #pragma unroll
    for (int s = 7; s > 0; s--) {
        if (v[s] > v[s - 1]) {
            float tv = v[s - 1]; v[s - 1] = v[s]; v[s] = tv;
            int   ti = id[s - 1]; id[s - 1] = id[s]; id[s] = ti;
        }
    }
}

// ---------------- K1: bicubic x4 upsample, smem-staged (24x24 -> 96x96) ----------
__global__ __launch_bounds__(256) void k_bicubic(const float* __restrict__ in) {
    __shared__ float s[HS * HS];
    int c = blockIdx.x;
    for (int i = threadIdx.x; i < HS * HS; i += 256) s[i] = in[c * HS * HS + i];
    __syncthreads();
    int obase = blockIdx.y * (NPIX / 4);
    for (int o = obase + threadIdx.x; o < obase + NPIX / 4; o += 256) {
        int x = o % WW, y = o / WW;
        float fy = (y + 0.5f) * 0.25f - 0.5f;
        float iy = floorf(fy); float ty = fy - iy;
        float fx = (x + 0.5f) * 0.25f - 0.5f;
        float ix = floorf(fx); float tx = fx - ix;
        float wy[4], wx[4]; int sy[4], sx[4];
        #pragma unroll
        for (int k = 0; k < 4; k++) {
            wy[k] = cubw(ty - (float)(k - 1));
            wx[k] = cubw(tx - (float)(k - 1));
            sy[k] = min(max((int)iy + k - 1, 0), HS - 1);
            sx[k] = min(max((int)ix + k - 1, 0), HS - 1);
        }
        float acc = 0.0f;
        #pragma unroll
        for (int i = 0; i < 4; i++) {
            float r = 0.0f;
            #pragma unroll
            for (int j = 0; j < 4; j++) r = fmaf(wx[j], s[sy[i] * HS + sx[j]], r);
            acc = fmaf(wy[i], r, acc);
        }
        g_hsi_up[c * NPIX + o] = acc;
    }
}

// ---------------- K2: fused 2-layer 1x1-conv embed, both branches -----------------
__global__ __launch_bounds__(256) void k_embed(
    const float* __restrict__ X0, const float* __restrict__ X1,
    const float* __restrict__ Wa0, const float* __restrict__ ba0, const float* __restrict__ aa0,
    const float* __restrict__ Wb0, const float* __restrict__ bb0, const float* __restrict__ ab0,
    const float* __restrict__ Wa1, const float* __restrict__ ba1, const float* __restrict__ aa1,
    const float* __restrict__ Wb1, const float* __restrict__ bb1, const float* __restrict__ ab1,
    float* __restrict__ Y0, float* __restrict__ Y1,
    unsigned short* __restrict__ Yb0, unsigned short* __restrict__ Yb1)
{
    __shared__ float xs[64 * 64];
    __shared__ float ws[64 * 64];
    __shared__ float bsh[64];
    __shared__ float s_alpha;
    int br = blockIdx.y;
    const float* X  = br ? X1 : X0;
    const float* Wa = br ? Wa1 : Wa0;
    const float* ba = br ? ba1 : ba0;
    const float* aa = br ? aa1 : aa0;
    const float* Wb = br ? Wb1 : Wb0;
    const float* bb = br ? bb1 : bb0;
    const float* ab = br ? ab1 : ab0;
    float* Y = br ? Y1 : Y0;
    unsigned short* Yb = br ? Yb1 : Yb0;
    int tid = threadIdx.x;
    int tx = tid & 15, ty = tid >> 4;
    int pbase = blockIdx.x * 64;

    for (int t = tid; t < 1024; t += 256) {
        int c = t >> 4, p4 = t & 15;
        ((float4*)xs)[c * 16 + p4] = *(const float4*)(X + c * NPIX + pbase + p4 * 4);
    }
    for (int t = tid; t < 1024; t += 256)
        ((float4*)ws)[t] = ((const float4*)Wa)[t];
    if (tid < 64) bsh[tid] = ba[tid];
    if (tid == 0) s_alpha = aa[0];
    __syncthreads();

    float acc[4][4];
    #pragma unroll
    for (int j = 0; j < 4; j++)
        #pragma unroll
        for (int i = 0; i < 4; i++) acc[j][i] = bsh[ty * 4 + j];
    for (int c = 0; c < 64; c++) {
        float xv[4], wv[4];
        #pragma unroll
        for (int i = 0; i < 4; i++) xv[i] = xs[c * 64 + tx + 16 * i];
        #pragma unroll
        for (int j = 0; j < 4; j++) wv[j] = ws[(ty * 4 + j) * 64 + c];
        #pragma unroll
        for (int j = 0; j < 4; j++)
            #pragma unroll
            for (int i = 0; i < 4; i++) acc[j][i] = fmaf(wv[j], xv[i], acc[j][i]);
    }
    float al = s_alpha;
    __syncthreads();

    #pragma unroll
    for (int j = 0; j < 4; j++)
        #pragma unroll
        for (int i = 0; i < 4; i++) {
            float v = acc[j][i];
            v = (v >= 0.0f) ? v : al * v;
            xs[(ty * 4 + j) * 64 + tx + 16 * i] = v;
        }
    for (int t = tid; t < 1024; t += 256)
        ((float4*)ws)[t] = ((const float4*)Wb)[t];
    if (tid < 64) bsh[tid] = bb[tid];
    if (tid == 0) s_alpha = ab[0];
    __syncthreads();

    #pragma unroll
    for (int j = 0; j < 4; j++)
        #pragma unroll
        for (int i = 0; i < 4; i++) acc[j][i] = bsh[ty * 4 + j];
    for (int c = 0; c < 64; c++) {
        float xv[4], wv[4];
        #pragma unroll
        for (int i = 0; i < 4; i++) xv[i] = xs[c * 64 + tx + 16 * i];
        #pragma unroll
        for (int j = 0; j < 4; j++) wv[j] = ws[(ty * 4 + j) * 64 + c];
        #pragma unroll
        for (int j = 0; j < 4; j++)
            #pragma unroll
            for (int i = 0; i < 4; i++) acc[j][i] = fmaf(wv[j], xv[i], acc[j][i]);
    }
    float al2 = s_alpha;
    #pragma unroll
    for (int i = 0; i < 4; i++) {
        int pix = pbase + tx + 16 * i;
        float4 o4;
        float v;
        v = acc[0][i]; o4.x = (v >= 0.0f) ? v : al2 * v;
        v = acc[1][i]; o4.y = (v >= 0.0f) ? v : al2 * v;
        v = acc[2][i]; o4.z = (v >= 0.0f) ? v : al2 * v;
        v = acc[3][i]; o4.w = (v >= 0.0f) ? v : al2 * v;
        *(float4*)(Y + pix * 64 + ty * 4) = o4;
        uint2 b2;
        b2.x = pack_bf16x2(o4.x, o4.y);
        b2.y = pack_bf16x2(o4.z, o4.w);
        *(uint2*)(Yb + pix * 64 + ty * 4) = b2;
    }
}

// ---------------- K3: bf16 HMMA sim GEMM + fused per-thread top-8 candidates -------
#define BPITCH 72
__global__ __launch_bounds__(256) void k_sim_hmma() {
    __shared__ __align__(16) unsigned short Bs[128 * BPITCH];
    int tid = threadIdx.x;
    int w = tid >> 5, lane = tid & 31;
    int rowbase = blockIdx.x * 128;
    int split = blockIdx.y;
    int colbase = split * 4608;

    int r0 = rowbase + w * 16 + (lane >> 2);
    int r1 = r0 + 8;
    int lg = lane & 3;

    unsigned a[4][4];
    #pragma unroll
    for (int ks = 0; ks < 4; ks++) {
        int k0 = ks * 16 + lg * 2;
        a[ks][0] = *(const unsigned*)(g_hbf + r0 * 64 + k0);
        a[ks][1] = *(const unsigned*)(g_hbf + r1 * 64 + k0);
        a[ks][2] = *(const unsigned*)(g_hbf + r0 * 64 + k0 + 8);
        a[ks][3] = *(const unsigned*)(g_hbf + r1 * 64 + k0 + 8);
    }

    float v0[8], v1[8]; int id0[8], id1[8];
    #pragma unroll
    for (int j = 0; j < 8; j++) {
        v0[j] = -INFINITY; v1[j] = -INFINITY; id0[j] = 0; id1[j] = 0;
    }

    for (int tile = 0; tile < 36; tile++) {
        int cb = colbase + tile * 128;
        __syncthreads();
        for (int q = tid; q < 1024; q += 256) {
            int n = q >> 3, c8 = q & 7;
            *(float4*)(Bs + n * BPITCH + c8 * 8) =
                *(const float4*)(g_mbf + (cb + n) * 64 + c8 * 8);
        }
        __syncthreads();

        #pragma unroll 2
        for (int nc = 0; nc < 16; nc++) {
            int n0 = nc * 8;
            float c0 = 0.0f, c1 = 0.0f, c2 = 0.0f, c3 = 0.0f;
            const unsigned short* brow = Bs + (n0 + (lane >> 2)) * BPITCH + lg * 2;
            #pragma unroll
            for (int ks = 0; ks < 4; ks++) {
                unsigned b0 = *(const unsigned*)(brow + ks * 16);
                unsigned b1 = *(const unsigned*)(brow + ks * 16 + 8);
                asm volatile(
                    "mma.sync.aligned.m16n8k16.row.col.f32.bf16.bf16.f32 "
                    "{%0,%1,%2,%3}, {%4,%5,%6,%7}, {%8,%9}, {%0,%1,%2,%3};"
                    : "+f"(c0), "+f"(c1), "+f"(c2), "+f"(c3)
                    : "r"(a[ks][0]), "r"(a[ks][1]), "r"(a[ks][2]), "r"(a[ks][3]),
                      "r"(b0), "r"(b1));
            }
            int col = cb + n0 + lg * 2;
            if (fmaxf(c0, c1) > v0[7]) {
                top8_update(v0, id0, c0, col);
                top8_update(v0, id0, c1, col + 1);
            }
            if (fmaxf(c2, c3) > v1[7]) {
                top8_update(v1, id1, c2, col);
                top8_update(v1, id1, c3, col + 1);
            }
        }
    }

    int base0 = r0 * NCAND + split * 32 + lg * 8;
    int base1 = r1 * NCAND + split * 32 + lg * 8;
    #pragma unroll
    for (int j = 0; j < 8; j++) {
        g_cidx[base0 + j] = id0[j];
        g_cidx[base1 + j] = id1[j];
    }
}

// ---------------- K4: exact fp32 rescore, cooperative coalesced gathers ------------
// Warp per row. hfeat row: float2 per lane (registers). Per candidate: broadcast
// index, ALL lanes load consecutive float2 of that mfeat row (2 L1 lines instead
// of 32), butterfly-reduce. Groups of 8 candidates give ILP across reductions.
__global__ __launch_bounds__(256) void k_rescore() {
    int tid = threadIdx.x;
    int w = tid >> 5, lane = tid & 31;
    int row = blockIdx.x * 8 + w;

    float2 h = *(const float2*)(g_hfeat + row * 64 + lane * 2);
    int myc0 = g_cidx[row * NCAND + lane];
    int myc1 = g_cidx[row * NCAND + 32 + lane];

    float v[2]; int ix[2];
    ix[0] = myc0; ix[1] = myc1;
    v[0] = 0.0f; v[1] = 0.0f;

    #pragma unroll
    for (int half = 0; half < 2; half++) {
        int src = half ? myc1 : myc0;
        #pragma unroll
        for (int g = 0; g < 4; g++) {
            float p[8];
            #pragma unroll
            for (int j = 0; j < 8; j++) {
                int ci = __shfl_sync(0xffffffffu, src, g * 8 + j);
                float2 m = *(const float2*)(g_mfeat + ci * 64 + lane * 2);
                p[j] = fmaf(h.x, m.x, h.y * m.y);
            }
            #pragma unroll
            for (int j = 0; j < 8; j++) {
                #pragma unroll
                for (int off = 16; off; off >>= 1)
                    p[j] += __shfl_xor_sync(0xffffffffu, p[j], off);
            }
            #pragma unroll
            for (int j = 0; j < 8; j++)
                if (lane == g * 8 + j) v[half] = p[j];
        }
    }

    // 5 rounds of shuffle-argmax with (value desc, index asc) tie-break
    #pragma unroll
    for (int sel = 0; sel < KNN; sel++) {
        bool first = (v[0] > v[1]) || (v[0] == v[1] && ix[0] < ix[1]);
        float bv = first ? v[0] : v[1];
        int   bi = first ? ix[0] : ix[1];
        #pragma unroll
        for (int off = 16; off; off >>= 1) {
            float ov = __shfl_xor_sync(0xffffffffu, bv, off);
            int   oi = __shfl_xor_sync(0xffffffffu, bi, off);
            if (ov > bv || (ov == bv && oi < bi)) { bv = ov; bi = oi; }
        }
        if (lane == 0) g_topk[row * KNN + sel] = bi;
        if (ix[0] == bi) v[0] = -INFINITY;
        if (ix[1] == bi) v[1] = -INFINITY;
    }
}

// ---------------- K5: GAT fc  z = [hfeat|mfeat] @ Wg,  el/er per node --------------
__global__ __launch_bounds__(256) void k_gatz(const float* __restrict__ Wg,
                                              const float* __restrict__ alv,
                                              const float* __restrict__ arv) {
    __shared__ float xs[64 * 65];
    __shared__ float ws[64 * 64];
    __shared__ float als[64], ars[64];
    __shared__ float sel[64], ser[64];
    int tid = threadIdx.x, tx = tid & 15, ty = tid >> 4;
    int pbase = blockIdx.x * 64;
    if (tid < 64) { als[tid] = alv[tid]; ars[tid] = arv[tid]; sel[tid] = 0.0f; ser[tid] = 0.0f; }

    float acc[4][4];
    #pragma unroll
    for (int j = 0; j < 4; j++)
        #pragma unroll
        for (int i = 0; i < 4; i++) acc[j][i] = 0.0f;

    for (int half = 0; half < 2; half++) {
        const float* X = half ? g_mfeat : g_hfeat;
        __syncthreads();
        for (int t = tid; t < 1024; t += 256) {
            int p = t >> 4, cc = t & 15;
            float4 v = *(const float4*)(X + (pbase + p) * 64 + cc * 4);
            xs[(4 * cc + 0) * 65 + p] = v.x;
            xs[(4 * cc + 1) * 65 + p] = v.y;
            xs[(4 * cc + 2) * 65 + p] = v.z;
            xs[(4 * cc + 3) * 65 + p] = v.w;
        }
        for (int t = tid; t < 1024; t += 256)
            ((float4*)ws)[t] = ((const float4*)(Wg + half * 64 * 64))[t];
        __syncthreads();
        for (int c = 0; c < 64; c++) {
            float xv[4];
            #pragma unroll
            for (int i = 0; i < 4; i++) xv[i] = xs[c * 65 + tx + 16 * i];
            float4 w4 = *(const float4*)(ws + c * 64 + ty * 4);
            float wv[4] = {w4.x, w4.y, w4.z, w4.w};
            #pragma unroll
            for (int j = 0; j < 4; j++)
                #pragma unroll
                for (int i = 0; i < 4; i++) acc[j][i] = fmaf(wv[j], xv[i], acc[j][i]);
        }
    }

    float a_l[4], a_r[4];
    #pragma unroll
    for (int j = 0; j < 4; j++) { a_l[j] = als[ty * 4 + j]; a_r[j] = ars[ty * 4 + j]; }
    #pragma unroll
    for (int i = 0; i < 4; i++) {
        int p = pbase + tx + 16 * i;
        float4 z4 = make_float4(acc[0][i], acc[1][i], acc[2][i], acc[3][i]);
        *(float4*)(g_z + p * 64 + ty * 4) = z4;
        float e_l = 0.0f, e_r = 0.0f;
        #pragma unroll
        for (int j = 0; j < 4; j++) {
            e_l = fmaf(acc[j][i], a_l[j], e_l);
            e_r = fmaf(acc[j][i], a_r[j], e_r);
        }
        atomicAdd(&sel[tx + 16 * i], e_l);
        atomicAdd(&ser[tx + 16 * i], e_r);
    }
    __syncthreads();
    if (tid < 64) {
        g_el[pbase + tid] = sel[tid];
        g_er[pbase + tid] = ser[tid];
        g_den[pbase + tid] = 0.0f;
    }
}

// ---------------- K6: softmax denominator over ALL edges (k-NN + self loops) -------
__global__ void k_edge_den() {
    int e = blockIdx.x * blockDim.x + threadIdx.x;
    if (e >= ETOT) return;
    int src, dst;
    if (e < E5) { src = e % NPIX; dst = g_topk[e]; }
    else        { src = e - E5;   dst = src; }
    float l = g_el[src] + g_er[dst];
    l = (l >= 0.0f) ? l : 0.2f * l;
    atomicAdd(&g_den[dst], expf(l));
}

// ---------------- K7: self-loop contribution initializes g_agg (plain stores) -----
__global__ void k_selfagg() {
    int t = blockIdx.x * blockDim.x + threadIdx.x;   // n*16 + c4
    if (t >= NPIX * 16) return;
    int n = t >> 4, c4 = t & 15;
    float l = g_el[n] + g_er[n];
    l = (l >= 0.0f) ? l : 0.2f * l;
    float alpha = expf(l) / g_den[n];
    float4 zv = *(const float4*)(g_z + n * 64 + c4 * 4);
    float4 o;
    o.x = alpha * zv.x; o.y = alpha * zv.y; o.z = alpha * zv.z; o.w = alpha * zv.w;
    *(float4*)(g_agg + n * 64 + c4 * 4) = o;
}

// ---------------- K8: k-NN edge aggregation (4 threads / edge, 16 ch each) ---------
__global__ void k_edge_agg() {
    int t = blockIdx.x * blockDim.x + threadIdx.x;
    int e = t >> 2;
    if (e >= E5) return;
    int c0 = (t & 3) * 16;
    int src = e % NPIX;
    int dst = g_topk[e];
    float l = g_el[src] + g_er[dst];
    l = (l >= 0.0f) ? l : 0.2f * l;
    float alpha = expf(l) / g_den[dst];
    const float* zs = g_z + src * 64 + c0;
    float* ag = g_agg + dst * 64 + c0;
    #pragma unroll
    for (int c = 0; c < 16; c++) atomicAdd(ag + c, alpha * zs[c]);
}

// ---------------- K9: tiled transpose pixel-major agg -> channel-major (+bg) -------
__global__ __launch_bounds__(256) void k_transbias(const float* __restrict__ bg) {
    __shared__ float tb[64 * 65];
    __shared__ float bs[64];
    int tid = threadIdx.x;
    int nb = blockIdx.x * 64;
    if (tid < 64) bs[tid] = bg[tid];
    for (int t = tid; t < 1024; t += 256) {
        int p = t >> 4, cc = t & 15;
        float4 v = *(const float4*)(g_agg + (nb + p) * 64 + cc * 4);
        tb[(4 * cc + 0) * 65 + p] = v.x;
        tb[(4 * cc + 1) * 65 + p] = v.y;
        tb[(4 * cc + 2) * 65 + p] = v.z;
        tb[(4 * cc + 3) * 65 + p] = v.w;
    }
    __syncthreads();
    for (int k = 0; k < 16; k++) {
        int idx = tid + k * 256;
        int c = idx >> 6, nn = idx & 63;
        g_fmap[c * NPIX + nb + nn] = tb[c * 65 + nn] + bs[c];
    }
}

// ---------------- K10: 3x3 conv, 4 channels staged per barrier ---------------------
__global__ __launch_bounds__(256) void k_conv3x3(const float* __restrict__ In,
                                                 const float* __restrict__ Kw,
                                                 const float* __restrict__ bias,
                                                 const float* __restrict__ aptr,
                                                 float* __restrict__ Out,
                                                 const float* __restrict__ resid) {
    __shared__ float ws[16 * 64 * 9];   // 36864 B
    __shared__ float tile[4][324];
    int og = blockIdx.z * 16;
    for (int i = threadIdx.x; i < 16 * 64 * 9; i += 256) ws[i] = Kw[og * 576 + i];
    float alpha = aptr[0];
    int sub = threadIdx.x >> 6;
    int q   = threadIdx.x & 63;
    int qx  = q & 3, y = q >> 2;
    int x0 = blockIdx.x * 16, y0 = blockIdx.y * 16;
    float acc[4][4];
    #pragma unroll
    for (int j = 0; j < 4; j++) {
        float b = bias[og + sub * 4 + j];
        #pragma unroll
        for (int i = 0; i < 4; i++) acc[j][i] = b;
    }
    for (int cs = 0; cs < 64; cs += 4) {
        __syncthreads();
        for (int i = threadIdx.x; i < 1296; i += 256) {
            int cc = i / 324, p = i - cc * 324;
            int lx = p % 18 - 1 + x0;
            int ly = p / 18 - 1 + y0;
            tile[cc][p] = (lx >= 0 && lx < WW && ly >= 0 && ly < HH)
                            ? In[(cs + cc) * NPIX + ly * WW + lx] : 0.0f;
        }
        __syncthreads();
        #pragma unroll
        for (int cc = 0; cc < 4; cc++) {
            float r[3][6];
            #pragma unroll
            for (int ky = 0; ky < 3; ky++)
                #pragma unroll
                for (int m = 0; m < 6; m++)
                    r[ky][m] = tile[cc][(y + ky) * 18 + qx * 4 + m];
            #pragma unroll
            for (int j = 0; j < 4; j++) {
                const float* w = ws + ((sub * 4 + j) * 64 + cs + cc) * 9;
                float wv[9];
                #pragma unroll
                for (int k = 0; k < 9; k++) wv[k] = w[k];
                #pragma unroll
                for (int i = 0; i < 4; i++)
                    #pragma unroll
                    for (int ky = 0; ky < 3; ky++)
                        #pragma unroll
                        for (int kx = 0; kx < 3; kx++)
                            acc[j][i] = fmaf(wv[ky * 3 + kx], r[ky][kx + i], acc[j][i]);
            }
        }
    }
    int pix0 = (y0 + y) * WW + x0 + qx * 4;
    #pragma unroll
    for (int j = 0; j < 4; j++) {
        int o = og + sub * 4 + j;
        float4 v4;
        float v;
        v = acc[j][0]; v4.x = (v >= 0.0f) ? v : alpha * v;
        v = acc[j][1]; v4.y = (v >= 0.0f) ? v : alpha * v;
        v = acc[j][2]; v4.z = (v >= 0.0f) ? v : alpha * v;
        v = acc[j][3]; v4.w = (v >= 0.0f) ? v : alpha * v;
        if (resid) {
            float4 rr = *(const float4*)(resid + o * NPIX + pix0);
            v4.x += rr.x; v4.y += rr.y; v4.z += rr.z; v4.w += rr.w;
        }
        *(float4*)(Out + o * NPIX + pix0) = v4;
    }
}

// ---------------- launch ----------------
extern "C" void kernel_launch(void* const* d_in, const int* in_sizes, int n_in,
                              void* d_out, int out_size) {
    const float* msi  = (const float*)d_in[0];
    const float* hsi  = (const float*)d_in[1];
    const float* W1a  = (const float*)d_in[2];
    const float* b1a  = (const float*)d_in[3];
    const float* a1a  = (const float*)d_in[4];
    const float* W1b  = (const float*)d_in[5];
    const float* b1b  = (const float*)d_in[6];
    const float* a1b  = (const float*)d_in[7];
    const float* W2a  = (const float*)d_in[8];
    const float* b2a  = (const float*)d_in[9];
    const float* a2a  = (const float*)d_in[10];
    const float* W2b  = (const float*)d_in[11];
    const float* b2b  = (const float*)d_in[12];
    const float* a2b  = (const float*)d_in[13];
    const float* Wg   = (const float*)d_in[14];
    const float* attl = (const float*)d_in[15];
    const float* attr = (const float*)d_in[16];
    const float* bg   = (const float*)d_in[17];
    const float* Ku1  = (const float*)d_in[18];
    const float* bu1  = (const float*)d_in[19];
    const float* au1  = (const float*)d_in[20];
    const float* Ku2  = (const float*)d_in[21];
    const float* bu2  = (const float*)d_in[22];
    const float* au2  = (const float*)d_in[23];

    float *p_hsi_up, *p_hfeat, *p_mfeat, *p_fmap, *p_up1;
    unsigned short *p_hbf, *p_mbf;
    cudaGetSymbolAddress((void**)&p_hsi_up, g_hsi_up);
    cudaGetSymbolAddress((void**)&p_hfeat,  g_hfeat);
    cudaGetSymbolAddress((void**)&p_mfeat,  g_mfeat);
    cudaGetSymbolAddress((void**)&p_fmap,   g_fmap);
    cudaGetSymbolAddress((void**)&p_up1,    g_up1);
    cudaGetSymbolAddress((void**)&p_hbf,    g_hbf);
    cudaGetSymbolAddress((void**)&p_mbf,    g_mbf);

    k_bicubic<<<dim3(CCH, 4), 256>>>(hsi);

    k_embed<<<dim3(NPIX / 64, 2), 256>>>(p_hsi_up, msi,
                                         W1a, b1a, a1a, W1b, b1b, a1b,
                                         W2a, b2a, a2a, W2b, b2b, a2b,
                                         p_hfeat, p_mfeat, p_hbf, p_mbf);

    k_sim_hmma<<<dim3(72, 2), 256>>>();
    k_rescore<<<NPIX / 8, 256>>>();

    k_gatz<<<NPIX / 64, 256>>>(Wg, attl, attr);
    k_edge_den<<<(ETOT + 255) / 256, 256>>>();
    k_selfagg<<<(NPIX * 16 + 255) / 256, 256>>>();
    k_edge_agg<<<(E5 * 4 + 255) / 256, 256>>>();

    k_transbias<<<NPIX / 64, 256>>>(bg);

    k_conv3x3<<<dim3(6, 6, 4), 256>>>(p_fmap, Ku1, bu1, au1, p_up1, nullptr);
    k_conv3x3<<<dim3(6, 6, 4), 256>>>(p_up1, Ku2, bu2, au2, (float*)d_out, p_hsi_up);
}

// round 13
// speedup vs baseline: 2.1161x; 1.1316x over previous
#include <cuda_runtime.h>
#include <cuda_bf16.h>
#include <math.h>

#define NPIX 9216
#define CCH  64
#define HH   96
#define WW   96
#define HS   24
#define KNN  5
#define E5   (NPIX * KNN)                /* 46080 */
#define ETOT (E5 + NPIX)                 /* 55296 */
#define NCAND 64                         /* candidates per row (2 splits x 4 groups x 8) */

// ---------------- scratch (static device globals; no allocation) ----------------
__device__ float    g_hsi_up[CCH * NPIX];   // channel-major [c][pix]; also the residual
__device__ float    g_hfeat[NPIX * CCH];    // pixel-major [pix][c]
__device__ float    g_mfeat[NPIX * CCH];
__device__ unsigned short g_hbf[NPIX * CCH];  // bf16 copies, pixel-major
__device__ unsigned short g_mbf[NPIX * CCH];
__device__ float    g_z    [NPIX * CCH];
__device__ float    g_el   [NPIX];
__device__ float    g_er   [NPIX];
__device__ int      g_cidx [NPIX * NCAND];
__device__ int      g_topk [NPIX * KNN];
__device__ float    g_den  [NPIX];
__device__ float    g_agg  [CCH * NPIX];    // CHANNEL-major: spreads hot-dst atomics over LTS
__device__ float    g_up1  [CCH * NPIX];

// ---------------- helpers ----------------
__device__ __forceinline__ unsigned pack_bf16x2(float lo, float hi) {
    unsigned d;
    asm("cvt.rn.bf16x2.f32 %0, %1, %2;" : "=r"(d) : "f"(hi), "f"(lo));
    return d;
}

__device__ __forceinline__ float cubw(float d) {
    d = fabsf(d);
    const float a = -0.75f;
    if (d <= 1.0f) return ((a + 2.0f) * d - (a + 3.0f)) * d * d + 1.0f;
    if (d < 2.0f)  return ((a * d - 5.0f * a) * d + 8.0f * a) * d - 4.0f * a;
    return 0.0f;
}

// top-8 running list, all-static indexing (stays in registers)
__device__ __forceinline__ void top8_update(float (&v)[8], int (&id)[8], float val, int idx) {
    if (val <= v[7]) return;
    v[7] = val; id[7] = idx;
    #pragma unroll
    for (int s = 7; s > 0; s--) {
        if (v[s] > v[s - 1]) {
            float tv = v[s - 1]; v[s - 1] = v[s]; v[s] = tv;
            int   ti = id[s - 1]; id[s - 1] = id[s]; id[s] = ti;
        }
    }
}

// ---------------- K1: bicubic x4 upsample, smem-staged (24x24 -> 96x96) ----------
__global__ __launch_bounds__(256) void k_bicubic(const float* __restrict__ in) {
    __shared__ float s[HS * HS];
    int c = blockIdx.x;
    for (int i = threadIdx.x; i < HS * HS; i += 256) s[i] = in[c * HS * HS + i];
    __syncthreads();
    int obase = blockIdx.y * (NPIX / 4);
    for (int o = obase + threadIdx.x; o < obase + NPIX / 4; o += 256) {
        int x = o % WW, y = o / WW;
        float fy = (y + 0.5f) * 0.25f - 0.5f;
        float iy = floorf(fy); float ty = fy - iy;
        float fx = (x + 0.5f) * 0.25f - 0.5f;
        float ix = floorf(fx); float tx = fx - ix;
        float wy[4], wx[4]; int sy[4], sx[4];
        #pragma unroll
        for (int k = 0; k < 4; k++) {
            wy[k] = cubw(ty - (float)(k - 1));
            wx[k] = cubw(tx - (float)(k - 1));
            sy[k] = min(max((int)iy + k - 1, 0), HS - 1);
            sx[k] = min(max((int)ix + k - 1, 0), HS - 1);
        }
        float acc = 0.0f;
        #pragma unroll
        for (int i = 0; i < 4; i++) {
            float r = 0.0f;
            #pragma unroll
            for (int j = 0; j < 4; j++) r = fmaf(wx[j], s[sy[i] * HS + sx[j]], r);
            acc = fmaf(wy[i], r, acc);
        }
        g_hsi_up[c * NPIX + o] = acc;
    }
}

// ---------------- K2: fused 2-layer 1x1-conv embed, both branches -----------------
__global__ __launch_bounds__(256) void k_embed(
    const float* __restrict__ X0, const float* __restrict__ X1,
    const float* __restrict__ Wa0, const float* __restrict__ ba0, const float* __restrict__ aa0,
    const float* __restrict__ Wb0, const float* __restrict__ bb0, const float* __restrict__ ab0,
    const float* __restrict__ Wa1, const float* __restrict__ ba1, const float* __restrict__ aa1,
    const float* __restrict__ Wb1, const float* __restrict__ bb1, const float* __restrict__ ab1,
    float* __restrict__ Y0, float* __restrict__ Y1,
    unsigned short* __restrict__ Yb0, unsigned short* __restrict__ Yb1)
{
    __shared__ float xs[64 * 64];
    __shared__ float ws[64 * 64];
    __shared__ float bsh[64];
    __shared__ float s_alpha;
    int br = blockIdx.y;
    const float* X  = br ? X1 : X0;
    const float* Wa = br ? Wa1 : Wa0;
    const float* ba = br ? ba1 : ba0;
    const float* aa = br ? aa1 : aa0;
    const float* Wb = br ? Wb1 : Wb0;
    const float* bb = br ? bb1 : bb0;
    const float* ab = br ? ab1 : ab0;
    float* Y = br ? Y1 : Y0;
    unsigned short* Yb = br ? Yb1 : Yb0;
    int tid = threadIdx.x;
    int tx = tid & 15, ty = tid >> 4;
    int pbase = blockIdx.x * 64;

    for (int t = tid; t < 1024; t += 256) {
        int c = t >> 4, p4 = t & 15;
        ((float4*)xs)[c * 16 + p4] = *(const float4*)(X + c * NPIX + pbase + p4 * 4);
    }
    for (int t = tid; t < 1024; t += 256)
        ((float4*)ws)[t] = ((const float4*)Wa)[t];
    if (tid < 64) bsh[tid] = ba[tid];
    if (tid == 0) s_alpha = aa[0];
    __syncthreads();

    float acc[4][4];
    #pragma unroll
    for (int j = 0; j < 4; j++)
        #pragma unroll
        for (int i = 0; i < 4; i++) acc[j][i] = bsh[ty * 4 + j];
    for (int c = 0; c < 64; c++) {
        float xv[4], wv[4];
        #pragma unroll
        for (int i = 0; i < 4; i++) xv[i] = xs[c * 64 + tx + 16 * i];
        #pragma unroll
        for (int j = 0; j < 4; j++) wv[j] = ws[(ty * 4 + j) * 64 + c];
        #pragma unroll
        for (int j = 0; j < 4; j++)
            #pragma unroll
            for (int i = 0; i < 4; i++) acc[j][i] = fmaf(wv[j], xv[i], acc[j][i]);
    }
    float al = s_alpha;
    __syncthreads();

    #pragma unroll
    for (int j = 0; j < 4; j++)
        #pragma unroll
        for (int i = 0; i < 4; i++) {
            float v = acc[j][i];
            v = (v >= 0.0f) ? v : al * v;
            xs[(ty * 4 + j) * 64 + tx + 16 * i] = v;
        }
    for (int t = tid; t < 1024; t += 256)
        ((float4*)ws)[t] = ((const float4*)Wb)[t];
    if (tid < 64) bsh[tid] = bb[tid];
    if (tid == 0) s_alpha = ab[0];
    __syncthreads();

    #pragma unroll
    for (int j = 0; j < 4; j++)
        #pragma unroll
        for (int i = 0; i < 4; i++) acc[j][i] = bsh[ty * 4 + j];
    for (int c = 0; c < 64; c++) {
        float xv[4], wv[4];
        #pragma unroll
        for (int i = 0; i < 4; i++) xv[i] = xs[c * 64 + tx + 16 * i];
        #pragma unroll
        for (int j = 0; j < 4; j++) wv[j] = ws[(ty * 4 + j) * 64 + c];
        #pragma unroll
        for (int j = 0; j < 4; j++)
            #pragma unroll
            for (int i = 0; i < 4; i++) acc[j][i] = fmaf(wv[j], xv[i], acc[j][i]);
    }
    float al2 = s_alpha;
    #pragma unroll
    for (int i = 0; i < 4; i++) {
        int pix = pbase + tx + 16 * i;
        float4 o4;
        float v;
        v = acc[0][i]; o4.x = (v >= 0.0f) ? v : al2 * v;
        v = acc[1][i]; o4.y = (v >= 0.0f) ? v : al2 * v;
        v = acc[2][i]; o4.z = (v >= 0.0f) ? v : al2 * v;
        v = acc[3][i]; o4.w = (v >= 0.0f) ? v : al2 * v;
        *(float4*)(Y + pix * 64 + ty * 4) = o4;
        uint2 b2;
        b2.x = pack_bf16x2(o4.x, o4.y);
        b2.y = pack_bf16x2(o4.z, o4.w);
        *(uint2*)(Yb + pix * 64 + ty * 4) = b2;
    }
}

// ---------------- K3: bf16 HMMA sim GEMM + fused per-thread top-8 candidates -------
#define BPITCH 72
__global__ __launch_bounds__(256) void k_sim_hmma() {
    __shared__ __align__(16) unsigned short Bs[128 * BPITCH];
    int tid = threadIdx.x;
    int w = tid >> 5, lane = tid & 31;
    int rowbase = blockIdx.x * 128;
    int split = blockIdx.y;
    int colbase = split * 4608;

    int r0 = rowbase + w * 16 + (lane >> 2);
    int r1 = r0 + 8;
    int lg = lane & 3;

    unsigned a[4][4];
    #pragma unroll
    for (int ks = 0; ks < 4; ks++) {
        int k0 = ks * 16 + lg * 2;
        a[ks][0] = *(const unsigned*)(g_hbf + r0 * 64 + k0);
        a[ks][1] = *(const unsigned*)(g_hbf + r1 * 64 + k0);
        a[ks][2] = *(const unsigned*)(g_hbf + r0 * 64 + k0 + 8);
        a[ks][3] = *(const unsigned*)(g_hbf + r1 * 64 + k0 + 8);
    }

    float v0[8], v1[8]; int id0[8], id1[8];
    #pragma unroll
    for (int j = 0; j < 8; j++) {
        v0[j] = -INFINITY; v1[j] = -INFINITY; id0[j] = 0; id1[j] = 0;
    }

    for (int tile = 0; tile < 36; tile++) {
        int cb = colbase + tile * 128;
        __syncthreads();
        for (int q = tid; q < 1024; q += 256) {
            int n = q >> 3, c8 = q & 7;
            *(float4*)(Bs + n * BPITCH + c8 * 8) =
                *(const float4*)(g_mbf + (cb + n) * 64 + c8 * 8);
        }
        __syncthreads();

        #pragma unroll 2
        for (int nc = 0; nc < 16; nc++) {
            int n0 = nc * 8;
            float c0 = 0.0f, c1 = 0.0f, c2 = 0.0f, c3 = 0.0f;
            const unsigned short* brow = Bs + (n0 + (lane >> 2)) * BPITCH + lg * 2;
            #pragma unroll
            for (int ks = 0; ks < 4; ks++) {
                unsigned b0 = *(const unsigned*)(brow + ks * 16);
                unsigned b1 = *(const unsigned*)(brow + ks * 16 + 8);
                asm volatile(
                    "mma.sync.aligned.m16n8k16.row.col.f32.bf16.bf16.f32 "
                    "{%0,%1,%2,%3}, {%4,%5,%6,%7}, {%8,%9}, {%0,%1,%2,%3};"
                    : "+f"(c0), "+f"(c1), "+f"(c2), "+f"(c3)
                    : "r"(a[ks][0]), "r"(a[ks][1]), "r"(a[ks][2]), "r"(a[ks][3]),
                      "r"(b0), "r"(b1));
            }
            int col = cb + n0 + lg * 2;
            if (fmaxf(c0, c1) > v0[7]) {
                top8_update(v0, id0, c0, col);
                top8_update(v0, id0, c1, col + 1);
            }
            if (fmaxf(c2, c3) > v1[7]) {
                top8_update(v1, id1, c2, col);
                top8_update(v1, id1, c3, col + 1);
            }
        }
    }

    int base0 = r0 * NCAND + split * 32 + lg * 8;
    int base1 = r1 * NCAND + split * 32 + lg * 8;
    #pragma unroll
    for (int j = 0; j < 8; j++) {
        g_cidx[base0 + j] = id0[j];
        g_cidx[base1 + j] = id1[j];
    }
}

// ---------------- K4: exact fp32 rescore, cooperative coalesced gathers ------------
__global__ __launch_bounds__(256) void k_rescore() {
    int tid = threadIdx.x;
    int w = tid >> 5, lane = tid & 31;
    int row = blockIdx.x * 8 + w;

    float2 h = *(const float2*)(g_hfeat + row * 64 + lane * 2);
    int myc0 = g_cidx[row * NCAND + lane];
    int myc1 = g_cidx[row * NCAND + 32 + lane];

    float v[2]; int ix[2];
    ix[0] = myc0; ix[1] = myc1;
    v[0] = 0.0f; v[1] = 0.0f;

    #pragma unroll
    for (int half = 0; half < 2; half++) {
        int src = half ? myc1 : myc0;
        #pragma unroll
        for (int g = 0; g < 4; g++) {
            float p[8];
            #pragma unroll
            for (int j = 0; j < 8; j++) {
                int ci = __shfl_sync(0xffffffffu, src, g * 8 + j);
                float2 m = *(const float2*)(g_mfeat + ci * 64 + lane * 2);
                p[j] = fmaf(h.x, m.x, h.y * m.y);
            }
            #pragma unroll
            for (int j = 0; j < 8; j++) {
                #pragma unroll
                for (int off = 16; off; off >>= 1)
                    p[j] += __shfl_xor_sync(0xffffffffu, p[j], off);
            }
            #pragma unroll
            for (int j = 0; j < 8; j++)
                if (lane == g * 8 + j) v[half] = p[j];
        }
    }

    #pragma unroll
    for (int sel = 0; sel < KNN; sel++) {
        bool first = (v[0] > v[1]) || (v[0] == v[1] && ix[0] < ix[1]);
        float bv = first ? v[0] : v[1];
        int   bi = first ? ix[0] : ix[1];
        #pragma unroll
        for (int off = 16; off; off >>= 1) {
            float ov = __shfl_xor_sync(0xffffffffu, bv, off);
            int   oi = __shfl_xor_sync(0xffffffffu, bi, off);
            if (ov > bv || (ov == bv && oi < bi)) { bv = ov; bi = oi; }
        }
        if (lane == 0) g_topk[row * KNN + sel] = bi;
        if (ix[0] == bi) v[0] = -INFINITY;
        if (ix[1] == bi) v[1] = -INFINITY;
    }
}

// ---------------- K5: GAT fc  z = [hfeat|mfeat] @ Wg,  el/er per node --------------
__global__ __launch_bounds__(256) void k_gatz(const float* __restrict__ Wg,
                                              const float* __restrict__ alv,
                                              const float* __restrict__ arv) {
    __shared__ float xs[64 * 65];
    __shared__ float ws[64 * 64];
    __shared__ float als[64], ars[64];
    __shared__ float sel[64], ser[64];
    int tid = threadIdx.x, tx = tid & 15, ty = tid >> 4;
    int pbase = blockIdx.x * 64;
    if (tid < 64) { als[tid] = alv[tid]; ars[tid] = arv[tid]; sel[tid] = 0.0f; ser[tid] = 0.0f; }

    float acc[4][4];
    #pragma unroll
    for (int j = 0; j < 4; j++)
        #pragma unroll
        for (int i = 0; i < 4; i++) acc[j][i] = 0.0f;

    for (int half = 0; half < 2; half++) {
        const float* X = half ? g_mfeat : g_hfeat;
        __syncthreads();
        for (int t = tid; t < 1024; t += 256) {
            int p = t >> 4, cc = t & 15;
            float4 v = *(const float4*)(X + (pbase + p) * 64 + cc * 4);
            xs[(4 * cc + 0) * 65 + p] = v.x;
            xs[(4 * cc + 1) * 65 + p] = v.y;
            xs[(4 * cc + 2) * 65 + p] = v.z;
            xs[(4 * cc + 3) * 65 + p] = v.w;
        }
        for (int t = tid; t < 1024; t += 256)
            ((float4*)ws)[t] = ((const float4*)(Wg + half * 64 * 64))[t];
        __syncthreads();
        for (int c = 0; c < 64; c++) {
            float xv[4];
            #pragma unroll
            for (int i = 0; i < 4; i++) xv[i] = xs[c * 65 + tx + 16 * i];
            float4 w4 = *(const float4*)(ws + c * 64 + ty * 4);
            float wv[4] = {w4.x, w4.y, w4.z, w4.w};
            #pragma unroll
            for (int j = 0; j < 4; j++)
                #pragma unroll
                for (int i = 0; i < 4; i++) acc[j][i] = fmaf(wv[j], xv[i], acc[j][i]);
        }
    }

    float a_l[4], a_r[4];
    #pragma unroll
    for (int j = 0; j < 4; j++) { a_l[j] = als[ty * 4 + j]; a_r[j] = ars[ty * 4 + j]; }
    #pragma unroll
    for (int i = 0; i < 4; i++) {
        int p = pbase + tx + 16 * i;
        float4 z4 = make_float4(acc[0][i], acc[1][i], acc[2][i], acc[3][i]);
        *(float4*)(g_z + p * 64 + ty * 4) = z4;
        float e_l = 0.0f, e_r = 0.0f;
        #pragma unroll
        for (int j = 0; j < 4; j++) {
            e_l = fmaf(acc[j][i], a_l[j], e_l);
            e_r = fmaf(acc[j][i], a_r[j], e_r);
        }
        atomicAdd(&sel[tx + 16 * i], e_l);
        atomicAdd(&ser[tx + 16 * i], e_r);
    }
    __syncthreads();
    if (tid < 64) {
        g_el[pbase + tid] = sel[tid];
        g_er[pbase + tid] = ser[tid];
        g_den[pbase + tid] = 0.0f;
    }
}

// ---------------- K6: softmax denominator over ALL edges (k-NN + self loops) -------
__global__ void k_edge_den() {
    int e = blockIdx.x * blockDim.x + threadIdx.x;
    if (e >= ETOT) return;
    int src, dst;
    if (e < E5) { src = e % NPIX; dst = g_topk[e]; }
    else        { src = e - E5;   dst = src; }
    float l = g_el[src] + g_er[dst];
    l = (l >= 0.0f) ? l : 0.2f * l;
    atomicAdd(&g_den[dst], expf(l));
}

// ---------------- K7: self-loop init of channel-major agg (+bias), fused transpose -
// g_agg[c][n] = bg[c] + alpha_self(n) * z[n][c]
__global__ __launch_bounds__(256) void k_selfagg(const float* __restrict__ bg) {
    __shared__ float tb[64 * 65];
    __shared__ float bs[64];
    __shared__ float sal[64];
    int tid = threadIdx.x;
    int nb = blockIdx.x * 64;
    if (tid < 64) {
        bs[tid] = bg[tid];
        int n = nb + tid;
        float l = g_el[n] + g_er[n];
        l = (l >= 0.0f) ? l : 0.2f * l;
        sal[tid] = expf(l) / g_den[n];
    }
    for (int t = tid; t < 1024; t += 256) {
        int p = t >> 4, cc = t & 15;
        float4 v = *(const float4*)(g_z + (nb + p) * 64 + cc * 4);
        tb[(4 * cc + 0) * 65 + p] = v.x;
        tb[(4 * cc + 1) * 65 + p] = v.y;
        tb[(4 * cc + 2) * 65 + p] = v.z;
        tb[(4 * cc + 3) * 65 + p] = v.w;
    }
    __syncthreads();
    for (int k = 0; k < 16; k++) {
        int idx = tid + k * 256;
        int c = idx >> 6, nn = idx & 63;
        g_agg[c * NPIX + nb + nn] = fmaf(tb[c * 65 + nn], sal[nn], bs[c]);
    }
}

// ---------------- K8: k-NN edge aggregation, channel-major atomics -----------------
// 4 threads/edge, 16 channels each; atomics land on 64 widely-separated lines/dst.
__global__ void k_edge_agg() {
    int t = blockIdx.x * blockDim.x + threadIdx.x;
    int e = t >> 2;
    if (e >= E5) return;
    int c0 = (t & 3) * 16;
    int src = e % NPIX;
    int dst = g_topk[e];
    float l = g_el[src] + g_er[dst];
    l = (l >= 0.0f) ? l : 0.2f * l;
    float alpha = expf(l) / g_den[dst];
    const float* zs = g_z + src * 64 + c0;
    #pragma unroll
    for (int c = 0; c < 16; c++)
        atomicAdd(&g_agg[(c0 + c) * NPIX + dst], alpha * zs[c]);
}

// ---------------- K9: 3x3 conv, 4 channels staged per barrier ---------------------
__global__ __launch_bounds__(256) void k_conv3x3(const float* __restrict__ In,
                                                 const float* __restrict__ Kw,
                                                 const float* __restrict__ bias,
                                                 const float* __restrict__ aptr,
                                                 float* __restrict__ Out,
                                                 const float* __restrict__ resid) {
    __shared__ float ws[16 * 64 * 9];   // 36864 B
    __shared__ float tile[4][324];
    int og = blockIdx.z * 16;
    for (int i = threadIdx.x; i < 16 * 64 * 9; i += 256) ws[i] = Kw[og * 576 + i];
    float alpha = aptr[0];
    int sub = threadIdx.x >> 6;
    int q   = threadIdx.x & 63;
    int qx  = q & 3, y = q >> 2;
    int x0 = blockIdx.x * 16, y0 = blockIdx.y * 16;
    float acc[4][4];
    #pragma unroll
    for (int j = 0; j < 4; j++) {
        float b = bias[og + sub * 4 + j];
        #pragma unroll
        for (int i = 0; i < 4; i++) acc[j][i] = b;
    }
    for (int cs = 0; cs < 64; cs += 4) {
        __syncthreads();
        for (int i = threadIdx.x; i < 1296; i += 256) {
            int cc = i / 324, p = i - cc * 324;
            int lx = p % 18 - 1 + x0;
            int ly = p / 18 - 1 + y0;
            tile[cc][p] = (lx >= 0 && lx < WW && ly >= 0 && ly < HH)
                            ? In[(cs + cc) * NPIX + ly * WW + lx] : 0.0f;
        }
        __syncthreads();
        #pragma unroll
        for (int cc = 0; cc < 4; cc++) {
            float r[3][6];
            #pragma unroll
            for (int ky = 0; ky < 3; ky++)
                #pragma unroll
                for (int m = 0; m < 6; m++)
                    r[ky][m] = tile[cc][(y + ky) * 18 + qx * 4 + m];
            #pragma unroll
            for (int j = 0; j < 4; j++) {
                const float* w = ws + ((sub * 4 + j) * 64 + cs + cc) * 9;
                float wv[9];
                #pragma unroll
                for (int k = 0; k < 9; k++) wv[k] = w[k];
                #pragma unroll
                for (int i = 0; i < 4; i++)
                    #pragma unroll
                    for (int ky = 0; ky < 3; ky++)
                        #pragma unroll
                        for (int kx = 0; kx < 3; kx++)
                            acc[j][i] = fmaf(wv[ky * 3 + kx], r[ky][kx + i], acc[j][i]);
            }
        }
    }
    int pix0 = (y0 + y) * WW + x0 + qx * 4;
    #pragma unroll
    for (int j = 0; j < 4; j++) {
        int o = og + sub * 4 + j;
        float4 v4;
        float v;
        v = acc[j][0]; v4.x = (v >= 0.0f) ? v : alpha * v;
        v = acc[j][1]; v4.y = (v >= 0.0f) ? v : alpha * v;
        v = acc[j][2]; v4.z = (v >= 0.0f) ? v : alpha * v;
        v = acc[j][3]; v4.w = (v >= 0.0f) ? v : alpha * v;
        if (resid) {
            float4 rr = *(const float4*)(resid + o * NPIX + pix0);
            v4.x += rr.x; v4.y += rr.y; v4.z += rr.z; v4.w += rr.w;
        }
        *(float4*)(Out + o * NPIX + pix0) = v4;
    }
}

// ---------------- launch ----------------
extern "C" void kernel_launch(void* const* d_in, const int* in_sizes, int n_in,
                              void* d_out, int out_size) {
    const float* msi  = (const float*)d_in[0];
    const float* hsi  = (const float*)d_in[1];
    const float* W1a  = (const float*)d_in[2];
    const float* b1a  = (const float*)d_in[3];
    const float* a1a  = (const float*)d_in[4];
    const float* W1b  = (const float*)d_in[5];
    const float* b1b  = (const float*)d_in[6];
    const float* a1b  = (const float*)d_in[7];
    const float* W2a  = (const float*)d_in[8];
    const float* b2a  = (const float*)d_in[9];
    const float* a2a  = (const float*)d_in[10];
    const float* W2b  = (const float*)d_in[11];
    const float* b2b  = (const float*)d_in[12];
    const float* a2b  = (const float*)d_in[13];
    const float* Wg   = (const float*)d_in[14];
    const float* attl = (const float*)d_in[15];
    const float* attr = (const float*)d_in[16];
    const float* bg   = (const float*)d_in[17];
    const float* Ku1  = (const float*)d_in[18];
    const float* bu1  = (const float*)d_in[19];
    const float* au1  = (const float*)d_in[20];
    const float* Ku2  = (const float*)d_in[21];
    const float* bu2  = (const float*)d_in[22];
    const float* au2  = (const float*)d_in[23];

    float *p_hsi_up, *p_hfeat, *p_mfeat, *p_agg, *p_up1;
    unsigned short *p_hbf, *p_mbf;
    cudaGetSymbolAddress((void**)&p_hsi_up, g_hsi_up);
    cudaGetSymbolAddress((void**)&p_hfeat,  g_hfeat);
    cudaGetSymbolAddress((void**)&p_mfeat,  g_mfeat);
    cudaGetSymbolAddress((void**)&p_agg,    g_agg);
    cudaGetSymbolAddress((void**)&p_up1,    g_up1);
    cudaGetSymbolAddress((void**)&p_hbf,    g_hbf);
    cudaGetSymbolAddress((void**)&p_mbf,    g_mbf);

    k_bicubic<<<dim3(CCH, 4), 256>>>(hsi);

    k_embed<<<dim3(NPIX / 64, 2), 256>>>(p_hsi_up, msi,
                                         W1a, b1a, a1a, W1b, b1b, a1b,
                                         W2a, b2a, a2a, W2b, b2b, a2b,
                                         p_hfeat, p_mfeat, p_hbf, p_mbf);

    // gatz moved before sim_hmma (legal: needs only embed outputs) so the
    // profiler's fixed capture slot lands on k_sim_hmma this round.
    k_gatz<<<NPIX / 64, 256>>>(Wg, attl, attr);

    k_sim_hmma<<<dim3(72, 2), 256>>>();
    k_rescore<<<NPIX / 8, 256>>>();

    k_edge_den<<<(ETOT + 255) / 256, 256>>>();
    k_selfagg<<<NPIX / 64, 256>>>(bg);
    k_edge_agg<<<(E5 * 4 + 255) / 256, 256>>>();

    k_conv3x3<<<dim3(6, 6, 4), 256>>>(p_agg, Ku1, bu1, au1, p_up1, nullptr);
    k_conv3x3<<<dim3(6, 6, 4), 256>>>(p_up1, Ku2, bu2, au2, (float*)d_out, p_hsi_up);
}

// round 14
// speedup vs baseline: 2.8832x; 1.3625x over previous
#include <cuda_runtime.h>
#include <cuda_bf16.h>
#include <math.h>

#define NPIX 9216
#define CCH  64
#define HH   96
#define WW   96
#define HS   24
#define KNN  5
#define E5   (NPIX * KNN)                /* 46080 */
#define ETOT (E5 + NPIX)                 /* 55296 */
#define NCAND 64                         /* candidates per row (8 splits x 8) */
#define SPLITS 8
#define CPS 1152                         /* cols per split */
#define TILES (CPS / 128)                /* 9 */

// ---------------- scratch (static device globals; no allocation) ----------------
__device__ float    g_hsi_up[CCH * NPIX];   // channel-major [c][pix]; also the residual
__device__ float    g_hfeat[NPIX * CCH];    // pixel-major [pix][c]
__device__ float    g_mfeat[NPIX * CCH];
__device__ unsigned short g_hbf[NPIX * CCH];  // bf16 copies, pixel-major
__device__ unsigned short g_mbf[NPIX * CCH];
__device__ float    g_z    [NPIX * CCH];
__device__ float    g_el   [NPIX];
__device__ float    g_er   [NPIX];
__device__ int      g_cidx [NPIX * NCAND];
__device__ int      g_topk [NPIX * KNN];
__device__ float    g_den  [NPIX];
__device__ float    g_agg  [CCH * NPIX];    // CHANNEL-major: spreads hot-dst atomics over LTS
__device__ float    g_up1  [CCH * NPIX];

// ---------------- helpers ----------------
__device__ __forceinline__ unsigned pack_bf16x2(float lo, float hi) {
    unsigned d;
    asm("cvt.rn.bf16x2.f32 %0, %1, %2;" : "=r"(d) : "f"(hi), "f"(lo));
    return d;
}

__device__ __forceinline__ float cubw(float d) {
    d = fabsf(d);
    const float a = -0.75f;
    if (d <= 1.0f) return ((a + 2.0f) * d - (a + 3.0f)) * d * d + 1.0f;
    if (d < 2.0f)  return ((a * d - 5.0f * a) * d + 8.0f * a) * d - 4.0f * a;
    return 0.0f;
}

// branchless sorted insert into descending 8-list of packed s32 keys (16 IMNMX)
__device__ __forceinline__ void ins8(int (&v)[8], int x) {
    #pragma unroll
    for (int s = 0; s < 8; s++) {
        int hi = max(v[s], x);
        x      = min(v[s], x);
        v[s] = hi;
    }
}

// ---------------- K1: bicubic x4 upsample, smem-staged (24x24 -> 96x96) ----------
__global__ __launch_bounds__(256) void k_bicubic(const float* __restrict__ in) {
    __shared__ float s[HS * HS];
    int c = blockIdx.x;
    for (int i = threadIdx.x; i < HS * HS; i += 256) s[i] = in[c * HS * HS + i];
    __syncthreads();
    int obase = blockIdx.y * (NPIX / 4);
    for (int o = obase + threadIdx.x; o < obase + NPIX / 4; o += 256) {
        int x = o % WW, y = o / WW;
        float fy = (y + 0.5f) * 0.25f - 0.5f;
        float iy = floorf(fy); float ty = fy - iy;
        float fx = (x + 0.5f) * 0.25f - 0.5f;
        float ix = floorf(fx); float tx = fx - ix;
        float wy[4], wx[4]; int sy[4], sx[4];
        #pragma unroll
        for (int k = 0; k < 4; k++) {
            wy[k] = cubw(ty - (float)(k - 1));
            wx[k] = cubw(tx - (float)(k - 1));
            sy[k] = min(max((int)iy + k - 1, 0), HS - 1);
            sx[k] = min(max((int)ix + k - 1, 0), HS - 1);
        }
        float acc = 0.0f;
        #pragma unroll
        for (int i = 0; i < 4; i++) {
            float r = 0.0f;
            #pragma unroll
            for (int j = 0; j < 4; j++) r = fmaf(wx[j], s[sy[i] * HS + sx[j]], r);
            acc = fmaf(wy[i], r, acc);
        }
        g_hsi_up[c * NPIX + o] = acc;
    }
}

// ---------------- K2: fused 2-layer 1x1-conv embed, both branches -----------------
__global__ __launch_bounds__(256) void k_embed(
    const float* __restrict__ X0, const float* __restrict__ X1,
    const float* __restrict__ Wa0, const float* __restrict__ ba0, const float* __restrict__ aa0,
    const float* __restrict__ Wb0, const float* __restrict__ bb0, const float* __restrict__ ab0,
    const float* __restrict__ Wa1, const float* __restrict__ ba1, const float* __restrict__ aa1,
    const float* __restrict__ Wb1, const float* __restrict__ bb1, const float* __restrict__ ab1,
    float* __restrict__ Y0, float* __restrict__ Y1,
    unsigned short* __restrict__ Yb0, unsigned short* __restrict__ Yb1)
{
    __shared__ float xs[64 * 64];
    __shared__ float ws[64 * 64];
    __shared__ float bsh[64];
    __shared__ float s_alpha;
    int br = blockIdx.y;
    const float* X  = br ? X1 : X0;
    const float* Wa = br ? Wa1 : Wa0;
    const float* ba = br ? ba1 : ba0;
    const float* aa = br ? aa1 : aa0;
    const float* Wb = br ? Wb1 : Wb0;
    const float* bb = br ? bb1 : bb0;
    const float* ab = br ? ab1 : ab0;
    float* Y = br ? Y1 : Y0;
    unsigned short* Yb = br ? Yb1 : Yb0;
    int tid = threadIdx.x;
    int tx = tid & 15, ty = tid >> 4;
    int pbase = blockIdx.x * 64;

    for (int t = tid; t < 1024; t += 256) {
        int c = t >> 4, p4 = t & 15;
        ((float4*)xs)[c * 16 + p4] = *(const float4*)(X + c * NPIX + pbase + p4 * 4);
    }
    for (int t = tid; t < 1024; t += 256)
        ((float4*)ws)[t] = ((const float4*)Wa)[t];
    if (tid < 64) bsh[tid] = ba[tid];
    if (tid == 0) s_alpha = aa[0];
    __syncthreads();

    float acc[4][4];
    #pragma unroll
    for (int j = 0; j < 4; j++)
        #pragma unroll
        for (int i = 0; i < 4; i++) acc[j][i] = bsh[ty * 4 + j];
    for (int c = 0; c < 64; c++) {
        float xv[4], wv[4];
        #pragma unroll
        for (int i = 0; i < 4; i++) xv[i] = xs[c * 64 + tx + 16 * i];
        #pragma unroll
        for (int j = 0; j < 4; j++) wv[j] = ws[(ty * 4 + j) * 64 + c];
        #pragma unroll
        for (int j = 0; j < 4; j++)
            #pragma unroll
            for (int i = 0; i < 4; i++) acc[j][i] = fmaf(wv[j], xv[i], acc[j][i]);
    }
    float al = s_alpha;
    __syncthreads();

    #pragma unroll
    for (int j = 0; j < 4; j++)
        #pragma unroll
        for (int i = 0; i < 4; i++) {
            float v = acc[j][i];
            v = (v >= 0.0f) ? v : al * v;
            xs[(ty * 4 + j) * 64 + tx + 16 * i] = v;
        }
    for (int t = tid; t < 1024; t += 256)
        ((float4*)ws)[t] = ((const float4*)Wb)[t];
    if (tid < 64) bsh[tid] = bb[tid];
    if (tid == 0) s_alpha = ab[0];
    __syncthreads();

    #pragma unroll
    for (int j = 0; j < 4; j++)
        #pragma unroll
        for (int i = 0; i < 4; i++) acc[j][i] = bsh[ty * 4 + j];
    for (int c = 0; c < 64; c++) {
        float xv[4], wv[4];
        #pragma unroll
        for (int i = 0; i < 4; i++) xv[i] = xs[c * 64 + tx + 16 * i];
        #pragma unroll
        for (int j = 0; j < 4; j++) wv[j] = ws[(ty * 4 + j) * 64 + c];
        #pragma unroll
        for (int j = 0; j < 4; j++)
            #pragma unroll
            for (int i = 0; i < 4; i++) acc[j][i] = fmaf(wv[j], xv[i], acc[j][i]);
    }
    float al2 = s_alpha;
    #pragma unroll
    for (int i = 0; i < 4; i++) {
        int pix = pbase + tx + 16 * i;
        float4 o4;
        float v;
        v = acc[0][i]; o4.x = (v >= 0.0f) ? v : al2 * v;
        v = acc[1][i]; o4.y = (v >= 0.0f) ? v : al2 * v;
        v = acc[2][i]; o4.z = (v >= 0.0f) ? v : al2 * v;
        v = acc[3][i]; o4.w = (v >= 0.0f) ? v : al2 * v;
        *(float4*)(Y + pix * 64 + ty * 4) = o4;
        uint2 b2;
        b2.x = pack_bf16x2(o4.x, o4.y);
        b2.y = pack_bf16x2(o4.z, o4.w);
        *(uint2*)(Yb + pix * 64 + ty * 4) = b2;
    }
}

// ---------------- K3: bf16 HMMA sim GEMM + packed-key top-8 candidates -------------
// grid (72, 8): 128 rows x 1152-col split. 8 warps x 16 rows. Keys are s32:
// (float_bits & ~0x1FFF) | local_col (13 bits). Signed compare = bf16-top-8 order
// (negatives always lose; top-8 of 1152 dots are positive w.p. ~1). End-of-kernel
// shuffle merge collapses the 4 lane-group lists -> one top-8 per (row, split).
#define BPITCH 72
__global__ __launch_bounds__(256, 4) void k_sim_hmma() {
    __shared__ __align__(16) unsigned short Bs[128 * BPITCH];
    int tid = threadIdx.x;
    int w = tid >> 5, lane = tid & 31;
    int rowbase = blockIdx.x * 128;
    int split = blockIdx.y;
    int colbase = split * CPS;

    int r0 = rowbase + w * 16 + (lane >> 2);
    int r1 = r0 + 8;
    int lg = lane & 3;

    unsigned a[4][4];
    #pragma unroll
    for (int ks = 0; ks < 4; ks++) {
        int k0r = ks * 16 + lg * 2;
        a[ks][0] = *(const unsigned*)(g_hbf + r0 * 64 + k0r);
        a[ks][1] = *(const unsigned*)(g_hbf + r1 * 64 + k0r);
        a[ks][2] = *(const unsigned*)(g_hbf + r0 * 64 + k0r + 8);
        a[ks][3] = *(const unsigned*)(g_hbf + r1 * 64 + k0r + 8);
    }

    int k0[8], k1[8];
    #pragma unroll
    for (int j = 0; j < 8; j++) { k0[j] = (int)0x80000000; k1[j] = (int)0x80000000; }

    for (int tile = 0; tile < TILES; tile++) {
        int cbl = tile * 128;                 // local col base of tile
        __syncthreads();
        for (int q = tid; q < 1024; q += 256) {
            int n = q >> 3, c8 = q & 7;
            *(float4*)(Bs + n * BPITCH + c8 * 8) =
                *(const float4*)(g_mbf + (colbase + cbl + n) * 64 + c8 * 8);
        }
        __syncthreads();

        #pragma unroll 2
        for (int nc = 0; nc < 16; nc++) {
            int n0 = nc * 8;
            float c0 = 0.0f, c1 = 0.0f, c2 = 0.0f, c3 = 0.0f;
            const unsigned short* brow = Bs + (n0 + (lane >> 2)) * BPITCH + lg * 2;
            #pragma unroll
            for (int ks = 0; ks < 4; ks++) {
                unsigned b0 = *(const unsigned*)(brow + ks * 16);
                unsigned b1 = *(const unsigned*)(brow + ks * 16 + 8);
                asm volatile(
                    "mma.sync.aligned.m16n8k16.row.col.f32.bf16.bf16.f32 "
                    "{%0,%1,%2,%3}, {%4,%5,%6,%7}, {%8,%9}, {%0,%1,%2,%3};"
                    : "+f"(c0), "+f"(c1), "+f"(c2), "+f"(c3)
                    : "r"(a[ks][0]), "r"(a[ks][1]), "r"(a[ks][2]), "r"(a[ks][3]),
                      "r"(b0), "r"(b1));
            }
            int lidx = cbl + n0 + lg * 2;     // < 1152, fits 13 bits; even
            int key0 = (__float_as_int(c0) & ~0x1FFF) | lidx;
            int key1 = (__float_as_int(c1) & ~0x1FFF) | (lidx + 1);
            int key2 = (__float_as_int(c2) & ~0x1FFF) | lidx;
            int key3 = (__float_as_int(c3) & ~0x1FFF) | (lidx + 1);
            if (key0 > k0[7]) ins8(k0, key0);
            if (key1 > k0[7]) ins8(k0, key1);
            if (key2 > k1[7]) ins8(k1, key2);
            if (key3 > k1[7]) ins8(k1, key3);
        }
    }

    // merge the 4 lane-group lists (disjoint column sets) -> full-split top-8.
    // snapshot partner lists BEFORE inserting (shuffles read pre-merge state).
    #pragma unroll
    for (int lvl = 1; lvl <= 2; lvl <<= 1) {
        int o0[8], o1[8];
        #pragma unroll
        for (int j = 0; j < 8; j++) {
            o0[j] = __shfl_xor_sync(0xffffffffu, k0[j], lvl);
            o1[j] = __shfl_xor_sync(0xffffffffu, k1[j], lvl);
        }
        #pragma unroll
        for (int j = 0; j < 8; j++) {
            if (o0[j] > k0[7]) ins8(k0, o0[j]);
            if (o1[j] > k1[7]) ins8(k1, o1[j]);
        }
    }

    if (lg == 0) {
        int base0 = r0 * NCAND + split * 8;
        int base1 = r1 * NCAND + split * 8;
        #pragma unroll
        for (int j = 0; j < 8; j++) {
            g_cidx[base0 + j] = colbase + (k0[j] & 0x1FFF);
            g_cidx[base1 + j] = colbase + (k1[j] & 0x1FFF);
        }
    }
}

// ---------------- K4: exact fp32 rescore, cooperative coalesced gathers ------------
__global__ __launch_bounds__(256) void k_rescore() {
    int tid = threadIdx.x;
    int w = tid >> 5, lane = tid & 31;
    int row = blockIdx.x * 8 + w;

    float2 h = *(const float2*)(g_hfeat + row * 64 + lane * 2);
    int myc0 = g_cidx[row * NCAND + lane];
    int myc1 = g_cidx[row * NCAND + 32 + lane];

    float v[2]; int ix[2];
    ix[0] = myc0; ix[1] = myc1;
    v[0] = 0.0f; v[1] = 0.0f;

    #pragma unroll
    for (int half = 0; half < 2; half++) {
        int src = half ? myc1 : myc0;
        #pragma unroll
        for (int g = 0; g < 4; g++) {
            float p[8];
            #pragma unroll
            for (int j = 0; j < 8; j++) {
                int ci = __shfl_sync(0xffffffffu, src, g * 8 + j);
                float2 m = *(const float2*)(g_mfeat + ci * 64 + lane * 2);
                p[j] = fmaf(h.x, m.x, h.y * m.y);
            }
            #pragma unroll
            for (int j = 0; j < 8; j++) {
                #pragma unroll
                for (int off = 16; off; off >>= 1)
                    p[j] += __shfl_xor_sync(0xffffffffu, p[j], off);
            }
            #pragma unroll
            for (int j = 0; j < 8; j++)
                if (lane == g * 8 + j) v[half] = p[j];
        }
    }

    #pragma unroll
    for (int sel = 0; sel < KNN; sel++) {
        bool first = (v[0] > v[1]) || (v[0] == v[1] && ix[0] < ix[1]);
        float bv = first ? v[0] : v[1];
        int   bi = first ? ix[0] : ix[1];
        #pragma unroll
        for (int off = 16; off; off >>= 1) {
            float ov = __shfl_xor_sync(0xffffffffu, bv, off);
            int   oi = __shfl_xor_sync(0xffffffffu, bi, off);
            if (ov > bv || (ov == bv && oi < bi)) { bv = ov; bi = oi; }
        }
        if (lane == 0) g_topk[row * KNN + sel] = bi;
        if (ix[0] == bi) v[0] = -INFINITY;
        if (ix[1] == bi) v[1] = -INFINITY;
    }
}

// ---------------- K5: GAT fc  z = [hfeat|mfeat] @ Wg,  el/er per node --------------
__global__ __launch_bounds__(256) void k_gatz(const float* __restrict__ Wg,
                                              const float* __restrict__ alv,
                                              const float* __restrict__ arv) {
    __shared__ float xs[64 * 65];
    __shared__ float ws[64 * 64];
    __shared__ float als[64], ars[64];
    __shared__ float sel[64], ser[64];
    int tid = threadIdx.x, tx = tid & 15, ty = tid >> 4;
    int pbase = blockIdx.x * 64;
    if (tid < 64) { als[tid] = alv[tid]; ars[tid] = arv[tid]; sel[tid] = 0.0f; ser[tid] = 0.0f; }

    float acc[4][4];
    #pragma unroll
    for (int j = 0; j < 4; j++)
        #pragma unroll
        for (int i = 0; i < 4; i++) acc[j][i] = 0.0f;

    for (int half = 0; half < 2; half++) {
        const float* X = half ? g_mfeat : g_hfeat;
        __syncthreads();
        for (int t = tid; t < 1024; t += 256) {
            int p = t >> 4, cc = t & 15;
            float4 v = *(const float4*)(X + (pbase + p) * 64 + cc * 4);
            xs[(4 * cc + 0) * 65 + p] = v.x;
            xs[(4 * cc + 1) * 65 + p] = v.y;
            xs[(4 * cc + 2) * 65 + p] = v.z;
            xs[(4 * cc + 3) * 65 + p] = v.w;
        }
        for (int t = tid; t < 1024; t += 256)
            ((float4*)ws)[t] = ((const float4*)(Wg + half * 64 * 64))[t];
        __syncthreads();
        for (int c = 0; c < 64; c++) {
            float xv[4];
            #pragma unroll
            for (int i = 0; i < 4; i++) xv[i] = xs[c * 65 + tx + 16 * i];
            float4 w4 = *(const float4*)(ws + c * 64 + ty * 4);
            float wv[4] = {w4.x, w4.y, w4.z, w4.w};
            #pragma unroll
            for (int j = 0; j < 4; j++)
                #pragma unroll
                for (int i = 0; i < 4; i++) acc[j][i] = fmaf(wv[j], xv[i], acc[j][i]);
        }
    }

    float a_l[4], a_r[4];
    #pragma unroll
    for (int j = 0; j < 4; j++) { a_l[j] = als[ty * 4 + j]; a_r[j] = ars[ty * 4 + j]; }
    #pragma unroll
    for (int i = 0; i < 4; i++) {
        int p = pbase + tx + 16 * i;
        float4 z4 = make_float4(acc[0][i], acc[1][i], acc[2][i], acc[3][i]);
        *(float4*)(g_z + p * 64 + ty * 4) = z4;
        float e_l = 0.0f, e_r = 0.0f;
        #pragma unroll
        for (int j = 0; j < 4; j++) {
            e_l = fmaf(acc[j][i], a_l[j], e_l);
            e_r = fmaf(acc[j][i], a_r[j], e_r);
        }
        atomicAdd(&sel[tx + 16 * i], e_l);
        atomicAdd(&ser[tx + 16 * i], e_r);
    }
    __syncthreads();
    if (tid < 64) {
        g_el[pbase + tid] = sel[tid];
        g_er[pbase + tid] = ser[tid];
        g_den[pbase + tid] = 0.0f;
    }
}

// ---------------- K6: softmax denominator over ALL edges (k-NN + self loops) -------
__global__ void k_edge_den() {
    int e = blockIdx.x * blockDim.x + threadIdx.x;
    if (e >= ETOT) return;
    int src, dst;
    if (e < E5) { src = e % NPIX; dst = g_topk[e]; }
    else        { src = e - E5;   dst = src; }
    float l = g_el[src] + g_er[dst];
    l = (l >= 0.0f) ? l : 0.2f * l;
    atomicAdd(&g_den[dst], expf(l));
}

// ---------------- K7: self-loop init of channel-major agg (+bias), fused transpose -
__global__ __launch_bounds__(256) void k_selfagg(const float* __restrict__ bg) {
    __shared__ float tb[64 * 65];
    __shared__ float bs[64];
    __shared__ float sal[64];
    int tid = threadIdx.x;
    int nb = blockIdx.x * 64;
    if (tid < 64) {
        bs[tid] = bg[tid];
        int n = nb + tid;
        float l = g_el[n] + g_er[n];
        l = (l >= 0.0f) ? l : 0.2f * l;
        sal[tid] = expf(l) / g_den[n];
    }
    for (int t = tid; t < 1024; t += 256) {
        int p = t >> 4, cc = t & 15;
        float4 v = *(const float4*)(g_z + (nb + p) * 64 + cc * 4);
        tb[(4 * cc + 0) * 65 + p] = v.x;
        tb[(4 * cc + 1) * 65 + p] = v.y;
        tb[(4 * cc + 2) * 65 + p] = v.z;
        tb[(4 * cc + 3) * 65 + p] = v.w;
    }
    __syncthreads();
    for (int k = 0; k < 16; k++) {
        int idx = tid + k * 256;
        int c = idx >> 6, nn = idx & 63;
        g_agg[c * NPIX + nb + nn] = fmaf(tb[c * 65 + nn], sal[nn], bs[c]);
    }
}

// ---------------- K8: k-NN edge aggregation, channel-major atomics -----------------
__global__ void k_edge_agg() {
    int t = blockIdx.x * blockDim.x + threadIdx.x;
    int e = t >> 2;
    if (e >= E5) return;
    int c0 = (t & 3) * 16;
    int src = e % NPIX;
    int dst = g_topk[e];
    float l = g_el[src] + g_er[dst];
    l = (l >= 0.0f) ? l : 0.2f * l;
    float alpha = expf(l) / g_den[dst];
    const float* zs = g_z + src * 64 + c0;
    #pragma unroll
    for (int c = 0; c < 16; c++)
        atomicAdd(&g_agg[(c0 + c) * NPIX + dst], alpha * zs[c]);
}

// ---------------- K9: 3x3 conv, 4 channels staged per barrier ---------------------
__global__ __launch_bounds__(256) void k_conv3x3(const float* __restrict__ In,
                                                 const float* __restrict__ Kw,
                                                 const float* __restrict__ bias,
                                                 const float* __restrict__ aptr,
                                                 float* __restrict__ Out,
                                                 const float* __restrict__ resid) {
    __shared__ float ws[16 * 64 * 9];   // 36864 B
    __shared__ float tile[4][324];
    int og = blockIdx.z * 16;
    for (int i = threadIdx.x; i < 16 * 64 * 9; i += 256) ws[i] = Kw[og * 576 + i];
    float alpha = aptr[0];
    int sub = threadIdx.x >> 6;
    int q   = threadIdx.x & 63;
    int qx  = q & 3, y = q >> 2;
    int x0 = blockIdx.x * 16, y0 = blockIdx.y * 16;
    float acc[4][4];
    #pragma unroll
    for (int j = 0; j < 4; j++) {
        float b = bias[og + sub * 4 + j];
        #pragma unroll
        for (int i = 0; i < 4; i++) acc[j][i] = b;
    }
    for (int cs = 0; cs < 64; cs += 4) {
        __syncthreads();
        for (int i = threadIdx.x; i < 1296; i += 256) {
            int cc = i / 324, p = i - cc * 324;
            int lx = p % 18 - 1 + x0;
            int ly = p / 18 - 1 + y0;
            tile[cc][p] = (lx >= 0 && lx < WW && ly >= 0 && ly < HH)
                            ? In[(cs + cc) * NPIX + ly * WW + lx] : 0.0f;
        }
        __syncthreads();
        #pragma unroll
        for (int cc = 0; cc < 4; cc++) {
            float r[3][6];
            #pragma unroll
            for (int ky = 0; ky < 3; ky++)
                #pragma unroll
                for (int m = 0; m < 6; m++)
                    r[ky][m] = tile[cc][(y + ky) * 18 + qx * 4 + m];
            #pragma unroll
            for (int j = 0; j < 4; j++) {
                const float* w = ws + ((sub * 4 + j) * 64 + cs + cc) * 9;
                float wv[9];
                #pragma unroll
                for (int k = 0; k < 9; k++) wv[k] = w[k];
                #pragma unroll
                for (int i = 0; i < 4; i++)
                    #pragma unroll
                    for (int ky = 0; ky < 3; ky++)
                        #pragma unroll
                        for (int kx = 0; kx < 3; kx++)
                            acc[j][i] = fmaf(wv[ky * 3 + kx], r[ky][kx + i], acc[j][i]);
            }
        }
    }
    int pix0 = (y0 + y) * WW + x0 + qx * 4;
    #pragma unroll
    for (int j = 0; j < 4; j++) {
        int o = og + sub * 4 + j;
        float4 v4;
        float v;
        v = acc[j][0]; v4.x = (v >= 0.0f) ? v : alpha * v;
        v = acc[j][1]; v4.y = (v >= 0.0f) ? v : alpha * v;
        v = acc[j][2]; v4.z = (v >= 0.0f) ? v : alpha * v;
        v = acc[j][3]; v4.w = (v >= 0.0f) ? v : alpha * v;
        if (resid) {
            float4 rr = *(const float4*)(resid + o * NPIX + pix0);
            v4.x += rr.x; v4.y += rr.y; v4.z += rr.z; v4.w += rr.w;
        }
        *(float4*)(Out + o * NPIX + pix0) = v4;
    }
}

// ---------------- launch ----------------
extern "C" void kernel_launch(void* const* d_in, const int* in_sizes, int n_in,
                              void* d_out, int out_size) {
    const float* msi  = (const float*)d_in[0];
    const float* hsi  = (const float*)d_in[1];
    const float* W1a  = (const float*)d_in[2];
    const float* b1a  = (const float*)d_in[3];
    const float* a1a  = (const float*)d_in[4];
    const float* W1b  = (const float*)d_in[5];
    const float* b1b  = (const float*)d_in[6];
    const float* a1b  = (const float*)d_in[7];
    const float* W2a  = (const float*)d_in[8];
    const float* b2a  = (const float*)d_in[9];
    const float* a2a  = (const float*)d_in[10];
    const float* W2b  = (const float*)d_in[11];
    const float* b2b  = (const float*)d_in[12];
    const float* a2b  = (const float*)d_in[13];
    const float* Wg   = (const float*)d_in[14];
    const float* attl = (const float*)d_in[15];
    const float* attr = (const float*)d_in[16];
    const float* bg   = (const float*)d_in[17];
    const float* Ku1  = (const float*)d_in[18];
    const float* bu1  = (const float*)d_in[19];
    const float* au1  = (const float*)d_in[20];
    const float* Ku2  = (const float*)d_in[21];
    const float* bu2  = (const float*)d_in[22];
    const float* au2  = (const float*)d_in[23];

    float *p_hsi_up, *p_hfeat, *p_mfeat, *p_agg, *p_up1;
    unsigned short *p_hbf, *p_mbf;
    cudaGetSymbolAddress((void**)&p_hsi_up, g_hsi_up);
    cudaGetSymbolAddress((void**)&p_hfeat,  g_hfeat);
    cudaGetSymbolAddress((void**)&p_mfeat,  g_mfeat);
    cudaGetSymbolAddress((void**)&p_agg,    g_agg);
    cudaGetSymbolAddress((void**)&p_up1,    g_up1);
    cudaGetSymbolAddress((void**)&p_hbf,    g_hbf);
    cudaGetSymbolAddress((void**)&p_mbf,    g_mbf);

    k_bicubic<<<dim3(CCH, 4), 256>>>(hsi);

    k_embed<<<dim3(NPIX / 64, 2), 256>>>(p_hsi_up, msi,
                                         W1a, b1a, a1a, W1b, b1b, a1b,
                                         W2a, b2a, a2a, W2b, b2b, a2b,
                                         p_hfeat, p_mfeat, p_hbf, p_mbf);

    k_gatz<<<NPIX / 64, 256>>>(Wg, attl, attr);

    k_sim_hmma<<<dim3(72, SPLITS), 256>>>();
    k_rescore<<<NPIX / 8, 256>>>();

    k_edge_den<<<(ETOT + 255) / 256, 256>>>();
    k_selfagg<<<NPIX / 64, 256>>>(bg);
    k_edge_agg<<<(E5 * 4 + 255) / 256, 256>>>();

    k_conv3x3<<<dim3(6, 6, 4), 256>>>(p_agg, Ku1, bu1, au1, p_up1, nullptr);
    k_conv3x3<<<dim3(6, 6, 4), 256>>>(p_up1, Ku2, bu2, au2, (float*)d_out, p_hsi_up);
}